// round 4
// baseline (speedup 1.0000x reference)
#include <cuda_runtime.h>
#include <math.h>
#include <stdint.h>

// ---------------- problem dims (fixed) ----------------
#define NB   2      // batch
#define LT   512    // txt tokens
#define NI   2048   // img tokens (H=64, W=32)
#define DM   512    // model dim
#define NHD  4      // heads
#define HDD  128    // head dim
#define FFD  2048   // mlp hidden
#define KVL  2560   // LT + NI
#define E6   3072   // 6*DM adaln embedding
#define SCALE_C 0.08838834764831845f  // 128^-0.5

// ---------------- scratch (__device__ globals; allocation-free) ----------------
__device__ __align__(256) float d_e_img[NB*E6];
__device__ __align__(256) float d_e_txt[NB*E6];
__device__ __align__(256) float d_eff[NB];
__device__ __align__(256) float d_mod[NB*NHD*NI];
__device__ __align__(256) float d_nimg[NB*NI*DM];
__device__ __align__(256) float d_ntxt[NB*LT*DM];
__device__ __align__(256) float d_qkvi[NB*NI*3*NHD*HDD];
__device__ __align__(256) float d_qkvt[NB*LT*3*NHD*HDD];
__device__ __align__(256) float d_Qi[NB*NHD*NI*HDD];
__device__ __align__(256) float d_Qt[NB*NHD*LT*HDD];
__device__ __align__(256) float d_Kc[NB*NHD*KVL*HDD];
__device__ __align__(256) float d_VT[NB*NHD*HDD*KVL];
__device__ __align__(256) float d_St[NB*NHD*LT*KVL];
__device__ __align__(256) float d_Si[NB*NHD*NI*KVL];
__device__ __align__(256) float d_apt[NB*LT*DM];
__device__ __align__(256) float d_api[NB*NI*DM];
__device__ __align__(256) float d_prt[NB*LT*DM];
__device__ __align__(256) float d_pri[NB*NI*DM];
__device__ __align__(256) float d_ct[NB*LT*DM];
__device__ __align__(256) float d_ci[NB*NI*DM];
__device__ __align__(256) float d_ht[NB*LT*FFD];
__device__ __align__(256) float d_hi[NB*NI*FFD];

// ---------------- helpers ----------------
__device__ __forceinline__ float warpSum(float v){
  #pragma unroll
  for (int o=16;o>0;o>>=1) v += __shfl_xor_sync(0xffffffffu, v, o);
  return v;
}
__device__ __forceinline__ float warpMax(float v){
  #pragma unroll
  for (int o=16;o>0;o>>=1) v = fmaxf(v, __shfl_xor_sync(0xffffffffu, v, o));
  return v;
}
__device__ __forceinline__ uint32_t sptr(const void* p){
  uint32_t r;
  asm("{ .reg .u64 t; cvta.to.shared.u64 t, %1; cvt.u32.u64 %0, t; }" : "=r"(r) : "l"(p));
  return r;
}
__device__ __forceinline__ uint32_t f2tf32(float x){
  uint32_t r;
  asm("cvt.rna.tf32.f32 %0, %1;" : "=r"(r) : "f"(x));
  return r;
}

// ================= tf32 mma.sync batched GEMM: C = alpha * A(MxK) @ B(NxK)^T =================
// CTA tile 128x128, 4 warps (2x2), warp tile 64x64, K-chunk 32, double-buffered cp.async.
// C pointer per z-slice: C + (z/cdiv)*sC1 + (z%cdiv)*sC2, row stride ldc.
#define TSTRIDE 36                 // padded row stride (floats), conflict-free
#define STAGE_F (128*TSTRIDE)      // floats per matrix per stage
#define TG_DSMEM (4*STAGE_F*4)     // 2 stages x (A+B) x 4B = 73728

__global__ __launch_bounds__(128) void tgemm(
    const float* __restrict__ A, const float* __restrict__ Bm,
    float* __restrict__ C, int N, int K, int ldc,
    long long sA, long long sB, long long sC1, long long sC2, int cdiv,
    float alpha, const float* __restrict__ alphas, int adiv)
{
  extern __shared__ float smem[];
  float* As = smem;                // [2][STAGE_F]
  float* Bs = smem + 2*STAGE_F;    // [2][STAGE_F]

  const int tid = threadIdx.x;
  const int z   = blockIdx.z;
  const long long bm = (long long)blockIdx.y * 128;
  const long long bn = (long long)blockIdx.x * 128;

  const float* Ab = A  + z*sA + bm*K;
  const float* Bb = Bm + z*sB + bn*K;
  float alp = alphas ? alphas[z/adiv] : alpha;

  const int lw  = tid & 31;
  const int w   = tid >> 5;
  const int wr  = (w >> 1) * 64;   // warp row base in tile
  const int wc  = (w & 1) * 64;    // warp col base in tile
  const int g   = lw >> 2;         // group id 0..7
  const int tg  = lw & 3;          // thread in group 0..3

  float acc[4][8][4];
  #pragma unroll
  for (int i=0;i<4;i++)
    #pragma unroll
    for (int j=0;j<8;j++)
      #pragma unroll
      for (int q=0;q<4;q++) acc[i][j][q] = 0.f;

  const int nch = K >> 5;

  // loader: each of 128 threads owns one row, 8 x 16B per matrix
  auto load_chunk = [&](int c, int st){
    const float* Ag = Ab + (long long)tid*K + c*32;
    const float* Bg = Bb + (long long)tid*K + c*32;
    uint32_t da = sptr(As + st*STAGE_F + tid*TSTRIDE);
    uint32_t db = sptr(Bs + st*STAGE_F + tid*TSTRIDE);
    #pragma unroll
    for (int j = 0; j < 8; j++){
      asm volatile("cp.async.cg.shared.global [%0], [%1], 16;" :: "r"(da + j*16), "l"(Ag + j*4));
      asm volatile("cp.async.cg.shared.global [%0], [%1], 16;" :: "r"(db + j*16), "l"(Bg + j*4));
    }
    asm volatile("cp.async.commit_group;");
  };

  load_chunk(0, 0);

  for (int i = 0; i < nch; i++){
    int st = i & 1;
    if (i + 1 < nch){
      load_chunk(i+1, st^1);
      asm volatile("cp.async.wait_group 1;" ::: "memory");
    } else {
      asm volatile("cp.async.wait_group 0;" ::: "memory");
    }
    __syncthreads();

    const float* Ast = As + st*STAGE_F;
    const float* Bst = Bs + st*STAGE_F;

    #pragma unroll
    for (int ks = 0; ks < 4; ks++){
      int kb = ks*8;
      uint32_t af[4][4];
      #pragma unroll
      for (int mt = 0; mt < 4; mt++){
        const float* ap = Ast + (wr + mt*16 + g)*TSTRIDE + kb + tg;
        af[mt][0] = f2tf32(ap[0]);
        af[mt][1] = f2tf32(ap[8*TSTRIDE]);
        af[mt][2] = f2tf32(ap[4]);
        af[mt][3] = f2tf32(ap[8*TSTRIDE + 4]);
      }
      uint32_t bf[8][2];
      #pragma unroll
      for (int nt = 0; nt < 8; nt++){
        const float* bp = Bst + (wc + nt*8 + g)*TSTRIDE + kb + tg;
        bf[nt][0] = f2tf32(bp[0]);
        bf[nt][1] = f2tf32(bp[4]);
      }
      #pragma unroll
      for (int mt = 0; mt < 4; mt++)
        #pragma unroll
        for (int nt = 0; nt < 8; nt++){
          asm volatile(
            "mma.sync.aligned.m16n8k8.row.col.f32.tf32.tf32.f32 "
            "{%0,%1,%2,%3}, {%4,%5,%6,%7}, {%8,%9}, {%0,%1,%2,%3};"
            : "+f"(acc[mt][nt][0]), "+f"(acc[mt][nt][1]),
              "+f"(acc[mt][nt][2]), "+f"(acc[mt][nt][3])
            : "r"(af[mt][0]), "r"(af[mt][1]), "r"(af[mt][2]), "r"(af[mt][3]),
              "r"(bf[nt][0]), "r"(bf[nt][1]));
        }
    }
    __syncthreads();
  }

  // epilogue (generalized C placement)
  float* Cb = C + (long long)(z/cdiv)*sC1 + (long long)(z%cdiv)*sC2;
  #pragma unroll
  for (int mt = 0; mt < 4; mt++){
    long long r0 = bm + wr + mt*16 + g;
    #pragma unroll
    for (int nt = 0; nt < 8; nt++){
      long long c0 = bn + wc + nt*8 + 2*tg;
      float2 v0 = make_float2(acc[mt][nt][0]*alp, acc[mt][nt][1]*alp);
      float2 v1 = make_float2(acc[mt][nt][2]*alp, acc[mt][nt][3]*alp);
      *(float2*)(Cb + r0*ldc + c0)     = v0;
      *(float2*)(Cb + (r0+8)*ldc + c0) = v1;
    }
  }
}

// ---------------- adaln embedding: e = silu(vec) @ W^T + b ----------------
__global__ void k_emb(const float* __restrict__ vec, const float* __restrict__ W,
                      const float* __restrict__ bias, float* __restrict__ e)
{
  int b = blockIdx.y;
  __shared__ float s[DM];
  for (int i = threadIdx.x; i < DM; i += blockDim.x){
    float v = vec[b*DM + i];
    s[i] = v / (1.f + expf(-v));
  }
  __syncthreads();
  int n = blockIdx.x*blockDim.x + threadIdx.x;
  const float* wr = W + (long long)n*DM;
  float acc = 0.f;
  #pragma unroll 8
  for (int k = 0; k < DM; k++) acc += s[k]*wr[k];
  e[b*E6 + n] = acc + bias[n];
}

// ---------------- eff = SCALE / max(mean(temp), 0.1) ----------------
__global__ void k_eff(const float* __restrict__ t, float* __restrict__ eff){
  int b = threadIdx.x;
  if (b < NB){
    float m = 0.25f*(t[b*NHD+0]+t[b*NHD+1]+t[b*NHD+2]+t[b*NHD+3]);
    eff[b] = SCALE_C / fmaxf(m, 0.1f);
  }
}

// ---------------- mod[b,h,n] = exp(clip(bilerp(sol_spatial) * w[h] + b[h], -2, 2)) ----------------
__global__ void k_mod(const float* __restrict__ sp, const float* __restrict__ mw,
                      const float* __restrict__ mb, float* __restrict__ mod)
{
  int idx = blockIdx.x*blockDim.x + threadIdx.x;
  if (idx >= NB*NHD*NI) return;
  int n = idx & (NI-1);
  int h = (idx >> 11) & (NHD-1);
  int b = idx >> 13;
  int y = n >> 5;          // W = 32
  int x = n & 31;
  float fy = (y + 0.5f)*0.125f - 0.5f;   // 64 <- 8
  float fx = (x + 0.5f)*0.25f  - 0.5f;   // 32 <- 8
  int y0 = (int)floorf(fy); float wy = fy - (float)y0;
  int x0 = (int)floorf(fx); float wx = fx - (float)x0;
  int y0c = min(max(y0,0),7), y1c = min(max(y0+1,0),7);
  int x0c = min(max(x0,0),7), x1c = min(max(x0+1,0),7);
  const float* p = sp + b*64;
  float v = (1.f-wy)*((1.f-wx)*p[y0c*8+x0c] + wx*p[y0c*8+x1c])
          +      wy *((1.f-wx)*p[y1c*8+x0c] + wx*p[y1c*8+x1c]);
  v = v*mw[h] + mb[h];
  v = fminf(fmaxf(v, -2.f), 2.f);
  mod[idx] = expf(v);
}

// ---------------- rms-norm + adaln modulate ----------------
__global__ __launch_bounds__(128) void k_rmsmod(
    const float* __restrict__ x, const float* __restrict__ w,
    const float* __restrict__ e, int shift_off, int scale_off,
    float* __restrict__ out, int tok_per_b)
{
  int row = blockIdx.x;
  int b = row / tok_per_b;
  float4 xv = ((const float4*)(x + (long long)row*DM))[threadIdx.x];
  float ss = xv.x*xv.x + xv.y*xv.y + xv.z*xv.z + xv.w*xv.w;
  ss = warpSum(ss);
  __shared__ float red[4];
  int lane = threadIdx.x & 31, wid = threadIdx.x >> 5;
  if (lane==0) red[wid]=ss;
  __syncthreads();
  float tot = red[0]+red[1]+red[2]+red[3];
  float inv = rsqrtf(tot*(1.f/DM) + 1e-6f);
  int c = threadIdx.x*4;
  const float* eb = e + b*E6;
  float4 o;
  o.x = xv.x*inv*w[c+0]*(1.f+eb[scale_off+c+0]) + eb[shift_off+c+0];
  o.y = xv.y*inv*w[c+1]*(1.f+eb[scale_off+c+1]) + eb[shift_off+c+1];
  o.z = xv.z*inv*w[c+2]*(1.f+eb[scale_off+c+2]) + eb[shift_off+c+2];
  o.w = xv.w*inv*w[c+3]*(1.f+eb[scale_off+c+3]) + eb[shift_off+c+3];
  ((float4*)(out + (long long)row*DM))[threadIdx.x] = o;
}

// ---------------- scatter img qkv: rope + mod, build Q, K(+512 offset), V^T ----------------
__global__ void k_scatter_img(const float* __restrict__ qkv, const float* __restrict__ rope,
                              const float* __restrict__ mod,
                              float* __restrict__ Q, float* __restrict__ K,
                              float* __restrict__ VT)
{
  int idx = blockIdx.x*blockDim.x + threadIdx.x;   // NB*NHD*NI*64
  int d2 = idx & 63;
  int r  = idx >> 6;            // bh*NI + n
  int n  = r & (NI-1);
  int bh = r >> 11;
  int h  = bh & (NHD-1);
  int b  = bh >> 2;
  const float* base = qkv + ((long long)(b*NI + n))*(3*NHD*HDD) + h*HDD + 2*d2;
  float2 q = *(const float2*)(base);
  float2 k = *(const float2*)(base + NHD*HDD);
  float2 v = *(const float2*)(base + 2*NHD*HDD);
  float c = rope[n*HDD + 2*d2];
  float s = rope[n*HDD + 2*d2 + 1];
  float m = mod[r];
  float q0 = (q.x*c - q.y*s)*m, q1 = (q.y*c + q.x*s)*m;
  float k0 = (k.x*c - k.y*s)*m, k1 = (k.y*c + k.x*s)*m;
  *(float2*)(Q + (long long)r*HDD + 2*d2) = make_float2(q0,q1);
  long long kv = (long long)bh*KVL + (LT + n);
  *(float2*)(K + kv*HDD + 2*d2) = make_float2(k0,k1);
  VT[((long long)bh*HDD + 2*d2  )*KVL + (LT+n)] = v.x;
  VT[((long long)bh*HDD + 2*d2+1)*KVL + (LT+n)] = v.y;
}

// ---------------- scatter txt qkv ----------------
__global__ void k_scatter_txt(const float* __restrict__ qkv,
                              float* __restrict__ Q, float* __restrict__ K,
                              float* __restrict__ VT)
{
  int idx = blockIdx.x*blockDim.x + threadIdx.x;   // NB*NHD*LT*64
  int d2 = idx & 63;
  int r  = idx >> 6;            // bh*LT + l
  int l  = r & (LT-1);
  int bh = r >> 9;
  int h  = bh & (NHD-1);
  int b  = bh >> 2;
  const float* base = qkv + ((long long)(b*LT + l))*(3*NHD*HDD) + h*HDD + 2*d2;
  float2 q = *(const float2*)(base);
  float2 k = *(const float2*)(base + NHD*HDD);
  float2 v = *(const float2*)(base + 2*NHD*HDD);
  *(float2*)(Q + (long long)r*HDD + 2*d2) = q;
  long long kv = (long long)bh*KVL + l;
  *(float2*)(K + kv*HDD + 2*d2) = k;
  VT[((long long)bh*HDD + 2*d2  )*KVL + l] = v.x;
  VT[((long long)bh*HDD + 2*d2+1)*KVL + l] = v.y;
}

// ---------------- softmax over rows of length KVL ----------------
__global__ __launch_bounds__(256) void k_softmax(float* __restrict__ S){
  long long row = blockIdx.x;
  float* p = S + row*KVL;
  int tid = threadIdx.x;
  float v[10];
  float m = -1e30f;
  #pragma unroll
  for (int i=0;i<10;i++){ v[i] = p[tid + i*256]; m = fmaxf(m, v[i]); }
  m = warpMax(m);
  __shared__ float redm[8];
  __shared__ float reds[8];
  int lane = tid & 31, wid = tid >> 5;
  if (lane==0) redm[wid]=m;
  __syncthreads();
  float bm = redm[0];
  #pragma unroll
  for (int i=1;i<8;i++) bm = fmaxf(bm, redm[i]);
  float sum = 0.f;
  #pragma unroll
  for (int i=0;i<10;i++){ v[i] = __expf(v[i]-bm); sum += v[i]; }
  sum = warpSum(sum);
  if (lane==0) reds[wid]=sum;
  __syncthreads();
  float tot = reds[0]+reds[1]+reds[2]+reds[3]+reds[4]+reds[5]+reds[6]+reds[7];
  float inv = 1.f/tot;
  #pragma unroll
  for (int i=0;i<10;i++) p[tid + i*256] = v[i]*inv;
}

// ---------------- out = res + e[b, off + d] * x ----------------
__global__ void k_resgate(const float* __restrict__ res, const float* __restrict__ x,
                          const float* __restrict__ e, int off,
                          float* __restrict__ out, int T)
{
  int idx = blockIdx.x*blockDim.x + threadIdx.x;
  if (idx >= NB*T*DM) return;
  int d = idx & (DM-1);
  int b = (idx >> 9) / T;
  out[idx] = res[idx] + e[b*E6 + off + d]*x[idx];
}

// ---------------- h = gelu_tanh(h + bias) ----------------
__global__ void k_biasgelu(float* __restrict__ h, const float* __restrict__ bias, int total){
  int idx = blockIdx.x*blockDim.x + threadIdx.x;
  if (idx >= total) return;
  float x = h[idx] + bias[idx & (FFD-1)];
  float x3 = x*x*x;
  float t = tanhf(0.7978845608028654f*(x + 0.044715f*x3));
  h[idx] = 0.5f*x*(1.f+t);
}

// ---------------- out = cur + e[b, 2560 + d]*(x + bias[d]) ----------------
__global__ void k_final(const float* __restrict__ cur, const float* __restrict__ x,
                        const float* __restrict__ e, const float* __restrict__ bias,
                        float* __restrict__ out, int T)
{
  int idx = blockIdx.x*blockDim.x + threadIdx.x;
  if (idx >= NB*T*DM) return;
  int d = idx & (DM-1);
  int b = (idx >> 9) / T;
  out[idx] = cur[idx] + e[b*E6 + 2560 + d]*(x[idx] + bias[d]);
}

// ---------------- launch ----------------
#define GETSYM(var, sym) float* var; cudaGetSymbolAddress((void**)&var, sym)

extern "C" void kernel_launch(void* const* d_in, const int* in_sizes, int n_in,
                              void* d_out, int out_size)
{
  const float* txt          = (const float*)d_in[0];
  const float* img          = (const float*)d_in[1];
  const float* vec          = (const float*)d_in[2];
  const float* rope         = (const float*)d_in[3];
  const float* sol_t        = (const float*)d_in[4];
  const float* sol_s        = (const float*)d_in[5];
  const float* img_adaln_w  = (const float*)d_in[6];
  const float* img_adaln_b  = (const float*)d_in[7];
  const float* img_adaln_nw = (const float*)d_in[8];
  const float* txt_adaln_w  = (const float*)d_in[9];
  const float* txt_adaln_b  = (const float*)d_in[10];
  const float* txt_adaln_nw = (const float*)d_in[11];
  const float* txt_qkv_w    = (const float*)d_in[12];
  const float* img_qkv_w    = (const float*)d_in[13];
  const float* txt_out_w    = (const float*)d_in[14];
  const float* img_out_w    = (const float*)d_in[15];
  const float* sol_mod_w    = (const float*)d_in[16];
  const float* sol_mod_b    = (const float*)d_in[17];
  const float* img_norm2_w  = (const float*)d_in[18];
  const float* txt_norm2_w  = (const float*)d_in[19];
  const float* img_fc1_w    = (const float*)d_in[20];
  const float* img_fc1_b    = (const float*)d_in[21];
  const float* img_fc2_w    = (const float*)d_in[22];
  const float* img_fc2_b    = (const float*)d_in[23];
  const float* txt_fc1_w    = (const float*)d_in[24];
  const float* txt_fc1_b    = (const float*)d_in[25];
  const float* txt_fc2_w    = (const float*)d_in[26];
  const float* txt_fc2_b    = (const float*)d_in[27];
  float* out = (float*)d_out;

  GETSYM(e_img, d_e_img);  GETSYM(e_txt, d_e_txt);
  GETSYM(eff, d_eff);      GETSYM(mod, d_mod);
  GETSYM(nimg, d_nimg);    GETSYM(ntxt, d_ntxt);
  GETSYM(qkvi, d_qkvi);    GETSYM(qkvt, d_qkvt);
  GETSYM(Qi, d_Qi);        GETSYM(Qt, d_Qt);
  GETSYM(Kc, d_Kc);        GETSYM(VT, d_VT);
  GETSYM(St, d_St);        GETSYM(Si, d_Si);
  GETSYM(apt, d_apt);      GETSYM(api, d_api);
  GETSYM(prt, d_prt);      GETSYM(pri, d_pri);
  GETSYM(ct, d_ct);        GETSYM(ci, d_ci);
  GETSYM(ht, d_ht);        GETSYM(hi, d_hi);

  cudaFuncSetAttribute(tgemm, cudaFuncAttributeMaxDynamicSharedMemorySize, TG_DSMEM);

  // 1. adaln embeddings
  k_emb<<<dim3(E6/256, NB), 256>>>(vec, img_adaln_w, img_adaln_b, e_img);
  k_emb<<<dim3(E6/256, NB), 256>>>(vec, txt_adaln_w, txt_adaln_b, e_txt);
  // 2. eff + mod
  k_eff<<<1, 32>>>(sol_t, eff);
  k_mod<<<(NB*NHD*NI)/256, 256>>>(sol_s, sol_mod_w, sol_mod_b, mod);
  // 3. norm1 (shift=sm@0, scale=cm@512)
  k_rmsmod<<<NB*NI, 128>>>(img, img_adaln_nw, e_img, 0, 512, nimg, NI);
  k_rmsmod<<<NB*LT, 128>>>(txt, txt_adaln_nw, e_txt, 0, 512, ntxt, LT);
  // 4. qkv projections
  tgemm<<<dim3(12, 32, 1), 128, TG_DSMEM>>>(nimg, img_qkv_w, qkvi, 1536, DM, 1536,
      0,0,0,0,1, 1.f, nullptr, 1);
  tgemm<<<dim3(12,  8, 1), 128, TG_DSMEM>>>(ntxt, txt_qkv_w, qkvt, 1536, DM, 1536,
      0,0,0,0,1, 1.f, nullptr, 1);
  // 5. scatter -> Q, K, V^T (rope + mod on img)
  k_scatter_img<<<(NB*NHD*NI*64)/256, 256>>>(qkvi, rope, mod, Qi, Kc, VT);
  k_scatter_txt<<<(NB*NHD*LT*64)/256, 256>>>(qkvt, Qt, Kc, VT);
  // 6. scores: S = alpha * Q @ K^T, batched over 8 (b,h)
  tgemm<<<dim3(KVL/128, LT/128, NB*NHD), 128, TG_DSMEM>>>(Qt, Kc, St, KVL, HDD, KVL,
      (long long)LT*HDD, (long long)KVL*HDD, (long long)LT*KVL, 0, 1, SCALE_C, nullptr, 1);
  tgemm<<<dim3(KVL/128, NI/128, NB*NHD), 128, TG_DSMEM>>>(Qi, Kc, Si, KVL, HDD, KVL,
      (long long)NI*HDD, (long long)KVL*HDD, (long long)NI*KVL, 0, 1, 1.f, eff, NHD);
  // 7. softmax
  k_softmax<<<NB*NHD*LT, 256>>>(St);
  k_softmax<<<NB*NHD*NI, 256>>>(Si);
  // 8. P @ V, epilogue writes packed [b,t,h*128+d] directly (ldc=DM, split z offset)
  tgemm<<<dim3(1, LT/128, NB*NHD), 128, TG_DSMEM>>>(St, VT, apt, HDD, KVL, DM,
      (long long)LT*KVL, (long long)HDD*KVL, (long long)LT*DM, (long long)HDD, NHD,
      1.f, nullptr, 1);
  tgemm<<<dim3(1, NI/128, NB*NHD), 128, TG_DSMEM>>>(Si, VT, api, HDD, KVL, DM,
      (long long)NI*KVL, (long long)HDD*KVL, (long long)NI*DM, (long long)HDD, NHD,
      1.f, nullptr, 1);
  // 9. output projections
  tgemm<<<dim3(4,  8, 1), 128, TG_DSMEM>>>(apt, txt_out_w, prt, DM, DM, DM,
      0,0,0,0,1, 1.f, nullptr, 1);
  tgemm<<<dim3(4, 32, 1), 128, TG_DSMEM>>>(api, img_out_w, pri, DM, DM, DM,
      0,0,0,0,1, 1.f, nullptr, 1);
  // 10. attention residual with gate gm@1024
  k_resgate<<<(NB*LT*DM)/256, 256>>>(txt, prt, e_txt, 1024, ct, LT);
  k_resgate<<<(NB*NI*DM)/256, 256>>>(img, pri, e_img, 1024, ci, NI);
  // 11. norm2 (shift=sp@1536, scale=cp@2048)
  k_rmsmod<<<NB*LT, 128>>>(ct, txt_norm2_w, e_txt, 1536, 2048, ntxt, LT);
  k_rmsmod<<<NB*NI, 128>>>(ci, img_norm2_w, e_img, 1536, 2048, nimg, NI);
  // 12. mlp fc1
  tgemm<<<dim3(16,  8, 1), 128, TG_DSMEM>>>(ntxt, txt_fc1_w, ht, FFD, DM, FFD,
      0,0,0,0,1, 1.f, nullptr, 1);
  tgemm<<<dim3(16, 32, 1), 128, TG_DSMEM>>>(nimg, img_fc1_w, hi, FFD, DM, FFD,
      0,0,0,0,1, 1.f, nullptr, 1);
  // 13. bias + gelu
  k_biasgelu<<<(NB*LT*FFD)/256, 256>>>(ht, txt_fc1_b, NB*LT*FFD);
  k_biasgelu<<<(NB*NI*FFD)/256, 256>>>(hi, img_fc1_b, NB*NI*FFD);
  // 14. mlp fc2 (reuse proj buffers)
  tgemm<<<dim3(4,  8, 1), 128, TG_DSMEM>>>(ht, txt_fc2_w, prt, DM, FFD, DM,
      0,0,0,0,1, 1.f, nullptr, 1);
  tgemm<<<dim3(4, 32, 1), 128, TG_DSMEM>>>(hi, img_fc2_w, pri, DM, FFD, DM,
      0,0,0,0,1, 1.f, nullptr, 1);
  // 15. final residual with gate gp@2560 (+fc2 bias) -> d_out (txt first, then img)
  k_final<<<(NB*LT*DM)/256, 256>>>(ct, prt, e_txt, txt_fc2_b, out, LT);
  k_final<<<(NB*NI*DM)/256, 256>>>(ci, pri, e_img, img_fc2_b, out + NB*LT*DM, NI);
}

// round 5
// speedup vs baseline: 1.2132x; 1.2132x over previous
#include <cuda_runtime.h>
#include <math.h>
#include <stdint.h>

// ---------------- problem dims (fixed) ----------------
#define NB   2      // batch
#define LT   512    // txt tokens
#define NI   2048   // img tokens (H=64, W=32)
#define DM   512    // model dim
#define NHD  4      // heads
#define HDD  128    // head dim
#define FFD  2048   // mlp hidden
#define KVL  2560   // LT + NI
#define E6   3072   // 6*DM adaln embedding
#define MT   (NB*LT)          // 1024 txt rows
#define MI   (NB*NI)          // 4096 img rows
#define MALL (MT+MI)          // 5120 combined rows
#define SCALE_C 0.08838834764831845f  // 128^-0.5
#define BIGR (1<<30)

// ---------------- scratch (__device__ globals; allocation-free) ----------------
__device__ __align__(256) float d_e_img[NB*E6];
__device__ __align__(256) float d_e_txt[NB*E6];
__device__ __align__(256) float d_eff[NB];
__device__ __align__(256) float d_mod[NB*NHD*NI];
__device__ __align__(256) float d_nrm[MALL*DM];        // norm outputs (norm1, then norm2)
__device__ __align__(256) float d_qkv[MALL*3*NHD*HDD]; // combined qkv
__device__ __align__(256) float d_Qc[NB*NHD*KVL*HDD];  // Q combined (txt rows 0-511, img 512+)
__device__ __align__(256) float d_Kc[NB*NHD*KVL*HDD];
__device__ __align__(256) float d_VT[NB*NHD*HDD*KVL];
__device__ __align__(256) float d_S[NB*NHD*KVL*KVL];   // combined scores
__device__ __align__(256) float d_ap[MALL*DM];         // attention out, packed
__device__ __align__(256) float d_pr[MALL*DM];         // proj / fc2 out
__device__ __align__(256) float d_c[MALL*DM];          // post-attn residual
__device__ __align__(256) float d_h[MALL*FFD];         // mlp hidden

// ---------------- helpers ----------------
__device__ __forceinline__ float warpSum(float v){
  #pragma unroll
  for (int o=16;o>0;o>>=1) v += __shfl_xor_sync(0xffffffffu, v, o);
  return v;
}
__device__ __forceinline__ float warpMax(float v){
  #pragma unroll
  for (int o=16;o>0;o>>=1) v = fmaxf(v, __shfl_xor_sync(0xffffffffu, v, o));
  return v;
}
__device__ __forceinline__ uint32_t sptr(const void* p){
  uint32_t r;
  asm("{ .reg .u64 t; cvta.to.shared.u64 t, %1; cvt.u32.u64 %0, t; }" : "=r"(r) : "l"(p));
  return r;
}
__device__ __forceinline__ uint32_t f2tf32(float x){
  uint32_t r;
  asm("cvt.rna.tf32.f32 %0, %1;" : "=r"(r) : "f"(x));
  return r;
}

// ================= tf32 mma.sync batched GEMM: C = alpha * A(MxK) @ Bsel(NxK)^T =================
// CTA tile 128x128, 8 warps (2x4), warp tile 64x32 (R3 config), K-chunk 32, double-buffered cp.async.
// B selected per M-region (bm < msplit ? B1 : B2).
// C address: C + [bm<rsplit ? (z/zdiv)*sCt : cbase+(z/zdiv)*sCi] + (z%zdiv)*sCh + row*ldc + col
//   (region-2 row rebase folded into cbase).
// alpha: bm<arsplit ? alpha : alphas[z/adiv].
#define TSTRIDE 36
#define STAGE_F (128*TSTRIDE)
#define TG_DSMEM (4*STAGE_F*4)   // 73728 B

__global__ __launch_bounds__(256) void tgemm(
    const float* __restrict__ A, const float* __restrict__ B1,
    const float* __restrict__ B2, int msplit,
    float* __restrict__ C, int N, int K, int ldc,
    long long sA, long long sB,
    int rsplit, int zdiv, long long sCt, long long sCi, long long sCh, long long cbase,
    float alpha, const float* __restrict__ alphas, int adiv, int arsplit)
{
  extern __shared__ float smem[];
  float* As = smem;
  float* Bs = smem + 2*STAGE_F;

  const int tid = threadIdx.x;
  const int z   = blockIdx.z;
  const long long bm = (long long)blockIdx.y * 128;
  const long long bn = (long long)blockIdx.x * 128;

  const float* Ab = A + z*sA + bm*K;
  const float* Bsel = (bm < msplit) ? B1 : B2;
  const float* Bb = Bsel + z*sB + bn*K;

  float alp = ((int)bm < arsplit) ? alpha : alphas[z/adiv];
  long long zoff = ((int)bm < rsplit)
      ? (long long)(z/zdiv)*sCt + (long long)(z%zdiv)*sCh
      : cbase + (long long)(z/zdiv)*sCi + (long long)(z%zdiv)*sCh;

  const int lw  = tid & 31;
  const int w   = tid >> 5;
  const int wr  = (w >> 2) * 64;
  const int wc  = (w & 3) * 32;
  const int g   = lw >> 2;
  const int tg  = lw & 3;

  const int lrow = tid >> 1;
  const int lcol = (tid & 1) * 16;

  float acc[4][4][4];
  #pragma unroll
  for (int i=0;i<4;i++)
    #pragma unroll
    for (int j=0;j<4;j++)
      #pragma unroll
      for (int q=0;q<4;q++) acc[i][j][q] = 0.f;

  const int nch = K >> 5;

  auto load_chunk = [&](int c, int st){
    const float* Ag = Ab + (long long)lrow*K + c*32 + lcol;
    const float* Bg = Bb + (long long)lrow*K + c*32 + lcol;
    uint32_t da = sptr(As + st*STAGE_F + lrow*TSTRIDE + lcol);
    uint32_t db = sptr(Bs + st*STAGE_F + lrow*TSTRIDE + lcol);
    #pragma unroll
    for (int j = 0; j < 4; j++){
      asm volatile("cp.async.cg.shared.global [%0], [%1], 16;" :: "r"(da + j*16), "l"(Ag + j*4));
      asm volatile("cp.async.cg.shared.global [%0], [%1], 16;" :: "r"(db + j*16), "l"(Bg + j*4));
    }
    asm volatile("cp.async.commit_group;");
  };

  load_chunk(0, 0);

  for (int i = 0; i < nch; i++){
    int st = i & 1;
    if (i + 1 < nch){
      load_chunk(i+1, st^1);
      asm volatile("cp.async.wait_group 1;" ::: "memory");
    } else {
      asm volatile("cp.async.wait_group 0;" ::: "memory");
    }
    __syncthreads();

    const float* Ast = As + st*STAGE_F;
    const float* Bst = Bs + st*STAGE_F;

    #pragma unroll
    for (int ks = 0; ks < 4; ks++){
      int kb = ks*8;
      uint32_t af[4][4];
      #pragma unroll
      for (int mt = 0; mt < 4; mt++){
        const float* ap = Ast + (wr + mt*16 + g)*TSTRIDE + kb + tg;
        af[mt][0] = f2tf32(ap[0]);
        af[mt][1] = f2tf32(ap[8*TSTRIDE]);
        af[mt][2] = f2tf32(ap[4]);
        af[mt][3] = f2tf32(ap[8*TSTRIDE + 4]);
      }
      uint32_t bf[4][2];
      #pragma unroll
      for (int nt = 0; nt < 4; nt++){
        const float* bp = Bst + (wc + nt*8 + g)*TSTRIDE + kb + tg;
        bf[nt][0] = f2tf32(bp[0]);
        bf[nt][1] = f2tf32(bp[4]);
      }
      #pragma unroll
      for (int mt = 0; mt < 4; mt++)
        #pragma unroll
        for (int nt = 0; nt < 4; nt++){
          asm volatile(
            "mma.sync.aligned.m16n8k8.row.col.f32.tf32.tf32.f32 "
            "{%0,%1,%2,%3}, {%4,%5,%6,%7}, {%8,%9}, {%0,%1,%2,%3};"
            : "+f"(acc[mt][nt][0]), "+f"(acc[mt][nt][1]),
              "+f"(acc[mt][nt][2]), "+f"(acc[mt][nt][3])
            : "r"(af[mt][0]), "r"(af[mt][1]), "r"(af[mt][2]), "r"(af[mt][3]),
              "r"(bf[nt][0]), "r"(bf[nt][1]));
        }
    }
    __syncthreads();
  }

  // epilogue
  float* Cb = C + zoff;
  #pragma unroll
  for (int mt = 0; mt < 4; mt++){
    long long r0 = bm + wr + mt*16 + g;
    #pragma unroll
    for (int nt = 0; nt < 4; nt++){
      long long c0 = bn + wc + nt*8 + 2*tg;
      float2 v0 = make_float2(acc[mt][nt][0]*alp, acc[mt][nt][1]*alp);
      float2 v1 = make_float2(acc[mt][nt][2]*alp, acc[mt][nt][3]*alp);
      *(float2*)(Cb + r0*ldc + c0)     = v0;
      *(float2*)(Cb + (r0+8)*ldc + c0) = v1;
    }
  }
}

// ---------------- adaln embedding: e = silu(vec) @ W^T + b ----------------
__global__ void k_emb(const float* __restrict__ vec, const float* __restrict__ W,
                      const float* __restrict__ bias, float* __restrict__ e)
{
  int b = blockIdx.y;
  __shared__ float s[DM];
  for (int i = threadIdx.x; i < DM; i += blockDim.x){
    float v = vec[b*DM + i];
    s[i] = v / (1.f + expf(-v));
  }
  __syncthreads();
  int n = blockIdx.x*blockDim.x + threadIdx.x;
  const float* wr = W + (long long)n*DM;
  float acc = 0.f;
  #pragma unroll 8
  for (int k = 0; k < DM; k++) acc += s[k]*wr[k];
  e[b*E6 + n] = acc + bias[n];
}

// ---------------- eff = SCALE / max(mean(temp), 0.1) ----------------
__global__ void k_eff(const float* __restrict__ t, float* __restrict__ eff){
  int b = threadIdx.x;
  if (b < NB){
    float m = 0.25f*(t[b*NHD+0]+t[b*NHD+1]+t[b*NHD+2]+t[b*NHD+3]);
    eff[b] = SCALE_C / fmaxf(m, 0.1f);
  }
}

// ---------------- mod[b,h,n] = exp(clip(bilerp(sol_spatial)*w[h]+b[h], -2, 2)) ----------------
__global__ void k_mod(const float* __restrict__ sp, const float* __restrict__ mw,
                      const float* __restrict__ mb, float* __restrict__ mod)
{
  int idx = blockIdx.x*blockDim.x + threadIdx.x;
  if (idx >= NB*NHD*NI) return;
  int n = idx & (NI-1);
  int h = (idx >> 11) & (NHD-1);
  int b = idx >> 13;
  int y = n >> 5;
  int x = n & 31;
  float fy = (y + 0.5f)*0.125f - 0.5f;
  float fx = (x + 0.5f)*0.25f  - 0.5f;
  int y0 = (int)floorf(fy); float wy = fy - (float)y0;
  int x0 = (int)floorf(fx); float wx = fx - (float)x0;
  int y0c = min(max(y0,0),7), y1c = min(max(y0+1,0),7);
  int x0c = min(max(x0,0),7), x1c = min(max(x0+1,0),7);
  const float* p = sp + b*64;
  float v = (1.f-wy)*((1.f-wx)*p[y0c*8+x0c] + wx*p[y0c*8+x1c])
          +      wy *((1.f-wx)*p[y1c*8+x0c] + wx*p[y1c*8+x1c]);
  v = v*mw[h] + mb[h];
  v = fminf(fmaxf(v, -2.f), 2.f);
  mod[idx] = expf(v);
}

// ---------------- combined rms-norm + adaln modulate over MALL rows ----------------
__global__ __launch_bounds__(128) void k_rmsmod(
    const float* __restrict__ xt, const float* __restrict__ xi,
    const float* __restrict__ wt, const float* __restrict__ wi,
    const float* __restrict__ et, const float* __restrict__ ei,
    int shift_off, int scale_off, float* __restrict__ out)
{
  int row = blockIdx.x;
  const float* x; const float* w; const float* eb;
  if (row < MT){
    x = xt + (long long)row*DM; w = wt; eb = et + (row/LT)*E6;
  } else {
    int rr = row - MT;
    x = xi + (long long)rr*DM; w = wi; eb = ei + (rr/NI)*E6;
  }
  float4 xv = ((const float4*)x)[threadIdx.x];
  float ss = xv.x*xv.x + xv.y*xv.y + xv.z*xv.z + xv.w*xv.w;
  ss = warpSum(ss);
  __shared__ float red[4];
  int lane = threadIdx.x & 31, wid = threadIdx.x >> 5;
  if (lane==0) red[wid]=ss;
  __syncthreads();
  float tot = red[0]+red[1]+red[2]+red[3];
  float inv = rsqrtf(tot*(1.f/DM) + 1e-6f);
  int c = threadIdx.x*4;
  float4 o;
  o.x = xv.x*inv*w[c+0]*(1.f+eb[scale_off+c+0]) + eb[shift_off+c+0];
  o.y = xv.y*inv*w[c+1]*(1.f+eb[scale_off+c+1]) + eb[shift_off+c+1];
  o.z = xv.z*inv*w[c+2]*(1.f+eb[scale_off+c+2]) + eb[shift_off+c+2];
  o.w = xv.w*inv*w[c+3]*(1.f+eb[scale_off+c+3]) + eb[shift_off+c+3];
  ((float4*)(out + (long long)row*DM))[threadIdx.x] = o;
}

// ---------------- scatter img qkv: rope + mod -> Qc/Kc rows 512+, V^T ----------------
__global__ void k_scatter_img(const float* __restrict__ qkv, const float* __restrict__ rope,
                              const float* __restrict__ mod,
                              float* __restrict__ Q, float* __restrict__ K,
                              float* __restrict__ VT)
{
  int idx = blockIdx.x*blockDim.x + threadIdx.x;   // NB*NHD*NI*64
  int d2 = idx & 63;
  int r  = idx >> 6;            // bh*NI + n
  int n  = r & (NI-1);
  int bh = r >> 11;
  int h  = bh & (NHD-1);
  int b  = bh >> 2;
  const float* base = qkv + ((long long)(MT + b*NI + n))*(3*NHD*HDD) + h*HDD + 2*d2;
  float2 q = *(const float2*)(base);
  float2 k = *(const float2*)(base + NHD*HDD);
  float2 v = *(const float2*)(base + 2*NHD*HDD);
  float c = rope[n*HDD + 2*d2];
  float s = rope[n*HDD + 2*d2 + 1];
  float m = mod[r];
  float q0 = (q.x*c - q.y*s)*m, q1 = (q.y*c + q.x*s)*m;
  float k0 = (k.x*c - k.y*s)*m, k1 = (k.y*c + k.x*s)*m;
  long long kv = (long long)bh*KVL + (LT + n);
  *(float2*)(Q + kv*HDD + 2*d2) = make_float2(q0,q1);
  *(float2*)(K + kv*HDD + 2*d2) = make_float2(k0,k1);
  VT[((long long)bh*HDD + 2*d2  )*KVL + (LT+n)] = v.x;
  VT[((long long)bh*HDD + 2*d2+1)*KVL + (LT+n)] = v.y;
}

// ---------------- scatter txt qkv -> Qc/Kc rows 0-511, V^T ----------------
__global__ void k_scatter_txt(const float* __restrict__ qkv,
                              float* __restrict__ Q, float* __restrict__ K,
                              float* __restrict__ VT)
{
  int idx = blockIdx.x*blockDim.x + threadIdx.x;   // NB*NHD*LT*64
  int d2 = idx & 63;
  int r  = idx >> 6;            // bh*LT + l
  int l  = r & (LT-1);
  int bh = r >> 9;
  int h  = bh & (NHD-1);
  int b  = bh >> 2;
  const float* base = qkv + ((long long)(b*LT + l))*(3*NHD*HDD) + h*HDD + 2*d2;
  float2 q = *(const float2*)(base);
  float2 k = *(const float2*)(base + NHD*HDD);
  float2 v = *(const float2*)(base + 2*NHD*HDD);
  long long kv = (long long)bh*KVL + l;
  *(float2*)(Q + kv*HDD + 2*d2) = q;
  *(float2*)(K + kv*HDD + 2*d2) = k;
  VT[((long long)bh*HDD + 2*d2  )*KVL + l] = v.x;
  VT[((long long)bh*HDD + 2*d2+1)*KVL + l] = v.y;
}

// ---------------- softmax over rows of length KVL ----------------
__global__ __launch_bounds__(256) void k_softmax(float* __restrict__ S){
  long long row = blockIdx.x;
  float* p = S + row*KVL;
  int tid = threadIdx.x;
  float v[10];
  float m = -1e30f;
  #pragma unroll
  for (int i=0;i<10;i++){ v[i] = p[tid + i*256]; m = fmaxf(m, v[i]); }
  m = warpMax(m);
  __shared__ float redm[8];
  __shared__ float reds[8];
  int lane = tid & 31, wid = tid >> 5;
  if (lane==0) redm[wid]=m;
  __syncthreads();
  float bm = redm[0];
  #pragma unroll
  for (int i=1;i<8;i++) bm = fmaxf(bm, redm[i]);
  float sum = 0.f;
  #pragma unroll
  for (int i=0;i<10;i++){ v[i] = __expf(v[i]-bm); sum += v[i]; }
  sum = warpSum(sum);
  if (lane==0) reds[wid]=sum;
  __syncthreads();
  float tot = reds[0]+reds[1]+reds[2]+reds[3]+reds[4]+reds[5]+reds[6]+reds[7];
  float inv = 1.f/tot;
  #pragma unroll
  for (int i=0;i<10;i++) p[tid + i*256] = v[i]*inv;
}

// ---------------- combined resgate: out = res + e[gate] * x over MALL rows ----------------
__global__ void k_resgate(const float* __restrict__ rt, const float* __restrict__ ri,
                          const float* __restrict__ x,
                          const float* __restrict__ et, const float* __restrict__ ei,
                          int off, float* __restrict__ out)
{
  int idx = blockIdx.x*blockDim.x + threadIdx.x;
  if (idx >= MALL*DM) return;
  int d = idx & (DM-1);
  int row = idx >> 9;
  float res; const float* eb;
  if (row < MT){ res = rt[idx]; eb = et + (row/LT)*E6; }
  else { res = ri[idx - MT*DM]; eb = ei + ((row-MT)/NI)*E6; }
  out[idx] = res + eb[off + d]*x[idx];
}

// ---------------- h = gelu_tanh(h + bias), region-split bias ----------------
__global__ void k_biasgelu(float* __restrict__ h, const float* __restrict__ bt,
                           const float* __restrict__ bi){
  int idx = blockIdx.x*blockDim.x + threadIdx.x;
  if (idx >= MALL*FFD) return;
  const float* bias = (idx < MT*FFD) ? bt : bi;
  float x = h[idx] + bias[idx & (FFD-1)];
  float x3 = x*x*x;
  float t = tanhf(0.7978845608028654f*(x + 0.044715f*x3));
  h[idx] = 0.5f*x*(1.f+t);
}

// ---------------- final: out = cur + e[2560+d]*(x + bias[d]) over MALL rows ----------------
__global__ void k_final(const float* __restrict__ cur, const float* __restrict__ x,
                        const float* __restrict__ et, const float* __restrict__ ei,
                        const float* __restrict__ bt, const float* __restrict__ bi,
                        float* __restrict__ out)
{
  int idx = blockIdx.x*blockDim.x + threadIdx.x;
  if (idx >= MALL*DM) return;
  int d = idx & (DM-1);
  int row = idx >> 9;
  const float* eb; const float* bias;
  if (row < MT){ eb = et + (row/LT)*E6; bias = bt; }
  else { eb = ei + ((row-MT)/NI)*E6; bias = bi; }
  out[idx] = cur[idx] + eb[2560 + d]*(x[idx] + bias[d]);
}

// ---------------- launch ----------------
#define GETSYM(var, sym) float* var; cudaGetSymbolAddress((void**)&var, sym)

extern "C" void kernel_launch(void* const* d_in, const int* in_sizes, int n_in,
                              void* d_out, int out_size)
{
  const float* txt          = (const float*)d_in[0];
  const float* img          = (const float*)d_in[1];
  const float* vec          = (const float*)d_in[2];
  const float* rope         = (const float*)d_in[3];
  const float* sol_t        = (const float*)d_in[4];
  const float* sol_s        = (const float*)d_in[5];
  const float* img_adaln_w  = (const float*)d_in[6];
  const float* img_adaln_b  = (const float*)d_in[7];
  const float* img_adaln_nw = (const float*)d_in[8];
  const float* txt_adaln_w  = (const float*)d_in[9];
  const float* txt_adaln_b  = (const float*)d_in[10];
  const float* txt_adaln_nw = (const float*)d_in[11];
  const float* txt_qkv_w    = (const float*)d_in[12];
  const float* img_qkv_w    = (const float*)d_in[13];
  const float* txt_out_w    = (const float*)d_in[14];
  const float* img_out_w    = (const float*)d_in[15];
  const float* sol_mod_w    = (const float*)d_in[16];
  const float* sol_mod_b    = (const float*)d_in[17];
  const float* img_norm2_w  = (const float*)d_in[18];
  const float* txt_norm2_w  = (const float*)d_in[19];
  const float* img_fc1_w    = (const float*)d_in[20];
  const float* img_fc1_b    = (const float*)d_in[21];
  const float* img_fc2_w    = (const float*)d_in[22];
  const float* img_fc2_b    = (const float*)d_in[23];
  const float* txt_fc1_w    = (const float*)d_in[24];
  const float* txt_fc1_b    = (const float*)d_in[25];
  const float* txt_fc2_w    = (const float*)d_in[26];
  const float* txt_fc2_b    = (const float*)d_in[27];
  float* out = (float*)d_out;

  GETSYM(e_img, d_e_img);  GETSYM(e_txt, d_e_txt);
  GETSYM(eff, d_eff);      GETSYM(mod, d_mod);
  GETSYM(nrm, d_nrm);      GETSYM(qkv, d_qkv);
  GETSYM(Qc, d_Qc);        GETSYM(Kc, d_Kc);
  GETSYM(VT, d_VT);        GETSYM(S, d_S);
  GETSYM(ap, d_ap);        GETSYM(pr, d_pr);
  GETSYM(cc, d_c);         GETSYM(hh, d_h);

  cudaFuncSetAttribute(tgemm, cudaFuncAttributeMaxDynamicSharedMemorySize, TG_DSMEM);

  // 1. adaln embeddings + eff + mod
  k_emb<<<dim3(E6/256, NB), 256>>>(vec, img_adaln_w, img_adaln_b, e_img);
  k_emb<<<dim3(E6/256, NB), 256>>>(vec, txt_adaln_w, txt_adaln_b, e_txt);
  k_eff<<<1, 32>>>(sol_t, eff);
  k_mod<<<(NB*NHD*NI)/256, 256>>>(sol_s, sol_mod_w, sol_mod_b, mod);
  // 2. norm1 combined (shift=sm@0, scale=cm@512)
  k_rmsmod<<<MALL, 128>>>(txt, img, txt_adaln_nw, img_adaln_nw, e_txt, e_img, 0, 512, nrm);
  // 3. QKV combined (per-region weights)
  tgemm<<<dim3(12, MALL/128, 1), 256, TG_DSMEM>>>(nrm, txt_qkv_w, img_qkv_w, MT,
      qkv, 1536, DM, 1536, 0, 0,
      BIGR, 1, 0, 0, 0, 0, 1.f, eff, 1, BIGR);
  // 4. scatter -> Qc, Kc, V^T
  k_scatter_txt<<<(NB*NHD*LT*64)/256, 256>>>(qkv, Qc, Kc, VT);
  k_scatter_img<<<(NB*NHD*NI*64)/256, 256>>>(qkv, rope, mod, Qc, Kc, VT);
  // 5. scores combined: rows<512 alpha=SCALE_C (txt), rows>=512 alpha=eff[b] (img)
  tgemm<<<dim3(KVL/128, KVL/128, NB*NHD), 256, TG_DSMEM>>>(Qc, Kc, Kc, BIGR,
      S, KVL, HDD, KVL, (long long)KVL*HDD, (long long)KVL*HDD,
      BIGR, 1, (long long)KVL*KVL, 0, 0, 0,
      SCALE_C, eff, NHD, LT);
  // 6. softmax (all 8*2560 rows)
  k_softmax<<<NB*NHD*KVL, 256>>>(S);
  // 7. P @ V -> packed [token, h*128+d] directly
  tgemm<<<dim3(1, KVL/128, NB*NHD), 256, TG_DSMEM>>>(S, VT, VT, BIGR,
      ap, HDD, KVL, DM, (long long)KVL*KVL, (long long)HDD*KVL,
      LT, NHD, (long long)LT*DM, (long long)NI*DM, HDD,
      (long long)MT*DM - (long long)LT*DM,
      1.f, eff, 1, BIGR);
  // 8. output projection combined
  tgemm<<<dim3(4, MALL/128, 1), 256, TG_DSMEM>>>(ap, txt_out_w, img_out_w, MT,
      pr, DM, DM, DM, 0, 0,
      BIGR, 1, 0, 0, 0, 0, 1.f, eff, 1, BIGR);
  // 9. attention residual (gate gm@1024)
  k_resgate<<<(MALL*DM)/256, 256>>>(txt, img, pr, e_txt, e_img, 1024, cc);
  // 10. norm2 combined (shift=sp@1536, scale=cp@2048)
  k_rmsmod<<<MALL, 128>>>(cc, cc + (long long)MT*DM, txt_norm2_w, img_norm2_w,
                          e_txt, e_img, 1536, 2048, nrm);
  // 11. fc1 combined
  tgemm<<<dim3(16, MALL/128, 1), 256, TG_DSMEM>>>(nrm, txt_fc1_w, img_fc1_w, MT,
      hh, FFD, DM, FFD, 0, 0,
      BIGR, 1, 0, 0, 0, 0, 1.f, eff, 1, BIGR);
  // 12. bias + gelu
  k_biasgelu<<<(MALL*FFD)/256, 256>>>(hh, txt_fc1_b, img_fc1_b);
  // 13. fc2 combined
  tgemm<<<dim3(4, MALL/128, 1), 256, TG_DSMEM>>>(hh, txt_fc2_w, img_fc2_w, MT,
      pr, DM, FFD, DM, 0, 0,
      BIGR, 1, 0, 0, 0, 0, 1.f, eff, 1, BIGR);
  // 14. final residual (gate gp@2560, + fc2 bias) -> d_out (txt rows then img rows)
  k_final<<<(MALL*DM)/256, 256>>>(cc, pr, e_txt, e_img, txt_fc2_b, img_fc2_b, out);
}

// round 6
// speedup vs baseline: 1.2248x; 1.0096x over previous
#include <cuda_runtime.h>
#include <math.h>
#include <stdint.h>

// ---------------- problem dims (fixed) ----------------
#define NB   2
#define LT   512
#define NI   2048
#define DM   512
#define NHD  4
#define HDD  128
#define FFD  2048
#define KVL  2560
#define E6   3072
#define MT   (NB*LT)
#define MI   (NB*NI)
#define MALL (MT+MI)
#define SCALE_C 0.08838834764831845f
#define BIGR (1<<30)

// ---------------- scratch ----------------
__device__ __align__(256) float d_e_img[NB*E6];
__device__ __align__(256) float d_e_txt[NB*E6];
__device__ __align__(256) float d_eff[NB];
__device__ __align__(256) float d_mod[NB*NHD*NI];
__device__ __align__(256) float d_nrm[MALL*DM];
__device__ __align__(256) float d_qkv[MALL*3*NHD*HDD];
__device__ __align__(256) float d_Qc[NB*NHD*KVL*HDD];
__device__ __align__(256) float d_Kc[NB*NHD*KVL*HDD];
__device__ __align__(256) float d_VT[NB*NHD*HDD*KVL];
__device__ __align__(256) float d_S[NB*NHD*KVL*KVL];
__device__ __align__(256) float d_ap[MALL*DM];
__device__ __align__(256) float d_pr[MALL*DM];
__device__ __align__(256) float d_c[MALL*DM];
__device__ __align__(256) float d_h[MALL*FFD];
// rounded weights
__device__ __align__(256) float d_wq_t[1536*DM];
__device__ __align__(256) float d_wq_i[1536*DM];
__device__ __align__(256) float d_wo_t[DM*DM];
__device__ __align__(256) float d_wo_i[DM*DM];
__device__ __align__(256) float d_w1_t[FFD*DM];
__device__ __align__(256) float d_w1_i[FFD*DM];
__device__ __align__(256) float d_w2_t[DM*FFD];
__device__ __align__(256) float d_w2_i[DM*FFD];

// ---------------- helpers ----------------
__device__ __forceinline__ float warpSum(float v){
  #pragma unroll
  for (int o=16;o>0;o>>=1) v += __shfl_xor_sync(0xffffffffu, v, o);
  return v;
}
__device__ __forceinline__ float warpMax(float v){
  #pragma unroll
  for (int o=16;o>0;o>>=1) v = fmaxf(v, __shfl_xor_sync(0xffffffffu, v, o));
  return v;
}
__device__ __forceinline__ uint32_t sptr(const void* p){
  uint32_t r;
  asm("{ .reg .u64 t; cvta.to.shared.u64 t, %1; cvt.u32.u64 %0, t; }" : "=r"(r) : "l"(p));
  return r;
}
__device__ __forceinline__ uint32_t f2tf32(float x){
  uint32_t r;
  asm("cvt.rna.tf32.f32 %0, %1;" : "=r"(r) : "f"(x));
  return r;
}
__device__ __forceinline__ float RND(float x){ return __uint_as_float(f2tf32(x)); }
__device__ __forceinline__ float4 RND4(float4 v){
  return make_float4(RND(v.x),RND(v.y),RND(v.z),RND(v.w));
}

// ================= tf32 mma.sync batched GEMM (pre-rounded operands) =================
// CTA 128x128, 8 warps (2x4), warp tile 64x32, K-chunk 32, double-buffered cp.async.
#define TSTRIDE 36
#define STAGE_F (128*TSTRIDE)
#define TG_DSMEM (4*STAGE_F*4)

__global__ __launch_bounds__(256) void tgemm(
    const float* __restrict__ A, const float* __restrict__ B1,
    const float* __restrict__ B2, int msplit,
    float* __restrict__ C, int N, int K, int ldc,
    long long sA, long long sB,
    int rsplit, int zdiv, long long sCt, long long sCi, long long sCh, long long cbase,
    float alpha, const float* __restrict__ alphas, int adiv, int arsplit, int rnd)
{
  extern __shared__ float smem[];
  float* As = smem;
  float* Bs = smem + 2*STAGE_F;

  const int tid = threadIdx.x;
  const int z   = blockIdx.z;
  const long long bm = (long long)blockIdx.y * 128;
  const long long bn = (long long)blockIdx.x * 128;

  const float* Ab = A + z*sA + bm*K;
  const float* Bsel = (bm < msplit) ? B1 : B2;
  const float* Bb = Bsel + z*sB + bn*K;

  float alp = ((int)bm < arsplit) ? alpha : alphas[z/adiv];
  long long zoff = ((int)bm < rsplit)
      ? (long long)(z/zdiv)*sCt + (long long)(z%zdiv)*sCh
      : cbase + (long long)(z/zdiv)*sCi + (long long)(z%zdiv)*sCh;

  const int lw  = tid & 31;
  const int w   = tid >> 5;
  const int wr  = (w >> 2) * 64;
  const int wc  = (w & 3) * 32;
  const int g   = lw >> 2;
  const int tg  = lw & 3;

  const int lrow = tid >> 1;
  const int lcol = (tid & 1) * 16;

  float acc[4][4][4];
  #pragma unroll
  for (int i=0;i<4;i++)
    #pragma unroll
    for (int j=0;j<4;j++)
      #pragma unroll
      for (int q=0;q<4;q++) acc[i][j][q] = 0.f;

  const int nch = K >> 5;

  auto load_chunk = [&](int c, int st){
    const float* Ag = Ab + (long long)lrow*K + c*32 + lcol;
    const float* Bg = Bb + (long long)lrow*K + c*32 + lcol;
    uint32_t da = sptr(As + st*STAGE_F + lrow*TSTRIDE + lcol);
    uint32_t db = sptr(Bs + st*STAGE_F + lrow*TSTRIDE + lcol);
    #pragma unroll
    for (int j = 0; j < 4; j++){
      asm volatile("cp.async.cg.shared.global [%0], [%1], 16;" :: "r"(da + j*16), "l"(Ag + j*4));
      asm volatile("cp.async.cg.shared.global [%0], [%1], 16;" :: "r"(db + j*16), "l"(Bg + j*4));
    }
    asm volatile("cp.async.commit_group;");
  };

  load_chunk(0, 0);

  for (int i = 0; i < nch; i++){
    int st = i & 1;
    if (i + 1 < nch){
      load_chunk(i+1, st^1);
      asm volatile("cp.async.wait_group 1;" ::: "memory");
    } else {
      asm volatile("cp.async.wait_group 0;" ::: "memory");
    }
    __syncthreads();

    const uint32_t* Ast = (const uint32_t*)(As + st*STAGE_F);
    const uint32_t* Bst = (const uint32_t*)(Bs + st*STAGE_F);

    #pragma unroll
    for (int ks = 0; ks < 4; ks++){
      int kb = ks*8;
      uint32_t af[4][4];
      #pragma unroll
      for (int mt = 0; mt < 4; mt++){
        const uint32_t* ap = Ast + (wr + mt*16 + g)*TSTRIDE + kb + tg;
        af[mt][0] = ap[0];
        af[mt][1] = ap[8*TSTRIDE];
        af[mt][2] = ap[4];
        af[mt][3] = ap[8*TSTRIDE + 4];
      }
      uint32_t bf[4][2];
      #pragma unroll
      for (int nt = 0; nt < 4; nt++){
        const uint32_t* bp = Bst + (wc + nt*8 + g)*TSTRIDE + kb + tg;
        bf[nt][0] = bp[0];
        bf[nt][1] = bp[4];
      }
      #pragma unroll
      for (int mt = 0; mt < 4; mt++)
        #pragma unroll
        for (int nt = 0; nt < 4; nt++){
          asm volatile(
            "mma.sync.aligned.m16n8k8.row.col.f32.tf32.tf32.f32 "
            "{%0,%1,%2,%3}, {%4,%5,%6,%7}, {%8,%9}, {%0,%1,%2,%3};"
            : "+f"(acc[mt][nt][0]), "+f"(acc[mt][nt][1]),
              "+f"(acc[mt][nt][2]), "+f"(acc[mt][nt][3])
            : "r"(af[mt][0]), "r"(af[mt][1]), "r"(af[mt][2]), "r"(af[mt][3]),
              "r"(bf[nt][0]), "r"(bf[nt][1]));
        }
    }
    __syncthreads();
  }

  float* Cb = C + zoff;
  #pragma unroll
  for (int mt = 0; mt < 4; mt++){
    long long r0 = bm + wr + mt*16 + g;
    #pragma unroll
    for (int nt = 0; nt < 4; nt++){
      long long c0 = bn + wc + nt*8 + 2*tg;
      float2 v0 = make_float2(acc[mt][nt][0]*alp, acc[mt][nt][1]*alp);
      float2 v1 = make_float2(acc[mt][nt][2]*alp, acc[mt][nt][3]*alp);
      if (rnd){
        v0.x = RND(v0.x); v0.y = RND(v0.y);
        v1.x = RND(v1.x); v1.y = RND(v1.y);
      }
      *(float2*)(Cb + r0*ldc + c0)     = v0;
      *(float2*)(Cb + (r0+8)*ldc + c0) = v1;
    }
  }
}

// ---------------- round 8 weight matrices to tf32 grid ----------------
__global__ void k_round8(const float* __restrict__ i0, float* __restrict__ o0,
                         const float* __restrict__ i1, float* __restrict__ o1,
                         const float* __restrict__ i2, float* __restrict__ o2,
                         const float* __restrict__ i3, float* __restrict__ o3,
                         const float* __restrict__ i4, float* __restrict__ o4,
                         const float* __restrict__ i5, float* __restrict__ o5,
                         const float* __restrict__ i6, float* __restrict__ o6,
                         const float* __restrict__ i7, float* __restrict__ o7)
{
  // sizes/4: qkv 196608 x2, out 65536 x2, fc1 262144 x2, fc2 262144 x2
  int idx = blockIdx.x*blockDim.x + threadIdx.x;   // float4 index, total 1572864
  const float4* in; float4* out; int off;
  if      (idx <  196608){ in=(const float4*)i0; out=(float4*)o0; off=0; }
  else if (idx <  393216){ in=(const float4*)i1; out=(float4*)o1; off=196608; }
  else if (idx <  458752){ in=(const float4*)i2; out=(float4*)o2; off=393216; }
  else if (idx <  524288){ in=(const float4*)i3; out=(float4*)o3; off=458752; }
  else if (idx <  786432){ in=(const float4*)i4; out=(float4*)o4; off=524288; }
  else if (idx < 1048576){ in=(const float4*)i5; out=(float4*)o5; off=786432; }
  else if (idx < 1310720){ in=(const float4*)i6; out=(float4*)o6; off=1048576; }
  else                   { in=(const float4*)i7; out=(float4*)o7; off=1310720; }
  int j = idx - off;
  out[j] = RND4(in[j]);
}

// ---------------- adaln embedding ----------------
__global__ void k_emb(const float* __restrict__ vec, const float* __restrict__ W,
                      const float* __restrict__ bias, float* __restrict__ e)
{
  int b = blockIdx.y;
  __shared__ float s[DM];
  for (int i = threadIdx.x; i < DM; i += blockDim.x){
    float v = vec[b*DM + i];
    s[i] = v / (1.f + expf(-v));
  }
  __syncthreads();
  int n = blockIdx.x*blockDim.x + threadIdx.x;
  const float* wr = W + (long long)n*DM;
  float acc = 0.f;
  #pragma unroll 8
  for (int k = 0; k < DM; k++) acc += s[k]*wr[k];
  e[b*E6 + n] = acc + bias[n];
}

__global__ void k_eff(const float* __restrict__ t, float* __restrict__ eff){
  int b = threadIdx.x;
  if (b < NB){
    float m = 0.25f*(t[b*NHD+0]+t[b*NHD+1]+t[b*NHD+2]+t[b*NHD+3]);
    eff[b] = SCALE_C / fmaxf(m, 0.1f);
  }
}

__global__ void k_mod(const float* __restrict__ sp, const float* __restrict__ mw,
                      const float* __restrict__ mb, float* __restrict__ mod)
{
  int idx = blockIdx.x*blockDim.x + threadIdx.x;
  if (idx >= NB*NHD*NI) return;
  int n = idx & (NI-1);
  int h = (idx >> 11) & (NHD-1);
  int b = idx >> 13;
  int y = n >> 5;
  int x = n & 31;
  float fy = (y + 0.5f)*0.125f - 0.5f;
  float fx = (x + 0.5f)*0.25f  - 0.5f;
  int y0 = (int)floorf(fy); float wy = fy - (float)y0;
  int x0 = (int)floorf(fx); float wx = fx - (float)x0;
  int y0c = min(max(y0,0),7), y1c = min(max(y0+1,0),7);
  int x0c = min(max(x0,0),7), x1c = min(max(x0+1,0),7);
  const float* p = sp + b*64;
  float v = (1.f-wy)*((1.f-wx)*p[y0c*8+x0c] + wx*p[y0c*8+x1c])
          +      wy *((1.f-wx)*p[y1c*8+x0c] + wx*p[y1c*8+x1c]);
  v = v*mw[h] + mb[h];
  v = fminf(fmaxf(v, -2.f), 2.f);
  mod[idx] = expf(v);
}

// ---------------- combined rms-norm + adaln modulate (rounded output) ----------------
__global__ __launch_bounds__(128) void k_rmsmod(
    const float* __restrict__ xt, const float* __restrict__ xi,
    const float* __restrict__ wt, const float* __restrict__ wi,
    const float* __restrict__ et, const float* __restrict__ ei,
    int shift_off, int scale_off, float* __restrict__ out)
{
  int row = blockIdx.x;
  const float* x; const float* w; const float* eb;
  if (row < MT){
    x = xt + (long long)row*DM; w = wt; eb = et + (row/LT)*E6;
  } else {
    int rr = row - MT;
    x = xi + (long long)rr*DM; w = wi; eb = ei + (rr/NI)*E6;
  }
  float4 xv = ((const float4*)x)[threadIdx.x];
  float ss = xv.x*xv.x + xv.y*xv.y + xv.z*xv.z + xv.w*xv.w;
  ss = warpSum(ss);
  __shared__ float red[4];
  int lane = threadIdx.x & 31, wid = threadIdx.x >> 5;
  if (lane==0) red[wid]=ss;
  __syncthreads();
  float tot = red[0]+red[1]+red[2]+red[3];
  float inv = rsqrtf(tot*(1.f/DM) + 1e-6f);
  int c = threadIdx.x*4;
  float4 o;
  o.x = RND(xv.x*inv*w[c+0]*(1.f+eb[scale_off+c+0]) + eb[shift_off+c+0]);
  o.y = RND(xv.y*inv*w[c+1]*(1.f+eb[scale_off+c+1]) + eb[shift_off+c+1]);
  o.z = RND(xv.z*inv*w[c+2]*(1.f+eb[scale_off+c+2]) + eb[shift_off+c+2]);
  o.w = RND(xv.w*inv*w[c+3]*(1.f+eb[scale_off+c+3]) + eb[shift_off+c+3]);
  ((float4*)(out + (long long)row*DM))[threadIdx.x] = o;
}

// ---------------- scatter img qkv (rounded Q/K/VT) ----------------
__global__ void k_scatter_img(const float* __restrict__ qkv, const float* __restrict__ rope,
                              const float* __restrict__ mod,
                              float* __restrict__ Q, float* __restrict__ K,
                              float* __restrict__ VT)
{
  int idx = blockIdx.x*blockDim.x + threadIdx.x;
  int d2 = idx & 63;
  int r  = idx >> 6;
  int n  = r & (NI-1);
  int bh = r >> 11;
  int h  = bh & (NHD-1);
  int b  = bh >> 2;
  const float* base = qkv + ((long long)(MT + b*NI + n))*(3*NHD*HDD) + h*HDD + 2*d2;
  float2 q = *(const float2*)(base);
  float2 k = *(const float2*)(base + NHD*HDD);
  float2 v = *(const float2*)(base + 2*NHD*HDD);
  float c = rope[n*HDD + 2*d2];
  float s = rope[n*HDD + 2*d2 + 1];
  float m = mod[r];
  float q0 = RND((q.x*c - q.y*s)*m), q1 = RND((q.y*c + q.x*s)*m);
  float k0 = RND((k.x*c - k.y*s)*m), k1 = RND((k.y*c + k.x*s)*m);
  long long kv = (long long)bh*KVL + (LT + n);
  *(float2*)(Q + kv*HDD + 2*d2) = make_float2(q0,q1);
  *(float2*)(K + kv*HDD + 2*d2) = make_float2(k0,k1);
  VT[((long long)bh*HDD + 2*d2  )*KVL + (LT+n)] = RND(v.x);
  VT[((long long)bh*HDD + 2*d2+1)*KVL + (LT+n)] = RND(v.y);
}

// ---------------- scatter txt qkv (rounded) ----------------
__global__ void k_scatter_txt(const float* __restrict__ qkv,
                              float* __restrict__ Q, float* __restrict__ K,
                              float* __restrict__ VT)
{
  int idx = blockIdx.x*blockDim.x + threadIdx.x;
  int d2 = idx & 63;
  int r  = idx >> 6;
  int l  = r & (LT-1);
  int bh = r >> 9;
  int h  = bh & (NHD-1);
  int b  = bh >> 2;
  const float* base = qkv + ((long long)(b*LT + l))*(3*NHD*HDD) + h*HDD + 2*d2;
  float2 q = *(const float2*)(base);
  float2 k = *(const float2*)(base + NHD*HDD);
  float2 v = *(const float2*)(base + 2*NHD*HDD);
  long long kv = (long long)bh*KVL + l;
  *(float2*)(Q + kv*HDD + 2*d2) = make_float2(RND(q.x), RND(q.y));
  *(float2*)(K + kv*HDD + 2*d2) = make_float2(RND(k.x), RND(k.y));
  VT[((long long)bh*HDD + 2*d2  )*KVL + l] = RND(v.x);
  VT[((long long)bh*HDD + 2*d2+1)*KVL + l] = RND(v.y);
}

// ---------------- softmax (rounded output) ----------------
__global__ __launch_bounds__(256) void k_softmax(float* __restrict__ S){
  long long row = blockIdx.x;
  float* p = S + row*KVL;
  int tid = threadIdx.x;
  float v[10];
  float m = -1e30f;
  #pragma unroll
  for (int i=0;i<10;i++){ v[i] = p[tid + i*256]; m = fmaxf(m, v[i]); }
  m = warpMax(m);
  __shared__ float redm[8];
  __shared__ float reds[8];
  int lane = tid & 31, wid = tid >> 5;
  if (lane==0) redm[wid]=m;
  __syncthreads();
  float bm = redm[0];
  #pragma unroll
  for (int i=1;i<8;i++) bm = fmaxf(bm, redm[i]);
  float sum = 0.f;
  #pragma unroll
  for (int i=0;i<10;i++){ v[i] = __expf(v[i]-bm); sum += v[i]; }
  sum = warpSum(sum);
  if (lane==0) reds[wid]=sum;
  __syncthreads();
  float tot = reds[0]+reds[1]+reds[2]+reds[3]+reds[4]+reds[5]+reds[6]+reds[7];
  float inv = 1.f/tot;
  #pragma unroll
  for (int i=0;i<10;i++) p[tid + i*256] = RND(v[i]*inv);
}

// ---------------- combined resgate ----------------
__global__ void k_resgate(const float* __restrict__ rt, const float* __restrict__ ri,
                          const float* __restrict__ x,
                          const float* __restrict__ et, const float* __restrict__ ei,
                          int off, float* __restrict__ out)
{
  int idx = blockIdx.x*blockDim.x + threadIdx.x;
  if (idx >= MALL*DM) return;
  int d = idx & (DM-1);
  int row = idx >> 9;
  float res; const float* eb;
  if (row < MT){ res = rt[idx]; eb = et + (row/LT)*E6; }
  else { res = ri[idx - MT*DM]; eb = ei + ((row-MT)/NI)*E6; }
  out[idx] = res + eb[off + d]*x[idx];
}

// ---------------- bias + gelu (rounded output) ----------------
__global__ void k_biasgelu(float* __restrict__ h, const float* __restrict__ bt,
                           const float* __restrict__ bi){
  int idx = blockIdx.x*blockDim.x + threadIdx.x;
  if (idx >= MALL*FFD) return;
  const float* bias = (idx < MT*FFD) ? bt : bi;
  float x = h[idx] + bias[idx & (FFD-1)];
  float x3 = x*x*x;
  float t = tanhf(0.7978845608028654f*(x + 0.044715f*x3));
  h[idx] = RND(0.5f*x*(1.f+t));
}

// ---------------- final ----------------
__global__ void k_final(const float* __restrict__ cur, const float* __restrict__ x,
                        const float* __restrict__ et, const float* __restrict__ ei,
                        const float* __restrict__ bt, const float* __restrict__ bi,
                        float* __restrict__ out)
{
  int idx = blockIdx.x*blockDim.x + threadIdx.x;
  if (idx >= MALL*DM) return;
  int d = idx & (DM-1);
  int row = idx >> 9;
  const float* eb; const float* bias;
  if (row < MT){ eb = et + (row/LT)*E6; bias = bt; }
  else { eb = ei + ((row-MT)/NI)*E6; bias = bi; }
  out[idx] = cur[idx] + eb[2560 + d]*(x[idx] + bias[d]);
}

// ---------------- launch ----------------
#define GETSYM(var, sym) float* var; cudaGetSymbolAddress((void**)&var, sym)

extern "C" void kernel_launch(void* const* d_in, const int* in_sizes, int n_in,
                              void* d_out, int out_size)
{
  const float* txt          = (const float*)d_in[0];
  const float* img          = (const float*)d_in[1];
  const float* vec          = (const float*)d_in[2];
  const float* rope         = (const float*)d_in[3];
  const float* sol_t        = (const float*)d_in[4];
  const float* sol_s        = (const float*)d_in[5];
  const float* img_adaln_w  = (const float*)d_in[6];
  const float* img_adaln_b  = (const float*)d_in[7];
  const float* img_adaln_nw = (const float*)d_in[8];
  const float* txt_adaln_w  = (const float*)d_in[9];
  const float* txt_adaln_b  = (const float*)d_in[10];
  const float* txt_adaln_nw = (const float*)d_in[11];
  const float* txt_qkv_w    = (const float*)d_in[12];
  const float* img_qkv_w    = (const float*)d_in[13];
  const float* txt_out_w    = (const float*)d_in[14];
  const float* img_out_w    = (const float*)d_in[15];
  const float* sol_mod_w    = (const float*)d_in[16];
  const float* sol_mod_b    = (const float*)d_in[17];
  const float* img_norm2_w  = (const float*)d_in[18];
  const float* txt_norm2_w  = (const float*)d_in[19];
  const float* img_fc1_w    = (const float*)d_in[20];
  const float* img_fc1_b    = (const float*)d_in[21];
  const float* img_fc2_w    = (const float*)d_in[22];
  const float* img_fc2_b    = (const float*)d_in[23];
  const float* txt_fc1_w    = (const float*)d_in[24];
  const float* txt_fc1_b    = (const float*)d_in[25];
  const float* txt_fc2_w    = (const float*)d_in[26];
  const float* txt_fc2_b    = (const float*)d_in[27];
  float* out = (float*)d_out;

  GETSYM(e_img, d_e_img);  GETSYM(e_txt, d_e_txt);
  GETSYM(eff, d_eff);      GETSYM(mod, d_mod);
  GETSYM(nrm, d_nrm);      GETSYM(qkv, d_qkv);
  GETSYM(Qc, d_Qc);        GETSYM(Kc, d_Kc);
  GETSYM(VT, d_VT);        GETSYM(S, d_S);
  GETSYM(ap, d_ap);        GETSYM(pr, d_pr);
  GETSYM(cc, d_c);         GETSYM(hh, d_h);
  GETSYM(wq_t, d_wq_t);    GETSYM(wq_i, d_wq_i);
  GETSYM(wo_t, d_wo_t);    GETSYM(wo_i, d_wo_i);
  GETSYM(w1_t, d_w1_t);    GETSYM(w1_i, d_w1_i);
  GETSYM(w2_t, d_w2_t);    GETSYM(w2_i, d_w2_i);

  cudaFuncSetAttribute(tgemm, cudaFuncAttributeMaxDynamicSharedMemorySize, TG_DSMEM);

  // 0. round weights to tf32 grid (1572864 float4s)
  k_round8<<<1572864/256, 256>>>(txt_qkv_w, wq_t, img_qkv_w, wq_i,
                                 txt_out_w, wo_t, img_out_w, wo_i,
                                 txt_fc1_w, w1_t, img_fc1_w, w1_i,
                                 txt_fc2_w, w2_t, img_fc2_w, w2_i);
  // 1. adaln embeddings + eff + mod
  k_emb<<<dim3(E6/256, NB), 256>>>(vec, img_adaln_w, img_adaln_b, e_img);
  k_emb<<<dim3(E6/256, NB), 256>>>(vec, txt_adaln_w, txt_adaln_b, e_txt);
  k_eff<<<1, 32>>>(sol_t, eff);
  k_mod<<<(NB*NHD*NI)/256, 256>>>(sol_s, sol_mod_w, sol_mod_b, mod);
  // 2. norm1 combined
  k_rmsmod<<<MALL, 128>>>(txt, img, txt_adaln_nw, img_adaln_nw, e_txt, e_img, 0, 512, nrm);
  // 3. QKV combined
  tgemm<<<dim3(12, MALL/128, 1), 256, TG_DSMEM>>>(nrm, wq_t, wq_i, MT,
      qkv, 1536, DM, 1536, 0, 0,
      BIGR, 1, 0, 0, 0, 0, 1.f, eff, 1, BIGR, 0);
  // 4. scatter -> Qc, Kc, V^T
  k_scatter_txt<<<(NB*NHD*LT*64)/256, 256>>>(qkv, Qc, Kc, VT);
  k_scatter_img<<<(NB*NHD*NI*64)/256, 256>>>(qkv, rope, mod, Qc, Kc, VT);
  // 5. scores combined
  tgemm<<<dim3(KVL/128, KVL/128, NB*NHD), 256, TG_DSMEM>>>(Qc, Kc, Kc, BIGR,
      S, KVL, HDD, KVL, (long long)KVL*HDD, (long long)KVL*HDD,
      BIGR, 1, (long long)KVL*KVL, 0, 0, 0,
      SCALE_C, eff, NHD, LT, 0);
  // 6. softmax
  k_softmax<<<NB*NHD*KVL, 256>>>(S);
  // 7. P @ V -> packed, rounded (feeds proj GEMM)
  tgemm<<<dim3(1, KVL/128, NB*NHD), 256, TG_DSMEM>>>(S, VT, VT, BIGR,
      ap, HDD, KVL, DM, (long long)KVL*KVL, (long long)HDD*KVL,
      LT, NHD, (long long)LT*DM, (long long)NI*DM, HDD,
      (long long)MT*DM - (long long)LT*DM,
      1.f, eff, 1, BIGR, 1);
  // 8. output projection combined
  tgemm<<<dim3(4, MALL/128, 1), 256, TG_DSMEM>>>(ap, wo_t, wo_i, MT,
      pr, DM, DM, DM, 0, 0,
      BIGR, 1, 0, 0, 0, 0, 1.f, eff, 1, BIGR, 0);
  // 9. attention residual
  k_resgate<<<(MALL*DM)/256, 256>>>(txt, img, pr, e_txt, e_img, 1024, cc);
  // 10. norm2 combined
  k_rmsmod<<<MALL, 128>>>(cc, cc + (long long)MT*DM, txt_norm2_w, img_norm2_w,
                          e_txt, e_img, 1536, 2048, nrm);
  // 11. fc1 combined
  tgemm<<<dim3(16, MALL/128, 1), 256, TG_DSMEM>>>(nrm, w1_t, w1_i, MT,
      hh, FFD, DM, FFD, 0, 0,
      BIGR, 1, 0, 0, 0, 0, 1.f, eff, 1, BIGR, 0);
  // 12. bias + gelu (rounded)
  k_biasgelu<<<(MALL*FFD)/256, 256>>>(hh, txt_fc1_b, img_fc1_b);
  // 13. fc2 combined
  tgemm<<<dim3(4, MALL/128, 1), 256, TG_DSMEM>>>(hh, w2_t, w2_i, MT,
      pr, DM, FFD, DM, 0, 0,
      BIGR, 1, 0, 0, 0, 0, 1.f, eff, 1, BIGR, 0);
  // 14. final residual -> d_out
  k_final<<<(MALL*DM)/256, 256>>>(cc, pr, e_txt, e_img, txt_fc2_b, img_fc2_b, out);
}

// round 7
// speedup vs baseline: 1.9751x; 1.6126x over previous
#include <cuda_runtime.h>
#include <cuda_fp16.h>
#include <math.h>
#include <stdint.h>

// ---------------- problem dims (fixed) ----------------
#define NB   2
#define LT   512
#define NI   2048
#define DM   512
#define NHD  4
#define HDD  128
#define FFD  2048
#define KVL  2560
#define E6   3072
#define MT   (NB*LT)
#define MI   (NB*NI)
#define MALL (MT+MI)
#define SCALE_C 0.08838834764831845f
#define BIGR (1<<30)

// ---------------- scratch ----------------
__device__ __align__(256) float  d_e_img[NB*E6];
__device__ __align__(256) float  d_e_txt[NB*E6];
__device__ __align__(256) float  d_eff[NB];
__device__ __align__(256) float  d_mod[NB*NHD*NI];
__device__ __align__(256) __half d_nrm[MALL*DM];
__device__ __align__(256) __half d_qkv[MALL*3*NHD*HDD];
__device__ __align__(256) __half d_Qc[NB*NHD*KVL*HDD];
__device__ __align__(256) __half d_Kc[NB*NHD*KVL*HDD];
__device__ __align__(256) __half d_VT[NB*NHD*HDD*KVL];
__device__ __align__(256) __half d_S[NB*NHD*KVL*KVL];
__device__ __align__(256) __half d_ap[MALL*DM];
__device__ __align__(256) __half d_h[MALL*FFD];
__device__ __align__(256) float  d_pr[MALL*DM];
__device__ __align__(256) float  d_c[MALL*DM];
// half weights
__device__ __align__(256) __half d_wq_t[1536*DM];
__device__ __align__(256) __half d_wq_i[1536*DM];
__device__ __align__(256) __half d_wo_t[DM*DM];
__device__ __align__(256) __half d_wo_i[DM*DM];
__device__ __align__(256) __half d_w1_t[FFD*DM];
__device__ __align__(256) __half d_w1_i[FFD*DM];
__device__ __align__(256) __half d_w2_t[DM*FFD];
__device__ __align__(256) __half d_w2_i[DM*FFD];

// ---------------- helpers ----------------
__device__ __forceinline__ float warpSum(float v){
  #pragma unroll
  for (int o=16;o>0;o>>=1) v += __shfl_xor_sync(0xffffffffu, v, o);
  return v;
}
__device__ __forceinline__ float warpMax(float v){
  #pragma unroll
  for (int o=16;o>0;o>>=1) v = fmaxf(v, __shfl_xor_sync(0xffffffffu, v, o));
  return v;
}
__device__ __forceinline__ uint32_t sptr(const void* p){
  uint32_t r;
  asm("{ .reg .u64 t; cvta.to.shared.u64 t, %1; cvt.u32.u64 %0, t; }" : "=r"(r) : "l"(p));
  return r;
}

// ================= fp16 mma.sync batched GEMM: C = alpha * A(MxK) @ Bsel(NxK)^T =================
// CTA 128x128, 8 warps (2x4), warp tile 64x32, K-chunk 32 halves, double-buffered cp.async.
// Fragments via vectorized 32-bit LDS, conflict-free stride 40 halves.
#define TSH 40                    // halves per smem row
#define STAGE_H (128*TSH)         // halves per matrix per stage
#define TG_DSMEM (4*STAGE_H*2)    // 2 stages x (A+B) x 2B = 40960

__global__ __launch_bounds__(256) void tgemm(
    const __half* __restrict__ A, const __half* __restrict__ B1,
    const __half* __restrict__ B2, int msplit,
    void* __restrict__ C, int N, int K, int ldc,
    long long sA, long long sB,
    int rsplit, int zdiv, long long sCt, long long sCi, long long sCh, long long cbase,
    float alpha, const float* __restrict__ alphas, int adiv, int arsplit, int outHalf)
{
  extern __shared__ __half smh[];
  __half* As = smh;
  __half* Bs = smh + 2*STAGE_H;

  const int tid = threadIdx.x;
  const int z   = blockIdx.z;
  const long long bm = (long long)blockIdx.y * 128;
  const long long bn = (long long)blockIdx.x * 128;

  const __half* Ab = A + z*sA + bm*K;
  const __half* Bsel = (bm < msplit) ? B1 : B2;
  const __half* Bb = Bsel + z*sB + bn*K;

  float alp = ((int)bm < arsplit) ? alpha : alphas[z/adiv];
  long long zoff = ((int)bm < rsplit)
      ? (long long)(z/zdiv)*sCt + (long long)(z%zdiv)*sCh
      : cbase + (long long)(z/zdiv)*sCi + (long long)(z%zdiv)*sCh;

  const int lw  = tid & 31;
  const int w   = tid >> 5;
  const int wr  = (w >> 2) * 64;
  const int wc  = (w & 3) * 32;
  const int g   = lw >> 2;
  const int tg  = lw & 3;

  const int lrow = tid >> 1;
  const int lsel = (tid & 1) * 16;    // halves offset within 32-half chunk row

  float acc[4][4][4];
  #pragma unroll
  for (int i=0;i<4;i++)
    #pragma unroll
    for (int j=0;j<4;j++)
      #pragma unroll
      for (int q=0;q<4;q++) acc[i][j][q] = 0.f;

  const int nch = K >> 5;

  auto load_chunk = [&](int c, int st){
    const __half* Ag = Ab + (long long)lrow*K + c*32 + lsel;
    const __half* Bg = Bb + (long long)lrow*K + c*32 + lsel;
    uint32_t da = sptr(As + st*STAGE_H + lrow*TSH + lsel);
    uint32_t db = sptr(Bs + st*STAGE_H + lrow*TSH + lsel);
    asm volatile("cp.async.cg.shared.global [%0], [%1], 16;" :: "r"(da),      "l"(Ag));
    asm volatile("cp.async.cg.shared.global [%0], [%1], 16;" :: "r"(da + 16), "l"(Ag + 8));
    asm volatile("cp.async.cg.shared.global [%0], [%1], 16;" :: "r"(db),      "l"(Bg));
    asm volatile("cp.async.cg.shared.global [%0], [%1], 16;" :: "r"(db + 16), "l"(Bg + 8));
    asm volatile("cp.async.commit_group;");
  };

  load_chunk(0, 0);

  for (int i = 0; i < nch; i++){
    int st = i & 1;
    if (i + 1 < nch){
      load_chunk(i+1, st^1);
      asm volatile("cp.async.wait_group 1;" ::: "memory");
    } else {
      asm volatile("cp.async.wait_group 0;" ::: "memory");
    }
    __syncthreads();

    const uint32_t* A32 = (const uint32_t*)(As + st*STAGE_H);
    const uint32_t* B32 = (const uint32_t*)(Bs + st*STAGE_H);
    // b32 row stride = TSH/2 = 20

    #pragma unroll
    for (int ks = 0; ks < 2; ks++){
      int ko = ks*8;   // b32 offset per k16 step
      uint32_t af[4][4];
      #pragma unroll
      for (int mt = 0; mt < 4; mt++){
        int base = (wr + mt*16 + g)*20 + ko + tg;
        af[mt][0] = A32[base];
        af[mt][1] = A32[base + 8*20];
        af[mt][2] = A32[base + 4];
        af[mt][3] = A32[base + 8*20 + 4];
      }
      uint32_t bf[4][2];
      #pragma unroll
      for (int nt = 0; nt < 4; nt++){
        int base = (wc + nt*8 + g)*20 + ko + tg;
        bf[nt][0] = B32[base];
        bf[nt][1] = B32[base + 4];
      }
      #pragma unroll
      for (int mt = 0; mt < 4; mt++)
        #pragma unroll
        for (int nt = 0; nt < 4; nt++){
          asm volatile(
            "mma.sync.aligned.m16n8k16.row.col.f32.f16.f16.f32 "
            "{%0,%1,%2,%3}, {%4,%5,%6,%7}, {%8,%9}, {%0,%1,%2,%3};"
            : "+f"(acc[mt][nt][0]), "+f"(acc[mt][nt][1]),
              "+f"(acc[mt][nt][2]), "+f"(acc[mt][nt][3])
            : "r"(af[mt][0]), "r"(af[mt][1]), "r"(af[mt][2]), "r"(af[mt][3]),
              "r"(bf[nt][0]), "r"(bf[nt][1]));
        }
    }
    __syncthreads();
  }

  // epilogue
  if (outHalf){
    __half* Cb = (__half*)C + zoff;
    #pragma unroll
    for (int mt = 0; mt < 4; mt++){
      long long r0 = bm + wr + mt*16 + g;
      #pragma unroll
      for (int nt = 0; nt < 4; nt++){
        long long c0 = bn + wc + nt*8 + 2*tg;
        *(__half2*)(Cb + r0*ldc + c0)     = __floats2half2_rn(acc[mt][nt][0]*alp, acc[mt][nt][1]*alp);
        *(__half2*)(Cb + (r0+8)*ldc + c0) = __floats2half2_rn(acc[mt][nt][2]*alp, acc[mt][nt][3]*alp);
      }
    }
  } else {
    float* Cb = (float*)C + zoff;
    #pragma unroll
    for (int mt = 0; mt < 4; mt++){
      long long r0 = bm + wr + mt*16 + g;
      #pragma unroll
      for (int nt = 0; nt < 4; nt++){
        long long c0 = bn + wc + nt*8 + 2*tg;
        *(float2*)(Cb + r0*ldc + c0)     = make_float2(acc[mt][nt][0]*alp, acc[mt][nt][1]*alp);
        *(float2*)(Cb + (r0+8)*ldc + c0) = make_float2(acc[mt][nt][2]*alp, acc[mt][nt][3]*alp);
      }
    }
  }
}

// ---------------- convert 8 weight matrices float -> half ----------------
__global__ void k_half8(const float* __restrict__ i0, __half* __restrict__ o0,
                        const float* __restrict__ i1, __half* __restrict__ o1,
                        const float* __restrict__ i2, __half* __restrict__ o2,
                        const float* __restrict__ i3, __half* __restrict__ o3,
                        const float* __restrict__ i4, __half* __restrict__ o4,
                        const float* __restrict__ i5, __half* __restrict__ o5,
                        const float* __restrict__ i6, __half* __restrict__ o6,
                        const float* __restrict__ i7, __half* __restrict__ o7)
{
  int idx = blockIdx.x*blockDim.x + threadIdx.x;   // float4 index, total 1572864
  const float4* in; __half2* out; int off;
  if      (idx <  196608){ in=(const float4*)i0; out=(__half2*)o0; off=0; }
  else if (idx <  393216){ in=(const float4*)i1; out=(__half2*)o1; off=196608; }
  else if (idx <  458752){ in=(const float4*)i2; out=(__half2*)o2; off=393216; }
  else if (idx <  524288){ in=(const float4*)i3; out=(__half2*)o3; off=458752; }
  else if (idx <  786432){ in=(const float4*)i4; out=(__half2*)o4; off=524288; }
  else if (idx < 1048576){ in=(const float4*)i5; out=(__half2*)o5; off=786432; }
  else if (idx < 1310720){ in=(const float4*)i6; out=(__half2*)o6; off=1048576; }
  else                   { in=(const float4*)i7; out=(__half2*)o7; off=1310720; }
  int j = idx - off;
  float4 v = in[j];
  out[j*2]   = __floats2half2_rn(v.x, v.y);
  out[j*2+1] = __floats2half2_rn(v.z, v.w);
}

// ---------------- adaln embedding ----------------
__global__ void k_emb(const float* __restrict__ vec, const float* __restrict__ W,
                      const float* __restrict__ bias, float* __restrict__ e)
{
  int b = blockIdx.y;
  __shared__ float s[DM];
  for (int i = threadIdx.x; i < DM; i += blockDim.x){
    float v = vec[b*DM + i];
    s[i] = v / (1.f + expf(-v));
  }
  __syncthreads();
  int n = blockIdx.x*blockDim.x + threadIdx.x;
  const float* wr = W + (long long)n*DM;
  float acc = 0.f;
  #pragma unroll 8
  for (int k = 0; k < DM; k++) acc += s[k]*wr[k];
  e[b*E6 + n] = acc + bias[n];
}

__global__ void k_eff(const float* __restrict__ t, float* __restrict__ eff){
  int b = threadIdx.x;
  if (b < NB){
    float m = 0.25f*(t[b*NHD+0]+t[b*NHD+1]+t[b*NHD+2]+t[b*NHD+3]);
    eff[b] = SCALE_C / fmaxf(m, 0.1f);
  }
}

__global__ void k_mod(const float* __restrict__ sp, const float* __restrict__ mw,
                      const float* __restrict__ mb, float* __restrict__ mod)
{
  int idx = blockIdx.x*blockDim.x + threadIdx.x;
  if (idx >= NB*NHD*NI) return;
  int n = idx & (NI-1);
  int h = (idx >> 11) & (NHD-1);
  int b = idx >> 13;
  int y = n >> 5;
  int x = n & 31;
  float fy = (y + 0.5f)*0.125f - 0.5f;
  float fx = (x + 0.5f)*0.25f  - 0.5f;
  int y0 = (int)floorf(fy); float wy = fy - (float)y0;
  int x0 = (int)floorf(fx); float wx = fx - (float)x0;
  int y0c = min(max(y0,0),7), y1c = min(max(y0+1,0),7);
  int x0c = min(max(x0,0),7), x1c = min(max(x0+1,0),7);
  const float* p = sp + b*64;
  float v = (1.f-wy)*((1.f-wx)*p[y0c*8+x0c] + wx*p[y0c*8+x1c])
          +      wy *((1.f-wx)*p[y1c*8+x0c] + wx*p[y1c*8+x1c]);
  v = v*mw[h] + mb[h];
  v = fminf(fmaxf(v, -2.f), 2.f);
  mod[idx] = expf(v);
}

// ---------------- combined rms-norm + adaln modulate -> half ----------------
__global__ __launch_bounds__(128) void k_rmsmod(
    const float* __restrict__ xt, const float* __restrict__ xi,
    const float* __restrict__ wt, const float* __restrict__ wi,
    const float* __restrict__ et, const float* __restrict__ ei,
    int shift_off, int scale_off, __half* __restrict__ out)
{
  int row = blockIdx.x;
  const float* x; const float* w; const float* eb;
  if (row < MT){
    x = xt + (long long)row*DM; w = wt; eb = et + (row/LT)*E6;
  } else {
    int rr = row - MT;
    x = xi + (long long)rr*DM; w = wi; eb = ei + (rr/NI)*E6;
  }
  float4 xv = ((const float4*)x)[threadIdx.x];
  float ss = xv.x*xv.x + xv.y*xv.y + xv.z*xv.z + xv.w*xv.w;
  ss = warpSum(ss);
  __shared__ float red[4];
  int lane = threadIdx.x & 31, wid = threadIdx.x >> 5;
  if (lane==0) red[wid]=ss;
  __syncthreads();
  float tot = red[0]+red[1]+red[2]+red[3];
  float inv = rsqrtf(tot*(1.f/DM) + 1e-6f);
  int c = threadIdx.x*4;
  float ox = xv.x*inv*w[c+0]*(1.f+eb[scale_off+c+0]) + eb[shift_off+c+0];
  float oy = xv.y*inv*w[c+1]*(1.f+eb[scale_off+c+1]) + eb[shift_off+c+1];
  float oz = xv.z*inv*w[c+2]*(1.f+eb[scale_off+c+2]) + eb[shift_off+c+2];
  float ow = xv.w*inv*w[c+3]*(1.f+eb[scale_off+c+3]) + eb[shift_off+c+3];
  __half2* op = (__half2*)(out + (long long)row*DM);
  op[threadIdx.x*2]   = __floats2half2_rn(ox, oy);
  op[threadIdx.x*2+1] = __floats2half2_rn(oz, ow);
}

// ---------------- scatter img qkv (half) ----------------
__global__ void k_scatter_img(const __half* __restrict__ qkv, const float* __restrict__ rope,
                              const float* __restrict__ mod,
                              __half* __restrict__ Q, __half* __restrict__ K,
                              __half* __restrict__ VT)
{
  int idx = blockIdx.x*blockDim.x + threadIdx.x;
  int d2 = idx & 63;
  int r  = idx >> 6;
  int n  = r & (NI-1);
  int bh = r >> 11;
  int h  = bh & (NHD-1);
  int b  = bh >> 2;
  const __half* base = qkv + ((long long)(MT + b*NI + n))*(3*NHD*HDD) + h*HDD + 2*d2;
  float2 q = __half22float2(*(const __half2*)(base));
  float2 k = __half22float2(*(const __half2*)(base + NHD*HDD));
  float2 v = __half22float2(*(const __half2*)(base + 2*NHD*HDD));
  float c = rope[n*HDD + 2*d2];
  float s = rope[n*HDD + 2*d2 + 1];
  float m = mod[r];
  long long kv = (long long)bh*KVL + (LT + n);
  *(__half2*)(Q + kv*HDD + 2*d2) = __floats2half2_rn((q.x*c - q.y*s)*m, (q.y*c + q.x*s)*m);
  *(__half2*)(K + kv*HDD + 2*d2) = __floats2half2_rn((k.x*c - k.y*s)*m, (k.y*c + k.x*s)*m);
  VT[((long long)bh*HDD + 2*d2  )*KVL + (LT+n)] = __float2half_rn(v.x);
  VT[((long long)bh*HDD + 2*d2+1)*KVL + (LT+n)] = __float2half_rn(v.y);
}

// ---------------- scatter txt qkv (half) ----------------
__global__ void k_scatter_txt(const __half* __restrict__ qkv,
                              __half* __restrict__ Q, __half* __restrict__ K,
                              __half* __restrict__ VT)
{
  int idx = blockIdx.x*blockDim.x + threadIdx.x;
  int d2 = idx & 63;
  int r  = idx >> 6;
  int l  = r & (LT-1);
  int bh = r >> 9;
  int h  = bh & (NHD-1);
  int b  = bh >> 2;
  const __half* base = qkv + ((long long)(b*LT + l))*(3*NHD*HDD) + h*HDD + 2*d2;
  __half2 q = *(const __half2*)(base);
  __half2 k = *(const __half2*)(base + NHD*HDD);
  float2 v = __half22float2(*(const __half2*)(base + 2*NHD*HDD));
  long long kv = (long long)bh*KVL + l;
  *(__half2*)(Q + kv*HDD + 2*d2) = q;
  *(__half2*)(K + kv*HDD + 2*d2) = k;
  VT[((long long)bh*HDD + 2*d2  )*KVL + l] = __float2half_rn(v.x);
  VT[((long long)bh*HDD + 2*d2+1)*KVL + l] = __float2half_rn(v.y);
}

// ---------------- softmax over half rows of length KVL ----------------
__global__ __launch_bounds__(256) void k_softmax(__half* __restrict__ S){
  long long row = blockIdx.x;
  __half* p = S + row*KVL;
  int tid = threadIdx.x;
  float v[10];
  float m = -1e30f;
  #pragma unroll
  for (int i=0;i<10;i++){ v[i] = __half2float(p[tid + i*256]); m = fmaxf(m, v[i]); }
  m = warpMax(m);
  __shared__ float redm[8];
  __shared__ float reds[8];
  int lane = tid & 31, wid = tid >> 5;
  if (lane==0) redm[wid]=m;
  __syncthreads();
  float bm = redm[0];
  #pragma unroll
  for (int i=1;i<8;i++) bm = fmaxf(bm, redm[i]);
  float sum = 0.f;
  #pragma unroll
  for (int i=0;i<10;i++){ v[i] = __expf(v[i]-bm); sum += v[i]; }
  sum = warpSum(sum);
  if (lane==0) reds[wid]=sum;
  __syncthreads();
  float tot = reds[0]+reds[1]+reds[2]+reds[3]+reds[4]+reds[5]+reds[6]+reds[7];
  float inv = 1.f/tot;
  #pragma unroll
  for (int i=0;i<10;i++) p[tid + i*256] = __float2half_rn(v[i]*inv);
}

// ---------------- combined resgate (float) ----------------
__global__ void k_resgate(const float* __restrict__ rt, const float* __restrict__ ri,
                          const float* __restrict__ x,
                          const float* __restrict__ et, const float* __restrict__ ei,
                          int off, float* __restrict__ out)
{
  int idx = blockIdx.x*blockDim.x + threadIdx.x;
  if (idx >= MALL*DM) return;
  int d = idx & (DM-1);
  int row = idx >> 9;
  float res; const float* eb;
  if (row < MT){ res = rt[idx]; eb = et + (row/LT)*E6; }
  else { res = ri[idx - MT*DM]; eb = ei + ((row-MT)/NI)*E6; }
  out[idx] = res + eb[off + d]*x[idx];
}

// ---------------- bias + gelu on half ----------------
__global__ void k_biasgelu(__half* __restrict__ h, const float* __restrict__ bt,
                           const float* __restrict__ bi){
  int idx = blockIdx.x*blockDim.x + threadIdx.x;
  if (idx >= MALL*FFD) return;
  const float* bias = (idx < MT*FFD) ? bt : bi;
  float x = __half2float(h[idx]) + bias[idx & (FFD-1)];
  float x3 = x*x*x;
  float t = tanhf(0.7978845608028654f*(x + 0.044715f*x3));
  h[idx] = __float2half_rn(0.5f*x*(1.f+t));
}

// ---------------- final ----------------
__global__ void k_final(const float* __restrict__ cur, const float* __restrict__ x,
                        const float* __restrict__ et, const float* __restrict__ ei,
                        const float* __restrict__ bt, const float* __restrict__ bi,
                        float* __restrict__ out)
{
  int idx = blockIdx.x*blockDim.x + threadIdx.x;
  if (idx >= MALL*DM) return;
  int d = idx & (DM-1);
  int row = idx >> 9;
  const float* eb; const float* bias;
  if (row < MT){ eb = et + (row/LT)*E6; bias = bt; }
  else { eb = ei + ((row-MT)/NI)*E6; bias = bi; }
  out[idx] = cur[idx] + eb[2560 + d]*(x[idx] + bias[d]);
}

// ---------------- launch ----------------
#define GETSYMF(var, sym) float* var; cudaGetSymbolAddress((void**)&var, sym)
#define GETSYMH(var, sym) __half* var; cudaGetSymbolAddress((void**)&var, sym)

extern "C" void kernel_launch(void* const* d_in, const int* in_sizes, int n_in,
                              void* d_out, int out_size)
{
  const float* txt          = (const float*)d_in[0];
  const float* img          = (const float*)d_in[1];
  const float* vec          = (const float*)d_in[2];
  const float* rope         = (const float*)d_in[3];
  const float* sol_t        = (const float*)d_in[4];
  const float* sol_s        = (const float*)d_in[5];
  const float* img_adaln_w  = (const float*)d_in[6];
  const float* img_adaln_b  = (const float*)d_in[7];
  const float* img_adaln_nw = (const float*)d_in[8];
  const float* txt_adaln_w  = (const float*)d_in[9];
  const float* txt_adaln_b  = (const float*)d_in[10];
  const float* txt_adaln_nw = (const float*)d_in[11];
  const float* txt_qkv_w    = (const float*)d_in[12];
  const float* img_qkv_w    = (const float*)d_in[13];
  const float* txt_out_w    = (const float*)d_in[14];
  const float* img_out_w    = (const float*)d_in[15];
  const float* sol_mod_w    = (const float*)d_in[16];
  const float* sol_mod_b    = (const float*)d_in[17];
  const float* img_norm2_w  = (const float*)d_in[18];
  const float* txt_norm2_w  = (const float*)d_in[19];
  const float* img_fc1_w    = (const float*)d_in[20];
  const float* img_fc1_b    = (const float*)d_in[21];
  const float* img_fc2_w    = (const float*)d_in[22];
  const float* img_fc2_b    = (const float*)d_in[23];
  const float* txt_fc1_w    = (const float*)d_in[24];
  const float* txt_fc1_b    = (const float*)d_in[25];
  const float* txt_fc2_w    = (const float*)d_in[26];
  const float* txt_fc2_b    = (const float*)d_in[27];
  float* out = (float*)d_out;

  GETSYMF(e_img, d_e_img);  GETSYMF(e_txt, d_e_txt);
  GETSYMF(eff, d_eff);      GETSYMF(mod, d_mod);
  GETSYMH(nrm, d_nrm);      GETSYMH(qkv, d_qkv);
  GETSYMH(Qc, d_Qc);        GETSYMH(Kc, d_Kc);
  GETSYMH(VT, d_VT);        GETSYMH(S, d_S);
  GETSYMH(ap, d_ap);        GETSYMH(hh, d_h);
  GETSYMF(pr, d_pr);        GETSYMF(cc, d_c);
  GETSYMH(wq_t, d_wq_t);    GETSYMH(wq_i, d_wq_i);
  GETSYMH(wo_t, d_wo_t);    GETSYMH(wo_i, d_wo_i);
  GETSYMH(w1_t, d_w1_t);    GETSYMH(w1_i, d_w1_i);
  GETSYMH(w2_t, d_w2_t);    GETSYMH(w2_i, d_w2_i);

  // 0. weights -> half
  k_half8<<<1572864/256, 256>>>(txt_qkv_w, wq_t, img_qkv_w, wq_i,
                                txt_out_w, wo_t, img_out_w, wo_i,
                                txt_fc1_w, w1_t, img_fc1_w, w1_i,
                                txt_fc2_w, w2_t, img_fc2_w, w2_i);
  // 1. adaln embeddings + eff + mod
  k_emb<<<dim3(E6/256, NB), 256>>>(vec, img_adaln_w, img_adaln_b, e_img);
  k_emb<<<dim3(E6/256, NB), 256>>>(vec, txt_adaln_w, txt_adaln_b, e_txt);
  k_eff<<<1, 32>>>(sol_t, eff);
  k_mod<<<(NB*NHD*NI)/256, 256>>>(sol_s, sol_mod_w, sol_mod_b, mod);
  // 2. norm1 combined -> half
  k_rmsmod<<<MALL, 128>>>(txt, img, txt_adaln_nw, img_adaln_nw, e_txt, e_img, 0, 512, nrm);
  // 3. QKV combined -> half
  tgemm<<<dim3(12, MALL/128, 1), 256, TG_DSMEM>>>(nrm, wq_t, wq_i, MT,
      qkv, 1536, DM, 1536, 0, 0,
      BIGR, 1, 0, 0, 0, 0, 1.f, eff, 1, BIGR, 1);
  // 4. scatter -> Qc, Kc, V^T
  k_scatter_txt<<<(NB*NHD*LT*64)/256, 256>>>(qkv, Qc, Kc, VT);
  k_scatter_img<<<(NB*NHD*NI*64)/256, 256>>>(qkv, rope, mod, Qc, Kc, VT);
  // 5. scores combined -> half S
  tgemm<<<dim3(KVL/128, KVL/128, NB*NHD), 256, TG_DSMEM>>>(Qc, Kc, Kc, BIGR,
      S, KVL, HDD, KVL, (long long)KVL*HDD, (long long)KVL*HDD,
      BIGR, 1, (long long)KVL*KVL, 0, 0, 0,
      SCALE_C, eff, NHD, LT, 1);
  // 6. softmax (half)
  k_softmax<<<NB*NHD*KVL, 256>>>(S);
  // 7. P @ V -> packed half ap
  tgemm<<<dim3(1, KVL/128, NB*NHD), 256, TG_DSMEM>>>(S, VT, VT, BIGR,
      ap, HDD, KVL, DM, (long long)KVL*KVL, (long long)HDD*KVL,
      LT, NHD, (long long)LT*DM, (long long)NI*DM, HDD,
      (long long)MT*DM - (long long)LT*DM,
      1.f, eff, 1, BIGR, 1);
  // 8. output projection -> float pr
  tgemm<<<dim3(4, MALL/128, 1), 256, TG_DSMEM>>>(ap, wo_t, wo_i, MT,
      pr, DM, DM, DM, 0, 0,
      BIGR, 1, 0, 0, 0, 0, 1.f, eff, 1, BIGR, 0);
  // 9. attention residual (float)
  k_resgate<<<(MALL*DM)/256, 256>>>(txt, img, pr, e_txt, e_img, 1024, cc);
  // 10. norm2 combined -> half
  k_rmsmod<<<MALL, 128>>>(cc, cc + (long long)MT*DM, txt_norm2_w, img_norm2_w,
                          e_txt, e_img, 1536, 2048, nrm);
  // 11. fc1 -> half h
  tgemm<<<dim3(16, MALL/128, 1), 256, TG_DSMEM>>>(nrm, w1_t, w1_i, MT,
      hh, FFD, DM, FFD, 0, 0,
      BIGR, 1, 0, 0, 0, 0, 1.f, eff, 1, BIGR, 1);
  // 12. bias + gelu (half)
  k_biasgelu<<<(MALL*FFD)/256, 256>>>(hh, txt_fc1_b, img_fc1_b);
  // 13. fc2 -> float pr
  tgemm<<<dim3(4, MALL/128, 1), 256, TG_DSMEM>>>(hh, w2_t, w2_i, MT,
      pr, DM, FFD, DM, 0, 0,
      BIGR, 1, 0, 0, 0, 0, 1.f, eff, 1, BIGR, 0);
  // 14. final residual -> d_out
  k_final<<<(MALL*DM)/256, 256>>>(cc, pr, e_txt, e_img, txt_fc2_b, img_fc2_b, out);
}

// round 8
// speedup vs baseline: 2.0648x; 1.0454x over previous
#include <cuda_runtime.h>
#include <cuda_fp16.h>
#include <math.h>
#include <stdint.h>

// ---------------- problem dims (fixed) ----------------
#define NB   2
#define LT   512
#define NI   2048
#define DM   512
#define NHD  4
#define HDD  128
#define FFD  2048
#define KVL  2560
#define E6   3072
#define MT   (NB*LT)
#define MI   (NB*NI)
#define MALL (MT+MI)
#define SCALE_C 0.08838834764831845f
#define BIGR (1<<30)

// ---------------- scratch ----------------
__device__ __align__(256) float  d_e_img[NB*E6];
__device__ __align__(256) float  d_e_txt[NB*E6];
__device__ __align__(256) float  d_eff[NB];
__device__ __align__(256) float  d_mod[NB*NHD*NI];
__device__ __align__(256) __half d_nrm[MALL*DM];
__device__ __align__(256) __half d_qkv[MALL*3*NHD*HDD];
__device__ __align__(256) __half d_Qc[NB*NHD*KVL*HDD];
__device__ __align__(256) __half d_Kc[NB*NHD*KVL*HDD];
__device__ __align__(256) __half d_VT[NB*NHD*HDD*KVL];
__device__ __align__(256) __half d_S[NB*NHD*KVL*KVL];
__device__ __align__(256) __half d_ap[MALL*DM];
__device__ __align__(256) __half d_h[MALL*FFD];
__device__ __align__(256) float  d_pr[MALL*DM];
__device__ __align__(256) float  d_c[MALL*DM];
// half weights
__device__ __align__(256) __half d_wq_t[1536*DM];
__device__ __align__(256) __half d_wq_i[1536*DM];
__device__ __align__(256) __half d_wo_t[DM*DM];
__device__ __align__(256) __half d_wo_i[DM*DM];
__device__ __align__(256) __half d_w1_t[FFD*DM];
__device__ __align__(256) __half d_w1_i[FFD*DM];
__device__ __align__(256) __half d_w2_t[DM*FFD];
__device__ __align__(256) __half d_w2_i[DM*FFD];

// ---------------- helpers ----------------
__device__ __forceinline__ float warpSum(float v){
  #pragma unroll
  for (int o=16;o>0;o>>=1) v += __shfl_xor_sync(0xffffffffu, v, o);
  return v;
}
__device__ __forceinline__ float warpMax(float v){
  #pragma unroll
  for (int o=16;o>0;o>>=1) v = fmaxf(v, __shfl_xor_sync(0xffffffffu, v, o));
  return v;
}
__device__ __forceinline__ uint32_t sptr(const void* p){
  uint32_t r;
  asm("{ .reg .u64 t; cvta.to.shared.u64 t, %1; cvt.u32.u64 %0, t; }" : "=r"(r) : "l"(p));
  return r;
}

// ================= fp16 mma.sync batched GEMM: C = alpha * A(MxK) @ Bsel(NxK)^T =================
// CTA 128x128, 8 warps (2x4), warp tile 64x32, K-chunk 32 halves, double-buffered cp.async.
// Fragment loads via ldmatrix.x4 (conflict-free with 40-half row stride).
#define TSH 40
#define STAGE_H (128*TSH)          // halves per matrix per stage
#define STAGE_BYTES (STAGE_H*2)    // 10240
#define TG_DSMEM (4*STAGE_H*2)     // 40960

__global__ __launch_bounds__(256) void tgemm(
    const __half* __restrict__ A, const __half* __restrict__ B1,
    const __half* __restrict__ B2, int msplit,
    void* __restrict__ C, int N, int K, int ldc,
    long long sA, long long sB,
    int rsplit, int zdiv, long long sCt, long long sCi, long long sCh, long long cbase,
    float alpha, const float* __restrict__ alphas, int adiv, int arsplit, int outHalf)
{
  extern __shared__ __half smh[];
  __half* As = smh;
  __half* Bs = smh + 2*STAGE_H;

  const int tid = threadIdx.x;
  const int z   = blockIdx.z;
  const long long bm = (long long)blockIdx.y * 128;
  const long long bn = (long long)blockIdx.x * 128;

  const __half* Ab = A + z*sA + bm*K;
  const __half* Bsel = (bm < msplit) ? B1 : B2;
  const __half* Bb = Bsel + z*sB + bn*K;

  float alp = ((int)bm < arsplit) ? alpha : alphas[z/adiv];
  long long zoff = ((int)bm < rsplit)
      ? (long long)(z/zdiv)*sCt + (long long)(z%zdiv)*sCh
      : cbase + (long long)(z/zdiv)*sCi + (long long)(z%zdiv)*sCh;

  const int lw  = tid & 31;
  const int w   = tid >> 5;
  const int wr  = (w >> 2) * 64;
  const int wc  = (w & 3) * 32;
  const int g   = lw >> 2;
  const int tg  = lw & 3;

  const int lrow = tid >> 1;
  const int lsel = (tid & 1) * 16;

  // ldmatrix per-lane byte offsets (within a stage)
  // A x4: lanes 0-15 -> rows (l&15), k-halves 0-7; lanes 16-31 -> rows (l&15), k-halves 8-15
  const int a_row = lw & 15;
  const int a_kh  = (lw >> 4) * 8;
  uint32_t aoff[4];
  #pragma unroll
  for (int mt = 0; mt < 4; mt++)
    aoff[mt] = (uint32_t)(((wr + mt*16 + a_row)*TSH + a_kh) * 2);
  // B x4 (covers 2 n-tiles): m0=n0-7/k0-7, m1=n0-7/k8-15, m2=n8-15/k0-7, m3=n8-15/k8-15
  const int b_row = (lw & 7) + ((lw >> 4) & 1) * 8;
  const int b_kh  = ((lw >> 3) & 1) * 8;
  uint32_t boff[2];
  #pragma unroll
  for (int n2 = 0; n2 < 2; n2++)
    boff[n2] = (uint32_t)(((wc + n2*16 + b_row)*TSH + b_kh) * 2);

  const uint32_t Abase = sptr(As);
  const uint32_t Bbase = sptr(Bs);

  float acc[4][4][4];
  #pragma unroll
  for (int i=0;i<4;i++)
    #pragma unroll
    for (int j=0;j<4;j++)
      #pragma unroll
      for (int q=0;q<4;q++) acc[i][j][q] = 0.f;

  const int nch = K >> 5;

  auto load_chunk = [&](int c, int st){
    const __half* Ag = Ab + (long long)lrow*K + c*32 + lsel;
    const __half* Bg = Bb + (long long)lrow*K + c*32 + lsel;
    uint32_t da = sptr(As + st*STAGE_H + lrow*TSH + lsel);
    uint32_t db = sptr(Bs + st*STAGE_H + lrow*TSH + lsel);
    asm volatile("cp.async.cg.shared.global [%0], [%1], 16;" :: "r"(da),      "l"(Ag));
    asm volatile("cp.async.cg.shared.global [%0], [%1], 16;" :: "r"(da + 16), "l"(Ag + 8));
    asm volatile("cp.async.cg.shared.global [%0], [%1], 16;" :: "r"(db),      "l"(Bg));
    asm volatile("cp.async.cg.shared.global [%0], [%1], 16;" :: "r"(db + 16), "l"(Bg + 8));
    asm volatile("cp.async.commit_group;");
  };

  load_chunk(0, 0);

  for (int i = 0; i < nch; i++){
    int st = i & 1;
    if (i + 1 < nch){
      load_chunk(i+1, st^1);
      asm volatile("cp.async.wait_group 1;" ::: "memory");
    } else {
      asm volatile("cp.async.wait_group 0;" ::: "memory");
    }
    __syncthreads();

    uint32_t sa = Abase + st*STAGE_BYTES;
    uint32_t sb = Bbase + st*STAGE_BYTES;

    #pragma unroll
    for (int ks = 0; ks < 2; ks++){
      uint32_t koff = ks*32;   // 16 halves = 32 bytes
      uint32_t af[4][4];
      #pragma unroll
      for (int mt = 0; mt < 4; mt++){
        asm volatile(
          "ldmatrix.sync.aligned.m8n8.x4.shared.b16 {%0,%1,%2,%3}, [%4];"
          : "=r"(af[mt][0]), "=r"(af[mt][1]), "=r"(af[mt][2]), "=r"(af[mt][3])
          : "r"(sa + aoff[mt] + koff));
      }
      uint32_t bf[4][2];
      #pragma unroll
      for (int n2 = 0; n2 < 2; n2++){
        asm volatile(
          "ldmatrix.sync.aligned.m8n8.x4.shared.b16 {%0,%1,%2,%3}, [%4];"
          : "=r"(bf[n2*2][0]), "=r"(bf[n2*2][1]), "=r"(bf[n2*2+1][0]), "=r"(bf[n2*2+1][1])
          : "r"(sb + boff[n2] + koff));
      }
      #pragma unroll
      for (int mt = 0; mt < 4; mt++)
        #pragma unroll
        for (int nt = 0; nt < 4; nt++){
          asm volatile(
            "mma.sync.aligned.m16n8k16.row.col.f32.f16.f16.f32 "
            "{%0,%1,%2,%3}, {%4,%5,%6,%7}, {%8,%9}, {%0,%1,%2,%3};"
            : "+f"(acc[mt][nt][0]), "+f"(acc[mt][nt][1]),
              "+f"(acc[mt][nt][2]), "+f"(acc[mt][nt][3])
            : "r"(af[mt][0]), "r"(af[mt][1]), "r"(af[mt][2]), "r"(af[mt][3]),
              "r"(bf[nt][0]), "r"(bf[nt][1]));
        }
    }
    __syncthreads();
  }

  // epilogue
  if (outHalf){
    __half* Cb = (__half*)C + zoff;
    #pragma unroll
    for (int mt = 0; mt < 4; mt++){
      long long r0 = bm + wr + mt*16 + g;
      #pragma unroll
      for (int nt = 0; nt < 4; nt++){
        long long c0 = bn + wc + nt*8 + 2*tg;
        *(__half2*)(Cb + r0*ldc + c0)     = __floats2half2_rn(acc[mt][nt][0]*alp, acc[mt][nt][1]*alp);
        *(__half2*)(Cb + (r0+8)*ldc + c0) = __floats2half2_rn(acc[mt][nt][2]*alp, acc[mt][nt][3]*alp);
      }
    }
  } else {
    float* Cb = (float*)C + zoff;
    #pragma unroll
    for (int mt = 0; mt < 4; mt++){
      long long r0 = bm + wr + mt*16 + g;
      #pragma unroll
      for (int nt = 0; nt < 4; nt++){
        long long c0 = bn + wc + nt*8 + 2*tg;
        *(float2*)(Cb + r0*ldc + c0)     = make_float2(acc[mt][nt][0]*alp, acc[mt][nt][1]*alp);
        *(float2*)(Cb + (r0+8)*ldc + c0) = make_float2(acc[mt][nt][2]*alp, acc[mt][nt][3]*alp);
      }
    }
  }
}

// ---------------- convert 8 weight matrices float -> half ----------------
__global__ void k_half8(const float* __restrict__ i0, __half* __restrict__ o0,
                        const float* __restrict__ i1, __half* __restrict__ o1,
                        const float* __restrict__ i2, __half* __restrict__ o2,
                        const float* __restrict__ i3, __half* __restrict__ o3,
                        const float* __restrict__ i4, __half* __restrict__ o4,
                        const float* __restrict__ i5, __half* __restrict__ o5,
                        const float* __restrict__ i6, __half* __restrict__ o6,
                        const float* __restrict__ i7, __half* __restrict__ o7)
{
  int idx = blockIdx.x*blockDim.x + threadIdx.x;
  const float4* in; __half2* out; int off;
  if      (idx <  196608){ in=(const float4*)i0; out=(__half2*)o0; off=0; }
  else if (idx <  393216){ in=(const float4*)i1; out=(__half2*)o1; off=196608; }
  else if (idx <  458752){ in=(const float4*)i2; out=(__half2*)o2; off=393216; }
  else if (idx <  524288){ in=(const float4*)i3; out=(__half2*)o3; off=458752; }
  else if (idx <  786432){ in=(const float4*)i4; out=(__half2*)o4; off=524288; }
  else if (idx < 1048576){ in=(const float4*)i5; out=(__half2*)o5; off=786432; }
  else if (idx < 1310720){ in=(const float4*)i6; out=(__half2*)o6; off=1048576; }
  else                   { in=(const float4*)i7; out=(__half2*)o7; off=1310720; }
  int j = idx - off;
  float4 v = in[j];
  out[j*2]   = __floats2half2_rn(v.x, v.y);
  out[j*2+1] = __floats2half2_rn(v.z, v.w);
}

// ---------------- adaln embedding ----------------
__global__ void k_emb(const float* __restrict__ vec, const float* __restrict__ W,
                      const float* __restrict__ bias, float* __restrict__ e)
{
  int b = blockIdx.y;
  __shared__ float s[DM];
  for (int i = threadIdx.x; i < DM; i += blockDim.x){
    float v = vec[b*DM + i];
    s[i] = v / (1.f + expf(-v));
  }
  __syncthreads();
  int n = blockIdx.x*blockDim.x + threadIdx.x;
  const float* wr = W + (long long)n*DM;
  float acc = 0.f;
  #pragma unroll 8
  for (int k = 0; k < DM; k++) acc += s[k]*wr[k];
  e[b*E6 + n] = acc + bias[n];
}

__global__ void k_eff(const float* __restrict__ t, float* __restrict__ eff){
  int b = threadIdx.x;
  if (b < NB){
    float m = 0.25f*(t[b*NHD+0]+t[b*NHD+1]+t[b*NHD+2]+t[b*NHD+3]);
    eff[b] = SCALE_C / fmaxf(m, 0.1f);
  }
}

__global__ void k_mod(const float* __restrict__ sp, const float* __restrict__ mw,
                      const float* __restrict__ mb, float* __restrict__ mod)
{
  int idx = blockIdx.x*blockDim.x + threadIdx.x;
  if (idx >= NB*NHD*NI) return;
  int n = idx & (NI-1);
  int h = (idx >> 11) & (NHD-1);
  int b = idx >> 13;
  int y = n >> 5;
  int x = n & 31;
  float fy = (y + 0.5f)*0.125f - 0.5f;
  float fx = (x + 0.5f)*0.25f  - 0.5f;
  int y0 = (int)floorf(fy); float wy = fy - (float)y0;
  int x0 = (int)floorf(fx); float wx = fx - (float)x0;
  int y0c = min(max(y0,0),7), y1c = min(max(y0+1,0),7);
  int x0c = min(max(x0,0),7), x1c = min(max(x0+1,0),7);
  const float* p = sp + b*64;
  float v = (1.f-wy)*((1.f-wx)*p[y0c*8+x0c] + wx*p[y0c*8+x1c])
          +      wy *((1.f-wx)*p[y1c*8+x0c] + wx*p[y1c*8+x1c]);
  v = v*mw[h] + mb[h];
  v = fminf(fmaxf(v, -2.f), 2.f);
  mod[idx] = expf(v);
}

// ---------------- combined rms-norm + adaln modulate -> half ----------------
__global__ __launch_bounds__(128) void k_rmsmod(
    const float* __restrict__ xt, const float* __restrict__ xi,
    const float* __restrict__ wt, const float* __restrict__ wi,
    const float* __restrict__ et, const float* __restrict__ ei,
    int shift_off, int scale_off, __half* __restrict__ out)
{
  int row = blockIdx.x;
  const float* x; const float* w; const float* eb;
  if (row < MT){
    x = xt + (long long)row*DM; w = wt; eb = et + (row/LT)*E6;
  } else {
    int rr = row - MT;
    x = xi + (long long)rr*DM; w = wi; eb = ei + (rr/NI)*E6;
  }
  float4 xv = ((const float4*)x)[threadIdx.x];
  float ss = xv.x*xv.x + xv.y*xv.y + xv.z*xv.z + xv.w*xv.w;
  ss = warpSum(ss);
  __shared__ float red[4];
  int lane = threadIdx.x & 31, wid = threadIdx.x >> 5;
  if (lane==0) red[wid]=ss;
  __syncthreads();
  float tot = red[0]+red[1]+red[2]+red[3];
  float inv = rsqrtf(tot*(1.f/DM) + 1e-6f);
  int c = threadIdx.x*4;
  float ox = xv.x*inv*w[c+0]*(1.f+eb[scale_off+c+0]) + eb[shift_off+c+0];
  float oy = xv.y*inv*w[c+1]*(1.f+eb[scale_off+c+1]) + eb[shift_off+c+1];
  float oz = xv.z*inv*w[c+2]*(1.f+eb[scale_off+c+2]) + eb[shift_off+c+2];
  float ow = xv.w*inv*w[c+3]*(1.f+eb[scale_off+c+3]) + eb[shift_off+c+3];
  __half2* op = (__half2*)(out + (long long)row*DM);
  op[threadIdx.x*2]   = __floats2half2_rn(ox, oy);
  op[threadIdx.x*2+1] = __floats2half2_rn(oz, ow);
}

// ---------------- scatter img qkv (half) ----------------
__global__ void k_scatter_img(const __half* __restrict__ qkv, const float* __restrict__ rope,
                              const float* __restrict__ mod,
                              __half* __restrict__ Q, __half* __restrict__ K,
                              __half* __restrict__ VT)
{
  int idx = blockIdx.x*blockDim.x + threadIdx.x;
  int d2 = idx & 63;
  int r  = idx >> 6;
  int n  = r & (NI-1);
  int bh = r >> 11;
  int h  = bh & (NHD-1);
  int b  = bh >> 2;
  const __half* base = qkv + ((long long)(MT + b*NI + n))*(3*NHD*HDD) + h*HDD + 2*d2;
  float2 q = __half22float2(*(const __half2*)(base));
  float2 k = __half22float2(*(const __half2*)(base + NHD*HDD));
  float2 v = __half22float2(*(const __half2*)(base + 2*NHD*HDD));
  float c = rope[n*HDD + 2*d2];
  float s = rope[n*HDD + 2*d2 + 1];
  float m = mod[r];
  long long kv = (long long)bh*KVL + (LT + n);
  *(__half2*)(Q + kv*HDD + 2*d2) = __floats2half2_rn((q.x*c - q.y*s)*m, (q.y*c + q.x*s)*m);
  *(__half2*)(K + kv*HDD + 2*d2) = __floats2half2_rn((k.x*c - k.y*s)*m, (k.y*c + k.x*s)*m);
  VT[((long long)bh*HDD + 2*d2  )*KVL + (LT+n)] = __float2half_rn(v.x);
  VT[((long long)bh*HDD + 2*d2+1)*KVL + (LT+n)] = __float2half_rn(v.y);
}

// ---------------- scatter txt qkv (half) ----------------
__global__ void k_scatter_txt(const __half* __restrict__ qkv,
                              __half* __restrict__ Q, __half* __restrict__ K,
                              __half* __restrict__ VT)
{
  int idx = blockIdx.x*blockDim.x + threadIdx.x;
  int d2 = idx & 63;
  int r  = idx >> 6;
  int l  = r & (LT-1);
  int bh = r >> 9;
  int h  = bh & (NHD-1);
  int b  = bh >> 2;
  const __half* base = qkv + ((long long)(b*LT + l))*(3*NHD*HDD) + h*HDD + 2*d2;
  __half2 q = *(const __half2*)(base);
  __half2 k = *(const __half2*)(base + NHD*HDD);
  float2 v = __half22float2(*(const __half2*)(base + 2*NHD*HDD));
  long long kv = (long long)bh*KVL + l;
  *(__half2*)(Q + kv*HDD + 2*d2) = q;
  *(__half2*)(K + kv*HDD + 2*d2) = k;
  VT[((long long)bh*HDD + 2*d2  )*KVL + l] = __float2half_rn(v.x);
  VT[((long long)bh*HDD + 2*d2+1)*KVL + l] = __float2half_rn(v.y);
}

// ---------------- softmax over half rows of length KVL ----------------
__global__ __launch_bounds__(256) void k_softmax(__half* __restrict__ S){
  long long row = blockIdx.x;
  __half* p = S + row*KVL;
  int tid = threadIdx.x;
  float v[10];
  float m = -1e30f;
  #pragma unroll
  for (int i=0;i<10;i++){ v[i] = __half2float(p[tid + i*256]); m = fmaxf(m, v[i]); }
  m = warpMax(m);
  __shared__ float redm[8];
  __shared__ float reds[8];
  int lane = tid & 31, wid = tid >> 5;
  if (lane==0) redm[wid]=m;
  __syncthreads();
  float bm = redm[0];
  #pragma unroll
  for (int i=1;i<8;i++) bm = fmaxf(bm, redm[i]);
  float sum = 0.f;
  #pragma unroll
  for (int i=0;i<10;i++){ v[i] = __expf(v[i]-bm); sum += v[i]; }
  sum = warpSum(sum);
  if (lane==0) reds[wid]=sum;
  __syncthreads();
  float tot = reds[0]+reds[1]+reds[2]+reds[3]+reds[4]+reds[5]+reds[6]+reds[7];
  float inv = 1.f/tot;
  #pragma unroll
  for (int i=0;i<10;i++) p[tid + i*256] = __float2half_rn(v[i]*inv);
}

// ---------------- combined resgate (float) ----------------
__global__ void k_resgate(const float* __restrict__ rt, const float* __restrict__ ri,
                          const float* __restrict__ x,
                          const float* __restrict__ et, const float* __restrict__ ei,
                          int off, float* __restrict__ out)
{
  int idx = blockIdx.x*blockDim.x + threadIdx.x;
  if (idx >= MALL*DM) return;
  int d = idx & (DM-1);
  int row = idx >> 9;
  float res; const float* eb;
  if (row < MT){ res = rt[idx]; eb = et + (row/LT)*E6; }
  else { res = ri[idx - MT*DM]; eb = ei + ((row-MT)/NI)*E6; }
  out[idx] = res + eb[off + d]*x[idx];
}

// ---------------- bias + gelu on half ----------------
__global__ void k_biasgelu(__half* __restrict__ h, const float* __restrict__ bt,
                           const float* __restrict__ bi){
  int idx = blockIdx.x*blockDim.x + threadIdx.x;
  if (idx >= MALL*FFD) return;
  const float* bias = (idx < MT*FFD) ? bt : bi;
  float x = __half2float(h[idx]) + bias[idx & (FFD-1)];
  float x3 = x*x*x;
  float t = tanhf(0.7978845608028654f*(x + 0.044715f*x3));
  h[idx] = __float2half_rn(0.5f*x*(1.f+t));
}

// ---------------- final ----------------
__global__ void k_final(const float* __restrict__ cur, const float* __restrict__ x,
                        const float* __restrict__ et, const float* __restrict__ ei,
                        const float* __restrict__ bt, const float* __restrict__ bi,
                        float* __restrict__ out)
{
  int idx = blockIdx.x*blockDim.x + threadIdx.x;
  if (idx >= MALL*DM) return;
  int d = idx & (DM-1);
  int row = idx >> 9;
  const float* eb; const float* bias;
  if (row < MT){ eb = et + (row/LT)*E6; bias = bt; }
  else { eb = ei + ((row-MT)/NI)*E6; bias = bi; }
  out[idx] = cur[idx] + eb[2560 + d]*(x[idx] + bias[d]);
}

// ---------------- launch ----------------
#define GETSYMF(var, sym) float* var; cudaGetSymbolAddress((void**)&var, sym)
#define GETSYMH(var, sym) __half* var; cudaGetSymbolAddress((void**)&var, sym)

extern "C" void kernel_launch(void* const* d_in, const int* in_sizes, int n_in,
                              void* d_out, int out_size)
{
  const float* txt          = (const float*)d_in[0];
  const float* img          = (const float*)d_in[1];
  const float* vec          = (const float*)d_in[2];
  const float* rope         = (const float*)d_in[3];
  const float* sol_t        = (const float*)d_in[4];
  const float* sol_s        = (const float*)d_in[5];
  const float* img_adaln_w  = (const float*)d_in[6];
  const float* img_adaln_b  = (const float*)d_in[7];
  const float* img_adaln_nw = (const float*)d_in[8];
  const float* txt_adaln_w  = (const float*)d_in[9];
  const float* txt_adaln_b  = (const float*)d_in[10];
  const float* txt_adaln_nw = (const float*)d_in[11];
  const float* txt_qkv_w    = (const float*)d_in[12];
  const float* img_qkv_w    = (const float*)d_in[13];
  const float* txt_out_w    = (const float*)d_in[14];
  const float* img_out_w    = (const float*)d_in[15];
  const float* sol_mod_w    = (const float*)d_in[16];
  const float* sol_mod_b    = (const float*)d_in[17];
  const float* img_norm2_w  = (const float*)d_in[18];
  const float* txt_norm2_w  = (const float*)d_in[19];
  const float* img_fc1_w    = (const float*)d_in[20];
  const float* img_fc1_b    = (const float*)d_in[21];
  const float* img_fc2_w    = (const float*)d_in[22];
  const float* img_fc2_b    = (const float*)d_in[23];
  const float* txt_fc1_w    = (const float*)d_in[24];
  const float* txt_fc1_b    = (const float*)d_in[25];
  const float* txt_fc2_w    = (const float*)d_in[26];
  const float* txt_fc2_b    = (const float*)d_in[27];
  float* out = (float*)d_out;

  GETSYMF(e_img, d_e_img);  GETSYMF(e_txt, d_e_txt);
  GETSYMF(eff, d_eff);      GETSYMF(mod, d_mod);
  GETSYMH(nrm, d_nrm);      GETSYMH(qkv, d_qkv);
  GETSYMH(Qc, d_Qc);        GETSYMH(Kc, d_Kc);
  GETSYMH(VT, d_VT);        GETSYMH(S, d_S);
  GETSYMH(ap, d_ap);        GETSYMH(hh, d_h);
  GETSYMF(pr, d_pr);        GETSYMF(cc, d_c);
  GETSYMH(wq_t, d_wq_t);    GETSYMH(wq_i, d_wq_i);
  GETSYMH(wo_t, d_wo_t);    GETSYMH(wo_i, d_wo_i);
  GETSYMH(w1_t, d_w1_t);    GETSYMH(w1_i, d_w1_i);
  GETSYMH(w2_t, d_w2_t);    GETSYMH(w2_i, d_w2_i);

  // 0. weights -> half
  k_half8<<<1572864/256, 256>>>(txt_qkv_w, wq_t, img_qkv_w, wq_i,
                                txt_out_w, wo_t, img_out_w, wo_i,
                                txt_fc1_w, w1_t, img_fc1_w, w1_i,
                                txt_fc2_w, w2_t, img_fc2_w, w2_i);
  // 1. adaln embeddings + eff + mod
  k_emb<<<dim3(E6/256, NB), 256>>>(vec, img_adaln_w, img_adaln_b, e_img);
  k_emb<<<dim3(E6/256, NB), 256>>>(vec, txt_adaln_w, txt_adaln_b, e_txt);
  k_eff<<<1, 32>>>(sol_t, eff);
  k_mod<<<(NB*NHD*NI)/256, 256>>>(sol_s, sol_mod_w, sol_mod_b, mod);
  // 2. norm1 combined -> half
  k_rmsmod<<<MALL, 128>>>(txt, img, txt_adaln_nw, img_adaln_nw, e_txt, e_img, 0, 512, nrm);
  // 3. QKV combined -> half
  tgemm<<<dim3(12, MALL/128, 1), 256, TG_DSMEM>>>(nrm, wq_t, wq_i, MT,
      qkv, 1536, DM, 1536, 0, 0,
      BIGR, 1, 0, 0, 0, 0, 1.f, eff, 1, BIGR, 1);
  // 4. scatter -> Qc, Kc, V^T
  k_scatter_txt<<<(NB*NHD*LT*64)/256, 256>>>(qkv, Qc, Kc, VT);
  k_scatter_img<<<(NB*NHD*NI*64)/256, 256>>>(qkv, rope, mod, Qc, Kc, VT);
  // 5. scores combined -> half S
  tgemm<<<dim3(KVL/128, KVL/128, NB*NHD), 256, TG_DSMEM>>>(Qc, Kc, Kc, BIGR,
      S, KVL, HDD, KVL, (long long)KVL*HDD, (long long)KVL*HDD,
      BIGR, 1, (long long)KVL*KVL, 0, 0, 0,
      SCALE_C, eff, NHD, LT, 1);
  // 6. softmax (half)
  k_softmax<<<NB*NHD*KVL, 256>>>(S);
  // 7. P @ V -> packed half ap
  tgemm<<<dim3(1, KVL/128, NB*NHD), 256, TG_DSMEM>>>(S, VT, VT, BIGR,
      ap, HDD, KVL, DM, (long long)KVL*KVL, (long long)HDD*KVL,
      LT, NHD, (long long)LT*DM, (long long)NI*DM, HDD,
      (long long)MT*DM - (long long)LT*DM,
      1.f, eff, 1, BIGR, 1);
  // 8. output projection -> float pr
  tgemm<<<dim3(4, MALL/128, 1), 256, TG_DSMEM>>>(ap, wo_t, wo_i, MT,
      pr, DM, DM, DM, 0, 0,
      BIGR, 1, 0, 0, 0, 0, 1.f, eff, 1, BIGR, 0);
  // 9. attention residual (float)
  k_resgate<<<(MALL*DM)/256, 256>>>(txt, img, pr, e_txt, e_img, 1024, cc);
  // 10. norm2 combined -> half
  k_rmsmod<<<MALL, 128>>>(cc, cc + (long long)MT*DM, txt_norm2_w, img_norm2_w,
                          e_txt, e_img, 1536, 2048, nrm);
  // 11. fc1 -> half h
  tgemm<<<dim3(16, MALL/128, 1), 256, TG_DSMEM>>>(nrm, w1_t, w1_i, MT,
      hh, FFD, DM, FFD, 0, 0,
      BIGR, 1, 0, 0, 0, 0, 1.f, eff, 1, BIGR, 1);
  // 12. bias + gelu (half)
  k_biasgelu<<<(MALL*FFD)/256, 256>>>(hh, txt_fc1_b, img_fc1_b);
  // 13. fc2 -> float pr
  tgemm<<<dim3(4, MALL/128, 1), 256, TG_DSMEM>>>(hh, w2_t, w2_i, MT,
      pr, DM, FFD, DM, 0, 0,
      BIGR, 1, 0, 0, 0, 0, 1.f, eff, 1, BIGR, 0);
  // 14. final residual -> d_out
  k_final<<<(MALL*DM)/256, 256>>>(cc, pr, e_txt, e_img, txt_fc2_b, img_fc2_b, out);
}

// round 9
// speedup vs baseline: 2.0856x; 1.0101x over previous
#include <cuda_runtime.h>
#include <cuda_fp16.h>
#include <math.h>
#include <stdint.h>

// ---------------- problem dims (fixed) ----------------
#define NB   2
#define LT   512
#define NI   2048
#define DM   512
#define NHD  4
#define HDD  128
#define FFD  2048
#define KVL  2560
#define E6   3072
#define MT   (NB*LT)
#define MI   (NB*NI)
#define MALL (MT+MI)
#define SCALE_C 0.08838834764831845f
#define BIGR (1<<30)

// ---------------- scratch ----------------
__device__ __align__(256) float  d_e_img[NB*E6];
__device__ __align__(256) float  d_e_txt[NB*E6];
__device__ __align__(256) float  d_eff[NB];
__device__ __align__(256) float  d_mod[NB*NHD*NI];
__device__ __align__(256) __half d_nrm[MALL*DM];
__device__ __align__(256) __half d_qkv[MALL*3*NHD*HDD];
__device__ __align__(256) __half d_Qc[NB*NHD*KVL*HDD];
__device__ __align__(256) __half d_Kc[NB*NHD*KVL*HDD];
__device__ __align__(256) __half d_VT[NB*NHD*HDD*KVL];
__device__ __align__(256) __half d_ap[MALL*DM];
__device__ __align__(256) __half d_h[MALL*FFD];
__device__ __align__(256) float  d_pr[MALL*DM];
__device__ __align__(256) float  d_c[MALL*DM];
// half weights
__device__ __align__(256) __half d_wq_t[1536*DM];
__device__ __align__(256) __half d_wq_i[1536*DM];
__device__ __align__(256) __half d_wo_t[DM*DM];
__device__ __align__(256) __half d_wo_i[DM*DM];
__device__ __align__(256) __half d_w1_t[FFD*DM];
__device__ __align__(256) __half d_w1_i[FFD*DM];
__device__ __align__(256) __half d_w2_t[DM*FFD];
__device__ __align__(256) __half d_w2_i[DM*FFD];

// ---------------- helpers ----------------
__device__ __forceinline__ float warpSum(float v){
  #pragma unroll
  for (int o=16;o>0;o>>=1) v += __shfl_xor_sync(0xffffffffu, v, o);
  return v;
}
__device__ __forceinline__ uint32_t sptr(const void* p){
  uint32_t r;
  asm("{ .reg .u64 t; cvta.to.shared.u64 t, %1; cvt.u32.u64 %0, t; }" : "=r"(r) : "l"(p));
  return r;
}
#define HMMA(acc, a, b) \
  asm volatile( \
    "mma.sync.aligned.m16n8k16.row.col.f32.f16.f16.f32 " \
    "{%0,%1,%2,%3}, {%4,%5,%6,%7}, {%8,%9}, {%0,%1,%2,%3};" \
    : "+f"((acc)[0]), "+f"((acc)[1]), "+f"((acc)[2]), "+f"((acc)[3]) \
    : "r"((a)[0]), "r"((a)[1]), "r"((a)[2]), "r"((a)[3]), \
      "r"((b)[0]), "r"((b)[1]))
#define LDMX4(r0,r1,r2,r3, addr) \
  asm volatile("ldmatrix.sync.aligned.m8n8.x4.shared.b16 {%0,%1,%2,%3}, [%4];" \
    : "=r"(r0), "=r"(r1), "=r"(r2), "=r"(r3) : "r"(addr))
#define CPA16(dst, src) \
  asm volatile("cp.async.cg.shared.global [%0], [%1], 16;" :: "r"(dst), "l"(src))

// ================= fp16 mma.sync batched GEMM =================
#define TSH 40
#define STAGE_H (128*TSH)
#define STAGE_BYTES (STAGE_H*2)
#define TG_DSMEM (4*STAGE_H*2)

__global__ __launch_bounds__(256) void tgemm(
    const __half* __restrict__ A, const __half* __restrict__ B1,
    const __half* __restrict__ B2, int msplit,
    void* __restrict__ C, int N, int K, int ldc,
    long long sA, long long sB,
    int rsplit, int zdiv, long long sCt, long long sCi, long long sCh, long long cbase,
    float alpha, const float* __restrict__ alphas, int adiv, int arsplit, int outHalf)
{
  extern __shared__ __half smh[];
  __half* As = smh;
  __half* Bs = smh + 2*STAGE_H;

  const int tid = threadIdx.x;
  const int z   = blockIdx.z;
  const long long bm = (long long)blockIdx.y * 128;
  const long long bn = (long long)blockIdx.x * 128;

  const __half* Ab = A + z*sA + bm*K;
  const __half* Bsel = (bm < msplit) ? B1 : B2;
  const __half* Bb = Bsel + z*sB + bn*K;

  float alp = ((int)bm < arsplit) ? alpha : alphas[z/adiv];
  long long zoff = ((int)bm < rsplit)
      ? (long long)(z/zdiv)*sCt + (long long)(z%zdiv)*sCh
      : cbase + (long long)(z/zdiv)*sCi + (long long)(z%zdiv)*sCh;

  const int lw  = tid & 31;
  const int w   = tid >> 5;
  const int wr  = (w >> 2) * 64;
  const int wc  = (w & 3) * 32;
  const int g   = lw >> 2;
  const int tg  = lw & 3;

  const int lrow = tid >> 1;
  const int lsel = (tid & 1) * 16;

  const int a_row = lw & 15;
  const int a_kh  = (lw >> 4) * 8;
  uint32_t aoff[4];
  #pragma unroll
  for (int mt = 0; mt < 4; mt++)
    aoff[mt] = (uint32_t)(((wr + mt*16 + a_row)*TSH + a_kh) * 2);
  const int b_row = (lw & 7) + ((lw >> 4) & 1) * 8;
  const int b_kh  = ((lw >> 3) & 1) * 8;
  uint32_t boff[2];
  #pragma unroll
  for (int n2 = 0; n2 < 2; n2++)
    boff[n2] = (uint32_t)(((wc + n2*16 + b_row)*TSH + b_kh) * 2);

  const uint32_t Abase = sptr(As);
  const uint32_t Bbase = sptr(Bs);

  float acc[4][4][4];
  #pragma unroll
  for (int i=0;i<4;i++)
    #pragma unroll
    for (int j=0;j<4;j++)
      #pragma unroll
      for (int q=0;q<4;q++) acc[i][j][q] = 0.f;

  const int nch = K >> 5;

  auto load_chunk = [&](int c, int st){
    const __half* Ag = Ab + (long long)lrow*K + c*32 + lsel;
    const __half* Bg = Bb + (long long)lrow*K + c*32 + lsel;
    uint32_t da = sptr(As + st*STAGE_H + lrow*TSH + lsel);
    uint32_t db = sptr(Bs + st*STAGE_H + lrow*TSH + lsel);
    CPA16(da, Ag); CPA16(da+16, Ag+8);
    CPA16(db, Bg); CPA16(db+16, Bg+8);
    asm volatile("cp.async.commit_group;");
  };

  load_chunk(0, 0);

  for (int i = 0; i < nch; i++){
    int st = i & 1;
    if (i + 1 < nch){
      load_chunk(i+1, st^1);
      asm volatile("cp.async.wait_group 1;" ::: "memory");
    } else {
      asm volatile("cp.async.wait_group 0;" ::: "memory");
    }
    __syncthreads();

    uint32_t sa = Abase + st*STAGE_BYTES;
    uint32_t sb = Bbase + st*STAGE_BYTES;

    #pragma unroll
    for (int ks = 0; ks < 2; ks++){
      uint32_t koff = ks*32;
      uint32_t af[4][4];
      #pragma unroll
      for (int mt = 0; mt < 4; mt++)
        LDMX4(af[mt][0], af[mt][1], af[mt][2], af[mt][3], sa + aoff[mt] + koff);
      uint32_t bf[4][2];
      #pragma unroll
      for (int n2 = 0; n2 < 2; n2++)
        LDMX4(bf[n2*2][0], bf[n2*2][1], bf[n2*2+1][0], bf[n2*2+1][1], sb + boff[n2] + koff);
      #pragma unroll
      for (int mt = 0; mt < 4; mt++)
        #pragma unroll
        for (int nt = 0; nt < 4; nt++)
          HMMA(acc[mt][nt], af[mt], bf[nt]);
    }
    __syncthreads();
  }

  if (outHalf){
    __half* Cb = (__half*)C + zoff;
    #pragma unroll
    for (int mt = 0; mt < 4; mt++){
      long long r0 = bm + wr + mt*16 + g;
      #pragma unroll
      for (int nt = 0; nt < 4; nt++){
        long long c0 = bn + wc + nt*8 + 2*tg;
        *(__half2*)(Cb + r0*ldc + c0)     = __floats2half2_rn(acc[mt][nt][0]*alp, acc[mt][nt][1]*alp);
        *(__half2*)(Cb + (r0+8)*ldc + c0) = __floats2half2_rn(acc[mt][nt][2]*alp, acc[mt][nt][3]*alp);
      }
    }
  } else {
    float* Cb = (float*)C + zoff;
    #pragma unroll
    for (int mt = 0; mt < 4; mt++){
      long long r0 = bm + wr + mt*16 + g;
      #pragma unroll
      for (int nt = 0; nt < 4; nt++){
        long long c0 = bn + wc + nt*8 + 2*tg;
        *(float2*)(Cb + r0*ldc + c0)     = make_float2(acc[mt][nt][0]*alp, acc[mt][nt][1]*alp);
        *(float2*)(Cb + (r0+8)*ldc + c0) = make_float2(acc[mt][nt][2]*alp, acc[mt][nt][3]*alp);
      }
    }
  }
}

// ================= fused flash attention =================
#define QT 64
#define KT 64
#define NKT (KVL/KT)                     // 40 kv tiles
#define QSTR 136
#define VSTR 72
#define FL_Q   (QT*QSTR)                 // 8704 halves
#define FL_STG (KT*QSTR + HDD*VSTR)      // 17920 halves
#define FL_DSMEM ((FL_Q + 2*FL_STG)*2)   // 89088 bytes

__global__ __launch_bounds__(128, 2) void k_flash(
    const __half* __restrict__ Q, const __half* __restrict__ K,
    const __half* __restrict__ V,
    __half* __restrict__ ap, const float* __restrict__ eff)
{
  extern __shared__ __half sm[];
  __half* sq  = sm;
  __half* sst = sm + FL_Q;

  const int tid = threadIdx.x;
  const int lw  = tid & 31;
  const int w   = tid >> 5;
  const int g   = lw >> 2;
  const int tg  = lw & 3;
  const int qt  = blockIdx.x;
  const int z   = blockIdx.y;
  const int b   = z >> 2;
  const int h   = z & 3;
  const float alpha = (qt < LT/QT) ? SCALE_C : eff[b];

  const __half* Qg = Q + (long long)z*KVL*HDD + (long long)qt*QT*HDD;
  const __half* Kg = K + (long long)z*KVL*HDD;
  const __half* Vg = V + (long long)z*HDD*KVL;

  {
    int row = tid >> 1;
    int co  = (tid & 1) * 64;
    uint32_t dq = sptr(sq + row*QSTR + co);
    const __half* src = Qg + (long long)row*HDD + co;
    #pragma unroll
    for (int j = 0; j < 8; j++) CPA16(dq + j*16, src + j*8);
    asm volatile("cp.async.commit_group;");
  }

  auto load_tile = [&](int t, int st){
    __half* sk = sst + st*FL_STG;
    __half* sv = sk + KT*QSTR;
    int row = tid >> 1;
    int co  = (tid & 1) * 64;
    uint32_t dk = sptr(sk + row*QSTR + co);
    const __half* ks = Kg + (long long)(t*KT + row)*HDD + co;
    #pragma unroll
    for (int j = 0; j < 8; j++) CPA16(dk + j*16, ks + j*8);
    uint32_t dv = sptr(sv + tid*VSTR);
    const __half* vs = Vg + (long long)tid*KVL + t*KT;
    #pragma unroll
    for (int j = 0; j < 8; j++) CPA16(dv + j*16, vs + j*8);
    asm volatile("cp.async.commit_group;");
  };

  load_tile(0, 0);

  const int a_row = lw & 15;
  const int a_kh  = (lw >> 4) * 8;
  const int b_row = (lw & 7) + ((lw >> 4) & 1) * 8;
  const int b_kh  = ((lw >> 3) & 1) * 8;

  uint32_t aq[8][4];
  float O[16][4];
  #pragma unroll
  for (int i=0;i<16;i++){ O[i][0]=0.f; O[i][1]=0.f; O[i][2]=0.f; O[i][3]=0.f; }
  float m0 = -1e30f, m1 = -1e30f, l0 = 0.f, l1 = 0.f;
  const uint32_t sqb = sptr(sq);

  for (int t = 0; t < NKT; t++){
    int st = t & 1;
    if (t + 1 < NKT){
      load_tile(t+1, st^1);
      asm volatile("cp.async.wait_group 1;" ::: "memory");
    } else {
      asm volatile("cp.async.wait_group 0;" ::: "memory");
    }
    __syncthreads();

    if (t == 0){
      #pragma unroll
      for (int s = 0; s < 8; s++)
        LDMX4(aq[s][0], aq[s][1], aq[s][2], aq[s][3],
              sqb + (uint32_t)(((w*16 + a_row)*QSTR + s*16 + a_kh) * 2));
    }

    uint32_t skb = sptr(sst + st*FL_STG);
    uint32_t svb = skb + KT*QSTR*2;

    float sacc[8][4];
    #pragma unroll
    for (int i=0;i<8;i++){ sacc[i][0]=0.f; sacc[i][1]=0.f; sacc[i][2]=0.f; sacc[i][3]=0.f; }
    #pragma unroll
    for (int s = 0; s < 8; s++){
      uint32_t bk[8][2];
      #pragma unroll
      for (int p = 0; p < 4; p++)
        LDMX4(bk[p*2][0], bk[p*2][1], bk[p*2+1][0], bk[p*2+1][1],
              skb + (uint32_t)(((p*16 + b_row)*QSTR + s*16 + b_kh) * 2));
      #pragma unroll
      for (int nt = 0; nt < 8; nt++)
        HMMA(sacc[nt], aq[s], bk[nt]);
    }

    float mx0 = -1e30f, mx1 = -1e30f;
    #pragma unroll
    for (int nt = 0; nt < 8; nt++){
      sacc[nt][0] *= alpha; sacc[nt][1] *= alpha;
      sacc[nt][2] *= alpha; sacc[nt][3] *= alpha;
      mx0 = fmaxf(mx0, fmaxf(sacc[nt][0], sacc[nt][1]));
      mx1 = fmaxf(mx1, fmaxf(sacc[nt][2], sacc[nt][3]));
    }
    mx0 = fmaxf(mx0, __shfl_xor_sync(0xffffffffu, mx0, 1));
    mx0 = fmaxf(mx0, __shfl_xor_sync(0xffffffffu, mx0, 2));
    mx1 = fmaxf(mx1, __shfl_xor_sync(0xffffffffu, mx1, 1));
    mx1 = fmaxf(mx1, __shfl_xor_sync(0xffffffffu, mx1, 2));
    float mn0 = fmaxf(m0, mx0), mn1 = fmaxf(m1, mx1);
    float c0 = __expf(m0 - mn0), c1 = __expf(m1 - mn1);
    float sum0 = 0.f, sum1 = 0.f;
    #pragma unroll
    for (int nt = 0; nt < 8; nt++){
      sacc[nt][0] = __expf(sacc[nt][0] - mn0);
      sacc[nt][1] = __expf(sacc[nt][1] - mn0);
      sacc[nt][2] = __expf(sacc[nt][2] - mn1);
      sacc[nt][3] = __expf(sacc[nt][3] - mn1);
      sum0 += sacc[nt][0] + sacc[nt][1];
      sum1 += sacc[nt][2] + sacc[nt][3];
    }
    sum0 += __shfl_xor_sync(0xffffffffu, sum0, 1);
    sum0 += __shfl_xor_sync(0xffffffffu, sum0, 2);
    sum1 += __shfl_xor_sync(0xffffffffu, sum1, 1);
    sum1 += __shfl_xor_sync(0xffffffffu, sum1, 2);
    l0 = l0*c0 + sum0;  l1 = l1*c1 + sum1;
    m0 = mn0;  m1 = mn1;
    #pragma unroll
    for (int nt = 0; nt < 16; nt++){
      O[nt][0] *= c0; O[nt][1] *= c0;
      O[nt][2] *= c1; O[nt][3] *= c1;
    }

    uint32_t pf[4][4];
    #pragma unroll
    for (int j = 0; j < 4; j++){
      __half2 h0 = __floats2half2_rn(sacc[2*j][0],   sacc[2*j][1]);
      __half2 h1 = __floats2half2_rn(sacc[2*j][2],   sacc[2*j][3]);
      __half2 h2 = __floats2half2_rn(sacc[2*j+1][0], sacc[2*j+1][1]);
      __half2 h3 = __floats2half2_rn(sacc[2*j+1][2], sacc[2*j+1][3]);
      pf[j][0] = *(uint32_t*)&h0;  pf[j][1] = *(uint32_t*)&h1;
      pf[j][2] = *(uint32_t*)&h2;  pf[j][3] = *(uint32_t*)&h3;
    }

    #pragma unroll
    for (int s = 0; s < 4; s++){
      uint32_t bv[16][2];
      #pragma unroll
      for (int p = 0; p < 8; p++)
        LDMX4(bv[p*2][0], bv[p*2][1], bv[p*2+1][0], bv[p*2+1][1],
              svb + (uint32_t)(((p*16 + b_row)*VSTR + s*16 + b_kh) * 2));
      #pragma unroll
      for (int nt = 0; nt < 16; nt++)
        HMMA(O[nt], pf[s], bv[nt]);
    }
    __syncthreads();
  }

  float i0 = 1.f/l0, i1 = 1.f/l1;
  int q0 = qt*QT + w*16 + g;
  int q1 = q0 + 8;
  long long tok0 = (q0 < LT) ? (long long)(b*LT + q0) : (long long)(MT + b*NI + (q0 - LT));
  long long tok1 = (q1 < LT) ? (long long)(b*LT + q1) : (long long)(MT + b*NI + (q1 - LT));
  __half* o0 = ap + tok0*DM + h*HDD + 2*tg;
  __half* o1 = ap + tok1*DM + h*HDD + 2*tg;
  #pragma unroll
  for (int nt = 0; nt < 16; nt++){
    *(__half2*)(o0 + nt*8) = __floats2half2_rn(O[nt][0]*i0, O[nt][1]*i0);
    *(__half2*)(o1 + nt*8) = __floats2half2_rn(O[nt][2]*i1, O[nt][3]*i1);
  }
}

// ---------------- convert 8 weight matrices float -> half ----------------
__global__ void k_half8(const float* __restrict__ i0, __half* __restrict__ o0,
                        const float* __restrict__ i1, __half* __restrict__ o1,
                        const float* __restrict__ i2, __half* __restrict__ o2,
                        const float* __restrict__ i3, __half* __restrict__ o3,
                        const float* __restrict__ i4, __half* __restrict__ o4,
                        const float* __restrict__ i5, __half* __restrict__ o5,
                        const float* __restrict__ i6, __half* __restrict__ o6,
                        const float* __restrict__ i7, __half* __restrict__ o7)
{
  int idx = blockIdx.x*blockDim.x + threadIdx.x;
  const float4* in; __half2* out; int off;
  if      (idx <  196608){ in=(const float4*)i0; out=(__half2*)o0; off=0; }
  else if (idx <  393216){ in=(const float4*)i1; out=(__half2*)o1; off=196608; }
  else if (idx <  458752){ in=(const float4*)i2; out=(__half2*)o2; off=393216; }
  else if (idx <  524288){ in=(const float4*)i3; out=(__half2*)o3; off=458752; }
  else if (idx <  786432){ in=(const float4*)i4; out=(__half2*)o4; off=524288; }
  else if (idx < 1048576){ in=(const float4*)i5; out=(__half2*)o5; off=786432; }
  else if (idx < 1310720){ in=(const float4*)i6; out=(__half2*)o6; off=1048576; }
  else                   { in=(const float4*)i7; out=(__half2*)o7; off=1310720; }
  int j = idx - off;
  float4 v = in[j];
  out[j*2]   = __floats2half2_rn(v.x, v.y);
  out[j*2+1] = __floats2half2_rn(v.z, v.w);
}

// ---------------- adaln embedding ----------------
__global__ void k_emb(const float* __restrict__ vec, const float* __restrict__ W,
                      const float* __restrict__ bias, float* __restrict__ e)
{
  int b = blockIdx.y;
  __shared__ float s[DM];
  for (int i = threadIdx.x; i < DM; i += blockDim.x){
    float v = vec[b*DM + i];
    s[i] = v / (1.f + expf(-v));
  }
  __syncthreads();
  int n = blockIdx.x*blockDim.x + threadIdx.x;
  const float* wr = W + (long long)n*DM;
  float acc = 0.f;
  #pragma unroll 8
  for (int k = 0; k < DM; k++) acc += s[k]*wr[k];
  e[b*E6 + n] = acc + bias[n];
}

__global__ void k_eff(const float* __restrict__ t, float* __restrict__ eff){
  int b = threadIdx.x;
  if (b < NB){
    float m = 0.25f*(t[b*NHD+0]+t[b*NHD+1]+t[b*NHD+2]+t[b*NHD+3]);
    eff[b] = SCALE_C / fmaxf(m, 0.1f);
  }
}

__global__ void k_mod(const float* __restrict__ sp, const float* __restrict__ mw,
                      const float* __restrict__ mb, float* __restrict__ mod)
{
  int idx = blockIdx.x*blockDim.x + threadIdx.x;
  if (idx >= NB*NHD*NI) return;
  int n = idx & (NI-1);
  int h = (idx >> 11) & (NHD-1);
  int b = idx >> 13;
  int y = n >> 5;
  int x = n & 31;
  float fy = (y + 0.5f)*0.125f - 0.5f;
  float fx = (x + 0.5f)*0.25f  - 0.5f;
  int y0 = (int)floorf(fy); float wy = fy - (float)y0;
  int x0 = (int)floorf(fx); float wx = fx - (float)x0;
  int y0c = min(max(y0,0),7), y1c = min(max(y0+1,0),7);
  int x0c = min(max(x0,0),7), x1c = min(max(x0+1,0),7);
  const float* p = sp + b*64;
  float v = (1.f-wy)*((1.f-wx)*p[y0c*8+x0c] + wx*p[y0c*8+x1c])
          +      wy *((1.f-wx)*p[y1c*8+x0c] + wx*p[y1c*8+x1c]);
  v = v*mw[h] + mb[h];
  v = fminf(fmaxf(v, -2.f), 2.f);
  mod[idx] = expf(v);
}

// ---------------- combined rms-norm + adaln modulate -> half ----------------
__global__ __launch_bounds__(128) void k_rmsmod(
    const float* __restrict__ xt, const float* __restrict__ xi,
    const float* __restrict__ wt, const float* __restrict__ wi,
    const float* __restrict__ et, const float* __restrict__ ei,
    int shift_off, int scale_off, __half* __restrict__ out)
{
  int row = blockIdx.x;
  const float* x; const float* w; const float* eb;
  if (row < MT){
    x = xt + (long long)row*DM; w = wt; eb = et + (row/LT)*E6;
  } else {
    int rr = row - MT;
    x = xi + (long long)rr*DM; w = wi; eb = ei + (rr/NI)*E6;
  }
  float4 xv = ((const float4*)x)[threadIdx.x];
  float ss = xv.x*xv.x + xv.y*xv.y + xv.z*xv.z + xv.w*xv.w;
  ss = warpSum(ss);
  __shared__ float red[4];
  int lane = threadIdx.x & 31, wid = threadIdx.x >> 5;
  if (lane==0) red[wid]=ss;
  __syncthreads();
  float tot = red[0]+red[1]+red[2]+red[3];
  float inv = rsqrtf(tot*(1.f/DM) + 1e-6f);
  int c = threadIdx.x*4;
  float ox = xv.x*inv*w[c+0]*(1.f+eb[scale_off+c+0]) + eb[shift_off+c+0];
  float oy = xv.y*inv*w[c+1]*(1.f+eb[scale_off+c+1]) + eb[shift_off+c+1];
  float oz = xv.z*inv*w[c+2]*(1.f+eb[scale_off+c+2]) + eb[shift_off+c+2];
  float ow = xv.w*inv*w[c+3]*(1.f+eb[scale_off+c+3]) + eb[shift_off+c+3];
  __half2* op = (__half2*)(out + (long long)row*DM);
  op[threadIdx.x*2]   = __floats2half2_rn(ox, oy);
  op[threadIdx.x*2+1] = __floats2half2_rn(oz, ow);
}

// ---------------- scatter img qkv (half) ----------------
__global__ void k_scatter_img(const __half* __restrict__ qkv, const float* __restrict__ rope,
                              const float* __restrict__ mod,
                              __half* __restrict__ Q, __half* __restrict__ K,
                              __half* __restrict__ VT)
{
  int idx = blockIdx.x*blockDim.x + threadIdx.x;
  int d2 = idx & 63;
  int r  = idx >> 6;
  int n  = r & (NI-1);
  int bh = r >> 11;
  int h  = bh & (NHD-1);
  int b  = bh >> 2;
  const __half* base = qkv + ((long long)(MT + b*NI + n))*(3*NHD*HDD) + h*HDD + 2*d2;
  float2 q = __half22float2(*(const __half2*)(base));
  float2 k = __half22float2(*(const __half2*)(base + NHD*HDD));
  float2 v = __half22float2(*(const __half2*)(base + 2*NHD*HDD));
  float c = rope[n*HDD + 2*d2];
  float s = rope[n*HDD + 2*d2 + 1];
  float m = mod[r];
  long long kv = (long long)bh*KVL + (LT + n);
  *(__half2*)(Q + kv*HDD + 2*d2) = __floats2half2_rn((q.x*c - q.y*s)*m, (q.y*c + q.x*s)*m);
  *(__half2*)(K + kv*HDD + 2*d2) = __floats2half2_rn((k.x*c - k.y*s)*m, (k.y*c + k.x*s)*m);
  VT[((long long)bh*HDD + 2*d2  )*KVL + (LT+n)] = __float2half_rn(v.x);
  VT[((long long)bh*HDD + 2*d2+1)*KVL + (LT+n)] = __float2half_rn(v.y);
}

// ---------------- scatter txt qkv (half) ----------------
__global__ void k_scatter_txt(const __half* __restrict__ qkv,
                              __half* __restrict__ Q, __half* __restrict__ K,
                              __half* __restrict__ VT)
{
  int idx = blockIdx.x*blockDim.x + threadIdx.x;
  int d2 = idx & 63;
  int r  = idx >> 6;
  int l  = r & (LT-1);
  int bh = r >> 9;
  int h  = bh & (NHD-1);
  int b  = bh >> 2;
  const __half* base = qkv + ((long long)(b*LT + l))*(3*NHD*HDD) + h*HDD + 2*d2;
  __half2 q = *(const __half2*)(base);
  __half2 k = *(const __half2*)(base + NHD*HDD);
  float2 v = __half22float2(*(const __half2*)(base + 2*NHD*HDD));
  long long kv = (long long)bh*KVL + l;
  *(__half2*)(Q + kv*HDD + 2*d2) = q;
  *(__half2*)(K + kv*HDD + 2*d2) = k;
  VT[((long long)bh*HDD + 2*d2  )*KVL + l] = __float2half_rn(v.x);
  VT[((long long)bh*HDD + 2*d2+1)*KVL + l] = __float2half_rn(v.y);
}

// ---------------- combined resgate (float) ----------------
__global__ void k_resgate(const float* __restrict__ rt, const float* __restrict__ ri,
                          const float* __restrict__ x,
                          const float* __restrict__ et, const float* __restrict__ ei,
                          int off, float* __restrict__ out)
{
  int idx = blockIdx.x*blockDim.x + threadIdx.x;
  if (idx >= MALL*DM) return;
  int d = idx & (DM-1);
  int row = idx >> 9;
  float res; const float* eb;
  if (row < MT){ res = rt[idx]; eb = et + (row/LT)*E6; }
  else { res = ri[idx - MT*DM]; eb = ei + ((row-MT)/NI)*E6; }
  out[idx] = res + eb[off + d]*x[idx];
}

// ---------------- bias + gelu on half ----------------
__global__ void k_biasgelu(__half* __restrict__ h, const float* __restrict__ bt,
                           const float* __restrict__ bi){
  int idx = blockIdx.x*blockDim.x + threadIdx.x;
  if (idx >= MALL*FFD) return;
  const float* bias = (idx < MT*FFD) ? bt : bi;
  float x = __half2float(h[idx]) + bias[idx & (FFD-1)];
  float x3 = x*x*x;
  float t = tanhf(0.7978845608028654f*(x + 0.044715f*x3));
  h[idx] = __float2half_rn(0.5f*x*(1.f+t));
}

// ---------------- final ----------------
__global__ void k_final(const float* __restrict__ cur, const float* __restrict__ x,
                        const float* __restrict__ et, const float* __restrict__ ei,
                        const float* __restrict__ bt, const float* __restrict__ bi,
                        float* __restrict__ out)
{
  int idx = blockIdx.x*blockDim.x + threadIdx.x;
  if (idx >= MALL*DM) return;
  int d = idx & (DM-1);
  int row = idx >> 9;
  const float* eb; const float* bias;
  if (row < MT){ eb = et + (row/LT)*E6; bias = bt; }
  else { eb = ei + ((row-MT)/NI)*E6; bias = bi; }
  out[idx] = cur[idx] + eb[2560 + d]*(x[idx] + bias[d]);
}

// ---------------- launch ----------------
#define GETSYMF(var, sym) float* var; cudaGetSymbolAddress((void**)&var, sym)
#define GETSYMH(var, sym) __half* var; cudaGetSymbolAddress((void**)&var, sym)

extern "C" void kernel_launch(void* const* d_in, const int* in_sizes, int n_in,
                              void* d_out, int out_size)
{
  const float* txt          = (const float*)d_in[0];
  const float* img          = (const float*)d_in[1];
  const float* vec          = (const float*)d_in[2];
  const float* rope         = (const float*)d_in[3];
  const float* sol_t        = (const float*)d_in[4];
  const float* sol_s        = (const float*)d_in[5];
  const float* img_adaln_w  = (const float*)d_in[6];
  const float* img_adaln_b  = (const float*)d_in[7];
  const float* img_adaln_nw = (const float*)d_in[8];
  const float* txt_adaln_w  = (const float*)d_in[9];
  const float* txt_adaln_b  = (const float*)d_in[10];
  const float* txt_adaln_nw = (const float*)d_in[11];
  const float* txt_qkv_w    = (const float*)d_in[12];
  const float* img_qkv_w    = (const float*)d_in[13];
  const float* txt_out_w    = (const float*)d_in[14];
  const float* img_out_w    = (const float*)d_in[15];
  const float* sol_mod_w    = (const float*)d_in[16];
  const float* sol_mod_b    = (const float*)d_in[17];
  const float* img_norm2_w  = (const float*)d_in[18];
  const float* txt_norm2_w  = (const float*)d_in[19];
  const float* img_fc1_w    = (const float*)d_in[20];
  const float* img_fc1_b    = (const float*)d_in[21];
  const float* img_fc2_w    = (const float*)d_in[22];
  const float* img_fc2_b    = (const float*)d_in[23];
  const float* txt_fc1_w    = (const float*)d_in[24];
  const float* txt_fc1_b    = (const float*)d_in[25];
  const float* txt_fc2_w    = (const float*)d_in[26];
  const float* txt_fc2_b    = (const float*)d_in[27];
  float* out = (float*)d_out;

  GETSYMF(e_img, d_e_img);  GETSYMF(e_txt, d_e_txt);
  GETSYMF(eff, d_eff);      GETSYMF(mod, d_mod);
  GETSYMH(nrm, d_nrm);      GETSYMH(qkv, d_qkv);
  GETSYMH(Qc, d_Qc);        GETSYMH(Kc, d_Kc);
  GETSYMH(VT, d_VT);
  GETSYMH(ap, d_ap);        GETSYMH(hh, d_h);
  GETSYMF(pr, d_pr);        GETSYMF(cc, d_c);
  GETSYMH(wq_t, d_wq_t);    GETSYMH(wq_i, d_wq_i);
  GETSYMH(wo_t, d_wo_t);    GETSYMH(wo_i, d_wo_i);
  GETSYMH(w1_t, d_w1_t);    GETSYMH(w1_i, d_w1_i);
  GETSYMH(w2_t, d_w2_t);    GETSYMH(w2_i, d_w2_i);

  cudaFuncSetAttribute(tgemm,   cudaFuncAttributeMaxDynamicSharedMemorySize, TG_DSMEM);
  cudaFuncSetAttribute(k_flash, cudaFuncAttributeMaxDynamicSharedMemorySize, FL_DSMEM);

  // 0. weights -> half
  k_half8<<<1572864/256, 256>>>(txt_qkv_w, wq_t, img_qkv_w, wq_i,
                                txt_out_w, wo_t, img_out_w, wo_i,
                                txt_fc1_w, w1_t, img_fc1_w, w1_i,
                                txt_fc2_w, w2_t, img_fc2_w, w2_i);
  // 1. adaln embeddings + eff + mod
  k_emb<<<dim3(E6/256, NB), 256>>>(vec, img_adaln_w, img_adaln_b, e_img);
  k_emb<<<dim3(E6/256, NB), 256>>>(vec, txt_adaln_w, txt_adaln_b, e_txt);
  k_eff<<<1, 32>>>(sol_t, eff);
  k_mod<<<(NB*NHD*NI)/256, 256>>>(sol_s, sol_mod_w, sol_mod_b, mod);
  // 2. norm1 combined -> half
  k_rmsmod<<<MALL, 128>>>(txt, img, txt_adaln_nw, img_adaln_nw, e_txt, e_img, 0, 512, nrm);
  // 3. QKV combined -> half
  tgemm<<<dim3(12, MALL/128, 1), 256, TG_DSMEM>>>(nrm, wq_t, wq_i, MT,
      qkv, 1536, DM, 1536, 0, 0,
      BIGR, 1, 0, 0, 0, 0, 1.f, eff, 1, BIGR, 1);
  // 4. scatter -> Qc, Kc, V^T
  k_scatter_txt<<<(NB*NHD*LT*64)/256, 256>>>(qkv, Qc, Kc, VT);
  k_scatter_img<<<(NB*NHD*NI*64)/256, 256>>>(qkv, rope, mod, Qc, Kc, VT);
  // 5. fused flash attention -> packed half ap
  k_flash<<<dim3(KVL/QT, NB*NHD), 128, FL_DSMEM>>>(Qc, Kc, VT, ap, eff);
  // 6. output projection -> float pr
  tgemm<<<dim3(4, MALL/128, 1), 256, TG_DSMEM>>>(ap, wo_t, wo_i, MT,
      pr, DM, DM, DM, 0, 0,
      BIGR, 1, 0, 0, 0, 0, 1.f, eff, 1, BIGR, 0);
  // 7. attention residual (float)
  k_resgate<<<(MALL*DM)/256, 256>>>(txt, img, pr, e_txt, e_img, 1024, cc);
  // 8. norm2 combined -> half
  k_rmsmod<<<MALL, 128>>>(cc, cc + (long long)MT*DM, txt_norm2_w, img_norm2_w,
                          e_txt, e_img, 1536, 2048, nrm);
  // 9. fc1 -> half h
  tgemm<<<dim3(16, MALL/128, 1), 256, TG_DSMEM>>>(nrm, w1_t, w1_i, MT,
      hh, FFD, DM, FFD, 0, 0,
      BIGR, 1, 0, 0, 0, 0, 1.f, eff, 1, BIGR, 1);
  // 10. bias + gelu (half)
  k_biasgelu<<<(MALL*FFD)/256, 256>>>(hh, txt_fc1_b, img_fc1_b);
  // 11. fc2 -> float pr
  tgemm<<<dim3(4, MALL/128, 1), 256, TG_DSMEM>>>(hh, w2_t, w2_i, MT,
      pr, DM, FFD, DM, 0, 0,
      BIGR, 1, 0, 0, 0, 0, 1.f, eff, 1, BIGR, 0);
  // 12. final residual -> d_out
  k_final<<<(MALL*DM)/256, 256>>>(cc, pr, e_txt, e_img, txt_fc2_b, img_fc2_b, out);
}

// round 10
// speedup vs baseline: 2.2697x; 1.0882x over previous
#include <cuda_runtime.h>
#include <cuda_fp16.h>
#include <math.h>
#include <stdint.h>

// ---------------- problem dims (fixed) ----------------
#define NB   2
#define LT   512
#define NI   2048
#define DM   512
#define NHD  4
#define HDD  128
#define FFD  2048
#define KVL  2560
#define E6   3072
#define MT   (NB*LT)
#define MI   (NB*NI)
#define MALL (MT+MI)
#define SCALE_C 0.08838834764831845f
#define BIGR (1<<30)

// ---------------- scratch ----------------
__device__ __align__(256) float  d_e_img[NB*E6];
__device__ __align__(256) float  d_e_txt[NB*E6];
__device__ __align__(256) float  d_eff[NB];
__device__ __align__(256) float  d_mod[NB*NHD*NI];
__device__ __align__(256) __half d_nrm[MALL*DM];
__device__ __align__(256) __half d_qkv[MALL*3*NHD*HDD];
__device__ __align__(256) __half d_Qc[NB*NHD*KVL*HDD];
__device__ __align__(256) __half d_Kc[NB*NHD*KVL*HDD];
__device__ __align__(256) __half d_VT[NB*NHD*HDD*KVL];
__device__ __align__(256) __half d_ap[MALL*DM];
__device__ __align__(256) __half d_h[MALL*FFD];
__device__ __align__(256) float  d_c[MALL*DM];
// half weights
__device__ __align__(256) __half d_wq_t[1536*DM];
__device__ __align__(256) __half d_wq_i[1536*DM];
__device__ __align__(256) __half d_wo_t[DM*DM];
__device__ __align__(256) __half d_wo_i[DM*DM];
__device__ __align__(256) __half d_w1_t[FFD*DM];
__device__ __align__(256) __half d_w1_i[FFD*DM];
__device__ __align__(256) __half d_w2_t[DM*FFD];
__device__ __align__(256) __half d_w2_i[DM*FFD];

// ---------------- helpers ----------------
__device__ __forceinline__ float warpSum(float v){
  #pragma unroll
  for (int o=16;o>0;o>>=1) v += __shfl_xor_sync(0xffffffffu, v, o);
  return v;
}
__device__ __forceinline__ uint32_t sptr(const void* p){
  uint32_t r;
  asm("{ .reg .u64 t; cvta.to.shared.u64 t, %1; cvt.u32.u64 %0, t; }" : "=r"(r) : "l"(p));
  return r;
}
__device__ __forceinline__ float geluf(float x){
  float t = tanhf(0.7978845608028654f*(x + 0.044715f*x*x*x));
  return 0.5f*x*(1.f+t);
}
#define HMMA(acc, a, b) \
  asm volatile( \
    "mma.sync.aligned.m16n8k16.row.col.f32.f16.f16.f32 " \
    "{%0,%1,%2,%3}, {%4,%5,%6,%7}, {%8,%9}, {%0,%1,%2,%3};" \
    : "+f"((acc)[0]), "+f"((acc)[1]), "+f"((acc)[2]), "+f"((acc)[3]) \
    : "r"((a)[0]), "r"((a)[1]), "r"((a)[2]), "r"((a)[3]), \
      "r"((b)[0]), "r"((b)[1]))
#define LDMX4(r0,r1,r2,r3, addr) \
  asm volatile("ldmatrix.sync.aligned.m8n8.x4.shared.b16 {%0,%1,%2,%3}, [%4];" \
    : "=r"(r0), "=r"(r1), "=r"(r2), "=r"(r3) : "r"(addr))
#define CPA16(dst, src) \
  asm volatile("cp.async.cg.shared.global [%0], [%1], 16;" :: "r"(dst), "l"(src))

// ================= fp16 mma.sync batched GEMM with fused epilogues =================
// ep: 0=float*alpha, 1=half*alpha, 2=resgate float (R + g*acc),
//     3=bias+gelu half, 4=final float (Cur + g*(acc+bias))
#define TSH 40
#define STAGE_H (128*TSH)
#define STAGE_BYTES (STAGE_H*2)
#define TG_DSMEM (4*STAGE_H*2)

__global__ __launch_bounds__(256) void tgemm(
    const __half* __restrict__ A, const __half* __restrict__ B1,
    const __half* __restrict__ B2, int msplit,
    void* __restrict__ C, int N, int K, int ldc,
    long long sA, long long sB,
    int rsplit, int zdiv, long long sCt, long long sCi, long long sCh, long long cbase,
    float alpha, const float* __restrict__ alphas, int adiv, int arsplit,
    int ep,
    const float* __restrict__ epRt, const float* __restrict__ epRi,
    const float* __restrict__ epEt, const float* __restrict__ epEi,
    const float* __restrict__ epBt, const float* __restrict__ epBi, int go)
{
  extern __shared__ __half smh[];
  __half* As = smh;
  __half* Bs = smh + 2*STAGE_H;

  const int tid = threadIdx.x;
  const int z   = blockIdx.z;
  const long long bm = (long long)blockIdx.y * 128;
  const long long bn = (long long)blockIdx.x * 128;

  const __half* Ab = A + z*sA + bm*K;
  const __half* Bsel = (bm < msplit) ? B1 : B2;
  const __half* Bb = Bsel + z*sB + bn*K;

  float alp = ((int)bm < arsplit) ? alpha : alphas[z/adiv];
  long long zoff = ((int)bm < rsplit)
      ? (long long)(z/zdiv)*sCt + (long long)(z%zdiv)*sCh
      : cbase + (long long)(z/zdiv)*sCi + (long long)(z%zdiv)*sCh;

  const int lw  = tid & 31;
  const int w   = tid >> 5;
  const int wr  = (w >> 2) * 64;
  const int wc  = (w & 3) * 32;
  const int g   = lw >> 2;
  const int tg  = lw & 3;

  const int lrow = tid >> 1;
  const int lsel = (tid & 1) * 16;

  const int a_row = lw & 15;
  const int a_kh  = (lw >> 4) * 8;
  uint32_t aoff[4];
  #pragma unroll
  for (int mt = 0; mt < 4; mt++)
    aoff[mt] = (uint32_t)(((wr + mt*16 + a_row)*TSH + a_kh) * 2);
  const int b_row = (lw & 7) + ((lw >> 4) & 1) * 8;
  const int b_kh  = ((lw >> 3) & 1) * 8;
  uint32_t boff[2];
  #pragma unroll
  for (int n2 = 0; n2 < 2; n2++)
    boff[n2] = (uint32_t)(((wc + n2*16 + b_row)*TSH + b_kh) * 2);

  const uint32_t Abase = sptr(As);
  const uint32_t Bbase = sptr(Bs);

  float acc[4][4][4];
  #pragma unroll
  for (int i=0;i<4;i++)
    #pragma unroll
    for (int j=0;j<4;j++)
      #pragma unroll
      for (int q=0;q<4;q++) acc[i][j][q] = 0.f;

  const int nch = K >> 5;

  auto load_chunk = [&](int c, int st){
    const __half* Ag = Ab + (long long)lrow*K + c*32 + lsel;
    const __half* Bg = Bb + (long long)lrow*K + c*32 + lsel;
    uint32_t da = sptr(As + st*STAGE_H + lrow*TSH + lsel);
    uint32_t db = sptr(Bs + st*STAGE_H + lrow*TSH + lsel);
    CPA16(da, Ag); CPA16(da+16, Ag+8);
    CPA16(db, Bg); CPA16(db+16, Bg+8);
    asm volatile("cp.async.commit_group;");
  };

  load_chunk(0, 0);

  for (int i = 0; i < nch; i++){
    int st = i & 1;
    if (i + 1 < nch){
      load_chunk(i+1, st^1);
      asm volatile("cp.async.wait_group 1;" ::: "memory");
    } else {
      asm volatile("cp.async.wait_group 0;" ::: "memory");
    }
    __syncthreads();

    uint32_t sa = Abase + st*STAGE_BYTES;
    uint32_t sb = Bbase + st*STAGE_BYTES;

    #pragma unroll
    for (int ks = 0; ks < 2; ks++){
      uint32_t koff = ks*32;
      uint32_t af[4][4];
      #pragma unroll
      for (int mt = 0; mt < 4; mt++)
        LDMX4(af[mt][0], af[mt][1], af[mt][2], af[mt][3], sa + aoff[mt] + koff);
      uint32_t bf[4][2];
      #pragma unroll
      for (int n2 = 0; n2 < 2; n2++)
        LDMX4(bf[n2*2][0], bf[n2*2][1], bf[n2*2+1][0], bf[n2*2+1][1], sb + boff[n2] + koff);
      #pragma unroll
      for (int mt = 0; mt < 4; mt++)
        #pragma unroll
        for (int nt = 0; nt < 4; nt++)
          HMMA(acc[mt][nt], af[mt], bf[nt]);
    }
    __syncthreads();
  }

  // -------- epilogue --------
  if (ep == 1){
    __half* Cb = (__half*)C + zoff;
    #pragma unroll
    for (int mt = 0; mt < 4; mt++){
      long long r0 = bm + wr + mt*16 + g;
      #pragma unroll
      for (int nt = 0; nt < 4; nt++){
        long long c0 = bn + wc + nt*8 + 2*tg;
        *(__half2*)(Cb + r0*ldc + c0)     = __floats2half2_rn(acc[mt][nt][0]*alp, acc[mt][nt][1]*alp);
        *(__half2*)(Cb + (r0+8)*ldc + c0) = __floats2half2_rn(acc[mt][nt][2]*alp, acc[mt][nt][3]*alp);
      }
    }
  } else if (ep == 0){
    float* Cb = (float*)C + zoff;
    #pragma unroll
    for (int mt = 0; mt < 4; mt++){
      long long r0 = bm + wr + mt*16 + g;
      #pragma unroll
      for (int nt = 0; nt < 4; nt++){
        long long c0 = bn + wc + nt*8 + 2*tg;
        *(float2*)(Cb + r0*ldc + c0)     = make_float2(acc[mt][nt][0]*alp, acc[mt][nt][1]*alp);
        *(float2*)(Cb + (r0+8)*ldc + c0) = make_float2(acc[mt][nt][2]*alp, acc[mt][nt][3]*alp);
      }
    }
  } else if (ep == 2){
    // resgate: out = R + gate*acc  (float out, combined row space, ldc=DM)
    float* Cb = (float*)C;
    #pragma unroll
    for (int mt = 0; mt < 4; mt++){
      int r0 = (int)(bm + wr + mt*16 + g);
      #pragma unroll
      for (int half_ = 0; half_ < 2; half_++){
        int r = r0 + half_*8;
        int isT = (r < MT);
        int bb = isT ? (r/LT) : ((r-MT)/NI);
        const float* gate = (isT ? epEt : epEi) + bb*E6 + go;
        const float* R = isT ? (epRt + (long long)r*DM) : (epRi + (long long)(r-MT)*DM);
        #pragma unroll
        for (int nt = 0; nt < 4; nt++){
          int c0 = (int)(bn + wc + nt*8 + 2*tg);
          float a0 = acc[mt][nt][half_*2+0], a1 = acc[mt][nt][half_*2+1];
          float2 o = make_float2(R[c0] + gate[c0]*a0, R[c0+1] + gate[c0+1]*a1);
          *(float2*)(Cb + (long long)r*ldc + c0) = o;
        }
      }
    }
  } else if (ep == 3){
    // bias + gelu -> half (ldc = FFD)
    __half* Cb = (__half*)C;
    #pragma unroll
    for (int mt = 0; mt < 4; mt++){
      int r0 = (int)(bm + wr + mt*16 + g);
      #pragma unroll
      for (int half_ = 0; half_ < 2; half_++){
        int r = r0 + half_*8;
        const float* bias = (r < MT) ? epBt : epBi;
        #pragma unroll
        for (int nt = 0; nt < 4; nt++){
          int c0 = (int)(bn + wc + nt*8 + 2*tg);
          float a0 = geluf(acc[mt][nt][half_*2+0] + bias[c0]);
          float a1 = geluf(acc[mt][nt][half_*2+1] + bias[c0+1]);
          *(__half2*)(Cb + (long long)r*ldc + c0) = __floats2half2_rn(a0, a1);
        }
      }
    }
  } else {
    // ep == 4: final: out = Cur + gate*(acc + bias)  (float out, ldc = DM)
    float* Cb = (float*)C;
    #pragma unroll
    for (int mt = 0; mt < 4; mt++){
      int r0 = (int)(bm + wr + mt*16 + g);
      #pragma unroll
      for (int half_ = 0; half_ < 2; half_++){
        int r = r0 + half_*8;
        int isT = (r < MT);
        int bb = isT ? (r/LT) : ((r-MT)/NI);
        const float* gate = (isT ? epEt : epEi) + bb*E6 + go;
        const float* bias = isT ? epBt : epBi;
        const float* Cur = epRt + (long long)r*DM;
        #pragma unroll
        for (int nt = 0; nt < 4; nt++){
          int c0 = (int)(bn + wc + nt*8 + 2*tg);
          float a0 = acc[mt][nt][half_*2+0] + bias[c0];
          float a1 = acc[mt][nt][half_*2+1] + bias[c0+1];
          float2 o = make_float2(Cur[c0] + gate[c0]*a0, Cur[c0+1] + gate[c0+1]*a1);
          *(float2*)(Cb + (long long)r*ldc + c0) = o;
        }
      }
    }
  }
}

// ================= fused flash attention =================
#define QT 64
#define KT 64
#define NKT (KVL/KT)
#define QSTR 136
#define VSTR 72
#define FL_Q   (QT*QSTR)
#define FL_STG (KT*QSTR + HDD*VSTR)
#define FL_DSMEM ((FL_Q + 2*FL_STG)*2)

__global__ __launch_bounds__(128, 2) void k_flash(
    const __half* __restrict__ Q, const __half* __restrict__ K,
    const __half* __restrict__ V,
    __half* __restrict__ ap, const float* __restrict__ eff)
{
  extern __shared__ __half sm[];
  __half* sq  = sm;
  __half* sst = sm + FL_Q;

  const int tid = threadIdx.x;
  const int lw  = tid & 31;
  const int w   = tid >> 5;
  const int g   = lw >> 2;
  const int tg  = lw & 3;
  const int qt  = blockIdx.x;
  const int z   = blockIdx.y;
  const int b   = z >> 2;
  const int h   = z & 3;
  const float alpha = (qt < LT/QT) ? SCALE_C : eff[b];

  const __half* Qg = Q + (long long)z*KVL*HDD + (long long)qt*QT*HDD;
  const __half* Kg = K + (long long)z*KVL*HDD;
  const __half* Vg = V + (long long)z*HDD*KVL;

  {
    int row = tid >> 1;
    int co  = (tid & 1) * 64;
    uint32_t dq = sptr(sq + row*QSTR + co);
    const __half* src = Qg + (long long)row*HDD + co;
    #pragma unroll
    for (int j = 0; j < 8; j++) CPA16(dq + j*16, src + j*8);
    asm volatile("cp.async.commit_group;");
  }

  auto load_tile = [&](int t, int st){
    __half* sk = sst + st*FL_STG;
    __half* sv = sk + KT*QSTR;
    int row = tid >> 1;
    int co  = (tid & 1) * 64;
    uint32_t dk = sptr(sk + row*QSTR + co);
    const __half* ks = Kg + (long long)(t*KT + row)*HDD + co;
    #pragma unroll
    for (int j = 0; j < 8; j++) CPA16(dk + j*16, ks + j*8);
    uint32_t dv = sptr(sv + tid*VSTR);
    const __half* vs = Vg + (long long)tid*KVL + t*KT;
    #pragma unroll
    for (int j = 0; j < 8; j++) CPA16(dv + j*16, vs + j*8);
    asm volatile("cp.async.commit_group;");
  };

  load_tile(0, 0);

  const int a_row = lw & 15;
  const int a_kh  = (lw >> 4) * 8;
  const int b_row = (lw & 7) + ((lw >> 4) & 1) * 8;
  const int b_kh  = ((lw >> 3) & 1) * 8;

  uint32_t aq[8][4];
  float O[16][4];
  #pragma unroll
  for (int i=0;i<16;i++){ O[i][0]=0.f; O[i][1]=0.f; O[i][2]=0.f; O[i][3]=0.f; }
  float m0 = -1e30f, m1 = -1e30f, l0 = 0.f, l1 = 0.f;
  const uint32_t sqb = sptr(sq);

  for (int t = 0; t < NKT; t++){
    int st = t & 1;
    if (t + 1 < NKT){
      load_tile(t+1, st^1);
      asm volatile("cp.async.wait_group 1;" ::: "memory");
    } else {
      asm volatile("cp.async.wait_group 0;" ::: "memory");
    }
    __syncthreads();

    if (t == 0){
      #pragma unroll
      for (int s = 0; s < 8; s++)
        LDMX4(aq[s][0], aq[s][1], aq[s][2], aq[s][3],
              sqb + (uint32_t)(((w*16 + a_row)*QSTR + s*16 + a_kh) * 2));
    }

    uint32_t skb = sptr(sst + st*FL_STG);
    uint32_t svb = skb + KT*QSTR*2;

    float sacc[8][4];
    #pragma unroll
    for (int i=0;i<8;i++){ sacc[i][0]=0.f; sacc[i][1]=0.f; sacc[i][2]=0.f; sacc[i][3]=0.f; }
    #pragma unroll
    for (int s = 0; s < 8; s++){
      uint32_t bk[8][2];
      #pragma unroll
      for (int p = 0; p < 4; p++)
        LDMX4(bk[p*2][0], bk[p*2][1], bk[p*2+1][0], bk[p*2+1][1],
              skb + (uint32_t)(((p*16 + b_row)*QSTR + s*16 + b_kh) * 2));
      #pragma unroll
      for (int nt = 0; nt < 8; nt++)
        HMMA(sacc[nt], aq[s], bk[nt]);
    }

    float mx0 = -1e30f, mx1 = -1e30f;
    #pragma unroll
    for (int nt = 0; nt < 8; nt++){
      sacc[nt][0] *= alpha; sacc[nt][1] *= alpha;
      sacc[nt][2] *= alpha; sacc[nt][3] *= alpha;
      mx0 = fmaxf(mx0, fmaxf(sacc[nt][0], sacc[nt][1]));
      mx1 = fmaxf(mx1, fmaxf(sacc[nt][2], sacc[nt][3]));
    }
    mx0 = fmaxf(mx0, __shfl_xor_sync(0xffffffffu, mx0, 1));
    mx0 = fmaxf(mx0, __shfl_xor_sync(0xffffffffu, mx0, 2));
    mx1 = fmaxf(mx1, __shfl_xor_sync(0xffffffffu, mx1, 1));
    mx1 = fmaxf(mx1, __shfl_xor_sync(0xffffffffu, mx1, 2));
    float mn0 = fmaxf(m0, mx0), mn1 = fmaxf(m1, mx1);
    float c0 = __expf(m0 - mn0), c1 = __expf(m1 - mn1);
    float sum0 = 0.f, sum1 = 0.f;
    #pragma unroll
    for (int nt = 0; nt < 8; nt++){
      sacc[nt][0] = __expf(sacc[nt][0] - mn0);
      sacc[nt][1] = __expf(sacc[nt][1] - mn0);
      sacc[nt][2] = __expf(sacc[nt][2] - mn1);
      sacc[nt][3] = __expf(sacc[nt][3] - mn1);
      sum0 += sacc[nt][0] + sacc[nt][1];
      sum1 += sacc[nt][2] + sacc[nt][3];
    }
    sum0 += __shfl_xor_sync(0xffffffffu, sum0, 1);
    sum0 += __shfl_xor_sync(0xffffffffu, sum0, 2);
    sum1 += __shfl_xor_sync(0xffffffffu, sum1, 1);
    sum1 += __shfl_xor_sync(0xffffffffu, sum1, 2);
    l0 = l0*c0 + sum0;  l1 = l1*c1 + sum1;
    m0 = mn0;  m1 = mn1;
    #pragma unroll
    for (int nt = 0; nt < 16; nt++){
      O[nt][0] *= c0; O[nt][1] *= c0;
      O[nt][2] *= c1; O[nt][3] *= c1;
    }

    uint32_t pf[4][4];
    #pragma unroll
    for (int j = 0; j < 4; j++){
      __half2 h0 = __floats2half2_rn(sacc[2*j][0],   sacc[2*j][1]);
      __half2 h1 = __floats2half2_rn(sacc[2*j][2],   sacc[2*j][3]);
      __half2 h2 = __floats2half2_rn(sacc[2*j+1][0], sacc[2*j+1][1]);
      __half2 h3 = __floats2half2_rn(sacc[2*j+1][2], sacc[2*j+1][3]);
      pf[j][0] = *(uint32_t*)&h0;  pf[j][1] = *(uint32_t*)&h1;
      pf[j][2] = *(uint32_t*)&h2;  pf[j][3] = *(uint32_t*)&h3;
    }

    #pragma unroll
    for (int s = 0; s < 4; s++){
      uint32_t bv[16][2];
      #pragma unroll
      for (int p = 0; p < 8; p++)
        LDMX4(bv[p*2][0], bv[p*2][1], bv[p*2+1][0], bv[p*2+1][1],
              svb + (uint32_t)(((p*16 + b_row)*VSTR + s*16 + b_kh) * 2));
      #pragma unroll
      for (int nt = 0; nt < 16; nt++)
        HMMA(O[nt], pf[s], bv[nt]);
    }
    __syncthreads();
  }

  float i0 = 1.f/l0, i1 = 1.f/l1;
  int q0 = qt*QT + w*16 + g;
  int q1 = q0 + 8;
  long long tok0 = (q0 < LT) ? (long long)(b*LT + q0) : (long long)(MT + b*NI + (q0 - LT));
  long long tok1 = (q1 < LT) ? (long long)(b*LT + q1) : (long long)(MT + b*NI + (q1 - LT));
  __half* o0 = ap + tok0*DM + h*HDD + 2*tg;
  __half* o1 = ap + tok1*DM + h*HDD + 2*tg;
  #pragma unroll
  for (int nt = 0; nt < 16; nt++){
    *(__half2*)(o0 + nt*8) = __floats2half2_rn(O[nt][0]*i0, O[nt][1]*i0);
    *(__half2*)(o1 + nt*8) = __floats2half2_rn(O[nt][2]*i1, O[nt][3]*i1);
  }
}

// ---------------- convert 8 weight matrices float -> half ----------------
__global__ void k_half8(const float* __restrict__ i0, __half* __restrict__ o0,
                        const float* __restrict__ i1, __half* __restrict__ o1,
                        const float* __restrict__ i2, __half* __restrict__ o2,
                        const float* __restrict__ i3, __half* __restrict__ o3,
                        const float* __restrict__ i4, __half* __restrict__ o4,
                        const float* __restrict__ i5, __half* __restrict__ o5,
                        const float* __restrict__ i6, __half* __restrict__ o6,
                        const float* __restrict__ i7, __half* __restrict__ o7)
{
  int idx = blockIdx.x*blockDim.x + threadIdx.x;
  const float4* in; __half2* out; int off;
  if      (idx <  196608){ in=(const float4*)i0; out=(__half2*)o0; off=0; }
  else if (idx <  393216){ in=(const float4*)i1; out=(__half2*)o1; off=196608; }
  else if (idx <  458752){ in=(const float4*)i2; out=(__half2*)o2; off=393216; }
  else if (idx <  524288){ in=(const float4*)i3; out=(__half2*)o3; off=458752; }
  else if (idx <  786432){ in=(const float4*)i4; out=(__half2*)o4; off=524288; }
  else if (idx < 1048576){ in=(const float4*)i5; out=(__half2*)o5; off=786432; }
  else if (idx < 1310720){ in=(const float4*)i6; out=(__half2*)o6; off=1048576; }
  else                   { in=(const float4*)i7; out=(__half2*)o7; off=1310720; }
  int j = idx - off;
  float4 v = in[j];
  out[j*2]   = __floats2half2_rn(v.x, v.y);
  out[j*2+1] = __floats2half2_rn(v.z, v.w);
}

// ---------------- adaln embedding (both streams in one launch) ----------------
__global__ void k_emb2(const float* __restrict__ vec,
                       const float* __restrict__ Wi, const float* __restrict__ bi,
                       const float* __restrict__ Wt, const float* __restrict__ bt,
                       float* __restrict__ ei, float* __restrict__ et)
{
  int b = blockIdx.y;
  const float* W  = blockIdx.z ? Wt : Wi;
  const float* bs = blockIdx.z ? bt : bi;
  float* e        = blockIdx.z ? et : ei;
  __shared__ float s[DM];
  for (int i = threadIdx.x; i < DM; i += blockDim.x){
    float v = vec[b*DM + i];
    s[i] = v / (1.f + expf(-v));
  }
  __syncthreads();
  int n = blockIdx.x*blockDim.x + threadIdx.x;
  const float* wr = W + (long long)n*DM;
  float acc = 0.f;
  #pragma unroll 8
  for (int k = 0; k < DM; k++) acc += s[k]*wr[k];
  e[b*E6 + n] = acc + bs[n];
}

__global__ void k_eff(const float* __restrict__ t, float* __restrict__ eff){
  int b = threadIdx.x;
  if (b < NB){
    float m = 0.25f*(t[b*NHD+0]+t[b*NHD+1]+t[b*NHD+2]+t[b*NHD+3]);
    eff[b] = SCALE_C / fmaxf(m, 0.1f);
  }
}

__global__ void k_mod(const float* __restrict__ sp, const float* __restrict__ mw,
                      const float* __restrict__ mb, float* __restrict__ mod)
{
  int idx = blockIdx.x*blockDim.x + threadIdx.x;
  if (idx >= NB*NHD*NI) return;
  int n = idx & (NI-1);
  int h = (idx >> 11) & (NHD-1);
  int b = idx >> 13;
  int y = n >> 5;
  int x = n & 31;
  float fy = (y + 0.5f)*0.125f - 0.5f;
  float fx = (x + 0.5f)*0.25f  - 0.5f;
  int y0 = (int)floorf(fy); float wy = fy - (float)y0;
  int x0 = (int)floorf(fx); float wx = fx - (float)x0;
  int y0c = min(max(y0,0),7), y1c = min(max(y0+1,0),7);
  int x0c = min(max(x0,0),7), x1c = min(max(x0+1,0),7);
  const float* p = sp + b*64;
  float v = (1.f-wy)*((1.f-wx)*p[y0c*8+x0c] + wx*p[y0c*8+x1c])
          +      wy *((1.f-wx)*p[y1c*8+x0c] + wx*p[y1c*8+x1c]);
  v = v*mw[h] + mb[h];
  v = fminf(fmaxf(v, -2.f), 2.f);
  mod[idx] = expf(v);
}

// ---------------- combined rms-norm + adaln modulate -> half ----------------
__global__ __launch_bounds__(128) void k_rmsmod(
    const float* __restrict__ xt, const float* __restrict__ xi,
    const float* __restrict__ wt, const float* __restrict__ wi,
    const float* __restrict__ et, const float* __restrict__ ei,
    int shift_off, int scale_off, __half* __restrict__ out)
{
  int row = blockIdx.x;
  const float* x; const float* w; const float* eb;
  if (row < MT){
    x = xt + (long long)row*DM; w = wt; eb = et + (row/LT)*E6;
  } else {
    int rr = row - MT;
    x = xi + (long long)rr*DM; w = wi; eb = ei + (rr/NI)*E6;
  }
  float4 xv = ((const float4*)x)[threadIdx.x];
  float ss = xv.x*xv.x + xv.y*xv.y + xv.z*xv.z + xv.w*xv.w;
  ss = warpSum(ss);
  __shared__ float red[4];
  int lane = threadIdx.x & 31, wid = threadIdx.x >> 5;
  if (lane==0) red[wid]=ss;
  __syncthreads();
  float tot = red[0]+red[1]+red[2]+red[3];
  float inv = rsqrtf(tot*(1.f/DM) + 1e-6f);
  int c = threadIdx.x*4;
  float ox = xv.x*inv*w[c+0]*(1.f+eb[scale_off+c+0]) + eb[shift_off+c+0];
  float oy = xv.y*inv*w[c+1]*(1.f+eb[scale_off+c+1]) + eb[shift_off+c+1];
  float oz = xv.z*inv*w[c+2]*(1.f+eb[scale_off+c+2]) + eb[shift_off+c+2];
  float ow = xv.w*inv*w[c+3]*(1.f+eb[scale_off+c+3]) + eb[shift_off+c+3];
  __half2* op = (__half2*)(out + (long long)row*DM);
  op[threadIdx.x*2]   = __floats2half2_rn(ox, oy);
  op[threadIdx.x*2+1] = __floats2half2_rn(oz, ow);
}

// ---------------- scatter img qkv (half) ----------------
__global__ void k_scatter_img(const __half* __restrict__ qkv, const float* __restrict__ rope,
                              const float* __restrict__ mod,
                              __half* __restrict__ Q, __half* __restrict__ K,
                              __half* __restrict__ VT)
{
  int idx = blockIdx.x*blockDim.x + threadIdx.x;
  int d2 = idx & 63;
  int r  = idx >> 6;
  int n  = r & (NI-1);
  int bh = r >> 11;
  int h  = bh & (NHD-1);
  int b  = bh >> 2;
  const __half* base = qkv + ((long long)(MT + b*NI + n))*(3*NHD*HDD) + h*HDD + 2*d2;
  float2 q = __half22float2(*(const __half2*)(base));
  float2 k = __half22float2(*(const __half2*)(base + NHD*HDD));
  float2 v = __half22float2(*(const __half2*)(base + 2*NHD*HDD));
  float c = rope[n*HDD + 2*d2];
  float s = rope[n*HDD + 2*d2 + 1];
  float m = mod[r];
  long long kv = (long long)bh*KVL + (LT + n);
  *(__half2*)(Q + kv*HDD + 2*d2) = __floats2half2_rn((q.x*c - q.y*s)*m, (q.y*c + q.x*s)*m);
  *(__half2*)(K + kv*HDD + 2*d2) = __floats2half2_rn((k.x*c - k.y*s)*m, (k.y*c + k.x*s)*m);
  VT[((long long)bh*HDD + 2*d2  )*KVL + (LT+n)] = __float2half_rn(v.x);
  VT[((long long)bh*HDD + 2*d2+1)*KVL + (LT+n)] = __float2half_rn(v.y);
}

// ---------------- scatter txt qkv (half) ----------------
__global__ void k_scatter_txt(const __half* __restrict__ qkv,
                              __half* __restrict__ Q, __half* __restrict__ K,
                              __half* __restrict__ VT)
{
  int idx = blockIdx.x*blockDim.x + threadIdx.x;
  int d2 = idx & 63;
  int r  = idx >> 6;
  int l  = r & (LT-1);
  int bh = r >> 9;
  int h  = bh & (NHD-1);
  int b  = bh >> 2;
  const __half* base = qkv + ((long long)(b*LT + l))*(3*NHD*HDD) + h*HDD + 2*d2;
  __half2 q = *(const __half2*)(base);
  __half2 k = *(const __half2*)(base + NHD*HDD);
  float2 v = __half22float2(*(const __half2*)(base + 2*NHD*HDD));
  long long kv = (long long)bh*KVL + l;
  *(__half2*)(Q + kv*HDD + 2*d2) = q;
  *(__half2*)(K + kv*HDD + 2*d2) = k;
  VT[((long long)bh*HDD + 2*d2  )*KVL + l] = __float2half_rn(v.x);
  VT[((long long)bh*HDD + 2*d2+1)*KVL + l] = __float2half_rn(v.y);
}

// ---------------- launch ----------------
#define GETSYMF(var, sym) float* var; cudaGetSymbolAddress((void**)&var, sym)
#define GETSYMH(var, sym) __half* var; cudaGetSymbolAddress((void**)&var, sym)

extern "C" void kernel_launch(void* const* d_in, const int* in_sizes, int n_in,
                              void* d_out, int out_size)
{
  const float* txt          = (const float*)d_in[0];
  const float* img          = (const float*)d_in[1];
  const float* vec          = (const float*)d_in[2];
  const float* rope         = (const float*)d_in[3];
  const float* sol_t        = (const float*)d_in[4];
  const float* sol_s        = (const float*)d_in[5];
  const float* img_adaln_w  = (const float*)d_in[6];
  const float* img_adaln_b  = (const float*)d_in[7];
  const float* img_adaln_nw = (const float*)d_in[8];
  const float* txt_adaln_w  = (const float*)d_in[9];
  const float* txt_adaln_b  = (const float*)d_in[10];
  const float* txt_adaln_nw = (const float*)d_in[11];
  const float* txt_qkv_w    = (const float*)d_in[12];
  const float* img_qkv_w    = (const float*)d_in[13];
  const float* txt_out_w    = (const float*)d_in[14];
  const float* img_out_w    = (const float*)d_in[15];
  const float* sol_mod_w    = (const float*)d_in[16];
  const float* sol_mod_b    = (const float*)d_in[17];
  const float* img_norm2_w  = (const float*)d_in[18];
  const float* txt_norm2_w  = (const float*)d_in[19];
  const float* img_fc1_w    = (const float*)d_in[20];
  const float* img_fc1_b    = (const float*)d_in[21];
  const float* img_fc2_w    = (const float*)d_in[22];
  const float* img_fc2_b    = (const float*)d_in[23];
  const float* txt_fc1_w    = (const float*)d_in[24];
  const float* txt_fc1_b    = (const float*)d_in[25];
  const float* txt_fc2_w    = (const float*)d_in[26];
  const float* txt_fc2_b    = (const float*)d_in[27];
  float* out = (float*)d_out;

  GETSYMF(e_img, d_e_img);  GETSYMF(e_txt, d_e_txt);
  GETSYMF(eff, d_eff);      GETSYMF(mod, d_mod);
  GETSYMH(nrm, d_nrm);      GETSYMH(qkv, d_qkv);
  GETSYMH(Qc, d_Qc);        GETSYMH(Kc, d_Kc);
  GETSYMH(VT, d_VT);
  GETSYMH(ap, d_ap);        GETSYMH(hh, d_h);
  GETSYMF(cc, d_c);
  GETSYMH(wq_t, d_wq_t);    GETSYMH(wq_i, d_wq_i);
  GETSYMH(wo_t, d_wo_t);    GETSYMH(wo_i, d_wo_i);
  GETSYMH(w1_t, d_w1_t);    GETSYMH(w1_i, d_w1_i);
  GETSYMH(w2_t, d_w2_t);    GETSYMH(w2_i, d_w2_i);

  cudaFuncSetAttribute(tgemm,   cudaFuncAttributeMaxDynamicSharedMemorySize, TG_DSMEM);
  cudaFuncSetAttribute(k_flash, cudaFuncAttributeMaxDynamicSharedMemorySize, FL_DSMEM);

  // 0. weights -> half
  k_half8<<<1572864/256, 256>>>(txt_qkv_w, wq_t, img_qkv_w, wq_i,
                                txt_out_w, wo_t, img_out_w, wo_i,
                                txt_fc1_w, w1_t, img_fc1_w, w1_i,
                                txt_fc2_w, w2_t, img_fc2_w, w2_i);
  // 1. adaln embeddings (one launch) + eff + mod
  k_emb2<<<dim3(E6/256, NB, 2), 256>>>(vec, img_adaln_w, img_adaln_b,
                                       txt_adaln_w, txt_adaln_b, e_img, e_txt);
  k_eff<<<1, 32>>>(sol_t, eff);
  k_mod<<<(NB*NHD*NI)/256, 256>>>(sol_s, sol_mod_w, sol_mod_b, mod);
  // 2. norm1 combined -> half
  k_rmsmod<<<MALL, 128>>>(txt, img, txt_adaln_nw, img_adaln_nw, e_txt, e_img, 0, 512, nrm);
  // 3. QKV combined -> half (ep1)
  tgemm<<<dim3(12, MALL/128, 1), 256, TG_DSMEM>>>(nrm, wq_t, wq_i, MT,
      qkv, 1536, DM, 1536, 0, 0,
      BIGR, 1, 0, 0, 0, 0, 1.f, eff, 1, BIGR,
      1, nullptr, nullptr, nullptr, nullptr, nullptr, nullptr, 0);
  // 4. scatter -> Qc, Kc, V^T
  k_scatter_txt<<<(NB*NHD*LT*64)/256, 256>>>(qkv, Qc, Kc, VT);
  k_scatter_img<<<(NB*NHD*NI*64)/256, 256>>>(qkv, rope, mod, Qc, Kc, VT);
  // 5. fused flash attention -> packed half ap
  k_flash<<<dim3(KVL/QT, NB*NHD), 128, FL_DSMEM>>>(Qc, Kc, VT, ap, eff);
  // 6. output projection + residual gate fused (ep2) -> float cc
  tgemm<<<dim3(4, MALL/128, 1), 256, TG_DSMEM>>>(ap, wo_t, wo_i, MT,
      cc, DM, DM, DM, 0, 0,
      BIGR, 1, 0, 0, 0, 0, 1.f, eff, 1, BIGR,
      2, txt, img, e_txt, e_img, nullptr, nullptr, 1024);
  // 7. norm2 combined -> half
  k_rmsmod<<<MALL, 128>>>(cc, cc + (long long)MT*DM, txt_norm2_w, img_norm2_w,
                          e_txt, e_img, 1536, 2048, nrm);
  // 8. fc1 + bias + gelu fused (ep3) -> half h
  tgemm<<<dim3(16, MALL/128, 1), 256, TG_DSMEM>>>(nrm, w1_t, w1_i, MT,
      hh, FFD, DM, FFD, 0, 0,
      BIGR, 1, 0, 0, 0, 0, 1.f, eff, 1, BIGR,
      3, nullptr, nullptr, nullptr, nullptr, txt_fc1_b, img_fc1_b, 0);
  // 9. fc2 + bias + gate + residual fused (ep4) -> d_out directly
  tgemm<<<dim3(4, MALL/128, 1), 256, TG_DSMEM>>>(hh, w2_t, w2_i, MT,
      out, DM, FFD, DM, 0, 0,
      BIGR, 1, 0, 0, 0, 0, 1.f, eff, 1, BIGR,
      4, cc, nullptr, e_txt, e_img, txt_fc2_b, img_fc2_b, 2560);
}

// round 11
// speedup vs baseline: 2.4968x; 1.1001x over previous
#include <cuda_runtime.h>
#include <cuda_fp16.h>
#include <math.h>
#include <stdint.h>

// ---------------- problem dims (fixed) ----------------
#define NB   2
#define LT   512
#define NI   2048
#define DM   512
#define NHD  4
#define HDD  128
#define FFD  2048
#define KVL  2560
#define E6   3072
#define MT   (NB*LT)
#define MI   (NB*NI)
#define MALL (MT+MI)
#define SCALE_C 0.08838834764831845f
#define BIGR (1<<30)

// ---------------- scratch ----------------
__device__ __align__(256) float  d_e_img[NB*E6];
__device__ __align__(256) float  d_e_txt[NB*E6];
__device__ __align__(256) float  d_eff[NB];
__device__ __align__(256) float  d_mod[NB*NHD*NI];
__device__ __align__(256) __half d_nrm[MALL*DM];
__device__ __align__(256) __half d_Qc[NB*NHD*KVL*HDD];
__device__ __align__(256) __half d_Kc[NB*NHD*KVL*HDD];
__device__ __align__(256) __half d_VT[NB*NHD*HDD*KVL];
__device__ __align__(256) __half d_ap[MALL*DM];
__device__ __align__(256) __half d_h[MALL*FFD];
__device__ __align__(256) float  d_c[MALL*DM];
// half weights
__device__ __align__(256) __half d_wq_t[1536*DM];
__device__ __align__(256) __half d_wq_i[1536*DM];
__device__ __align__(256) __half d_wo_t[DM*DM];
__device__ __align__(256) __half d_wo_i[DM*DM];
__device__ __align__(256) __half d_w1_t[FFD*DM];
__device__ __align__(256) __half d_w1_i[FFD*DM];
__device__ __align__(256) __half d_w2_t[DM*FFD];
__device__ __align__(256) __half d_w2_i[DM*FFD];

// ---------------- helpers ----------------
__device__ __forceinline__ float warpSum(float v){
  #pragma unroll
  for (int o=16;o>0;o>>=1) v += __shfl_xor_sync(0xffffffffu, v, o);
  return v;
}
__device__ __forceinline__ uint32_t sptr(const void* p){
  uint32_t r;
  asm("{ .reg .u64 t; cvta.to.shared.u64 t, %1; cvt.u32.u64 %0, t; }" : "=r"(r) : "l"(p));
  return r;
}
__device__ __forceinline__ float geluf(float x){
  float t = tanhf(0.7978845608028654f*(x + 0.044715f*x*x*x));
  return 0.5f*x*(1.f+t);
}
#define HMMA(acc, a, b) \
  asm volatile( \
    "mma.sync.aligned.m16n8k16.row.col.f32.f16.f16.f32 " \
    "{%0,%1,%2,%3}, {%4,%5,%6,%7}, {%8,%9}, {%0,%1,%2,%3};" \
    : "+f"((acc)[0]), "+f"((acc)[1]), "+f"((acc)[2]), "+f"((acc)[3]) \
    : "r"((a)[0]), "r"((a)[1]), "r"((a)[2]), "r"((a)[3]), \
      "r"((b)[0]), "r"((b)[1]))
#define LDMX4(r0,r1,r2,r3, addr) \
  asm volatile("ldmatrix.sync.aligned.m8n8.x4.shared.b16 {%0,%1,%2,%3}, [%4];" \
    : "=r"(r0), "=r"(r1), "=r"(r2), "=r"(r3) : "r"(addr))
#define CPA16(dst, src) \
  asm volatile("cp.async.cg.shared.global [%0], [%1], 16;" :: "r"(dst), "l"(src))

// ================= fp16 mma.sync batched GEMM, K-chunk 64, fused epilogues =================
// ep: 0=float*alpha, 1=half*alpha, 2=resgate float, 3=bias+gelu half,
//     4=final float, 5=qkv scatter (rope+mod -> Qc/Kc/VT)
#define TSH 72
#define STAGE_H (128*TSH)
#define STAGE_BYTES (STAGE_H*2)     // 18432
#define TG_DSMEM (4*STAGE_H*2)      // 73728

__global__ __launch_bounds__(256) void tgemm(
    const __half* __restrict__ A, const __half* __restrict__ B1,
    const __half* __restrict__ B2, int msplit,
    void* __restrict__ C, int N, int K, int ldc,
    long long sA, long long sB,
    int rsplit, int zdiv, long long sCt, long long sCi, long long sCh, long long cbase,
    float alpha, const float* __restrict__ alphas, int adiv, int arsplit,
    int ep,
    const float* __restrict__ epRt, const float* __restrict__ epRi,
    const float* __restrict__ epEt, const float* __restrict__ epEi,
    const float* __restrict__ epBt, const float* __restrict__ epBi, int go,
    const float* __restrict__ ropep, const float* __restrict__ modp,
    __half* __restrict__ Qp, __half* __restrict__ Kp, __half* __restrict__ Vp)
{
  extern __shared__ __half smh[];
  __half* As = smh;
  __half* Bs = smh + 2*STAGE_H;

  const int tid = threadIdx.x;
  const int z   = blockIdx.z;
  const long long bm = (long long)blockIdx.y * 128;
  const long long bn = (long long)blockIdx.x * 128;

  const __half* Ab = A + z*sA + bm*K;
  const __half* Bsel = (bm < msplit) ? B1 : B2;
  const __half* Bb = Bsel + z*sB + bn*K;

  float alp = ((int)bm < arsplit) ? alpha : alphas[z/adiv];
  long long zoff = ((int)bm < rsplit)
      ? (long long)(z/zdiv)*sCt + (long long)(z%zdiv)*sCh
      : cbase + (long long)(z/zdiv)*sCi + (long long)(z%zdiv)*sCh;

  const int lw  = tid & 31;
  const int w   = tid >> 5;
  const int wr  = (w >> 2) * 64;
  const int wc  = (w & 3) * 32;
  const int g   = lw >> 2;
  const int tg  = lw & 3;

  const int lrow = tid >> 1;
  const int lsel = (tid & 1) * 32;   // halves

  const int a_row = lw & 15;
  const int a_kh  = (lw >> 4) * 8;
  uint32_t aoff[4];
  #pragma unroll
  for (int mt = 0; mt < 4; mt++)
    aoff[mt] = (uint32_t)(((wr + mt*16 + a_row)*TSH + a_kh) * 2);
  const int b_row = (lw & 7) + ((lw >> 4) & 1) * 8;
  const int b_kh  = ((lw >> 3) & 1) * 8;
  uint32_t boff[2];
  #pragma unroll
  for (int n2 = 0; n2 < 2; n2++)
    boff[n2] = (uint32_t)(((wc + n2*16 + b_row)*TSH + b_kh) * 2);

  const uint32_t Abase = sptr(As);
  const uint32_t Bbase = sptr(Bs);

  float acc[4][4][4];
  #pragma unroll
  for (int i=0;i<4;i++)
    #pragma unroll
    for (int j=0;j<4;j++)
      #pragma unroll
      for (int q=0;q<4;q++) acc[i][j][q] = 0.f;

  const int nch = K >> 6;

  auto load_chunk = [&](int c, int st){
    const __half* Ag = Ab + (long long)lrow*K + c*64 + lsel;
    const __half* Bg = Bb + (long long)lrow*K + c*64 + lsel;
    uint32_t da = sptr(As + st*STAGE_H + lrow*TSH + lsel);
    uint32_t db = sptr(Bs + st*STAGE_H + lrow*TSH + lsel);
    #pragma unroll
    for (int j = 0; j < 4; j++){
      CPA16(da + j*16, Ag + j*8);
      CPA16(db + j*16, Bg + j*8);
    }
    asm volatile("cp.async.commit_group;");
  };

  load_chunk(0, 0);

  for (int i = 0; i < nch; i++){
    int st = i & 1;
    if (i + 1 < nch){
      load_chunk(i+1, st^1);
      asm volatile("cp.async.wait_group 1;" ::: "memory");
    } else {
      asm volatile("cp.async.wait_group 0;" ::: "memory");
    }
    __syncthreads();

    uint32_t sa = Abase + st*STAGE_BYTES;
    uint32_t sb = Bbase + st*STAGE_BYTES;

    #pragma unroll
    for (int ks = 0; ks < 4; ks++){
      uint32_t koff = ks*32;   // 16 halves
      uint32_t af[4][4];
      #pragma unroll
      for (int mt = 0; mt < 4; mt++)
        LDMX4(af[mt][0], af[mt][1], af[mt][2], af[mt][3], sa + aoff[mt] + koff);
      uint32_t bf[4][2];
      #pragma unroll
      for (int n2 = 0; n2 < 2; n2++)
        LDMX4(bf[n2*2][0], bf[n2*2][1], bf[n2*2+1][0], bf[n2*2+1][1], sb + boff[n2] + koff);
      #pragma unroll
      for (int mt = 0; mt < 4; mt++)
        #pragma unroll
        for (int nt = 0; nt < 4; nt++)
          HMMA(acc[mt][nt], af[mt], bf[nt]);
    }
    __syncthreads();
  }

  // -------- epilogue --------
  if (ep == 1){
    __half* Cb = (__half*)C + zoff;
    #pragma unroll
    for (int mt = 0; mt < 4; mt++){
      long long r0 = bm + wr + mt*16 + g;
      #pragma unroll
      for (int nt = 0; nt < 4; nt++){
        long long c0 = bn + wc + nt*8 + 2*tg;
        *(__half2*)(Cb + r0*ldc + c0)     = __floats2half2_rn(acc[mt][nt][0]*alp, acc[mt][nt][1]*alp);
        *(__half2*)(Cb + (r0+8)*ldc + c0) = __floats2half2_rn(acc[mt][nt][2]*alp, acc[mt][nt][3]*alp);
      }
    }
  } else if (ep == 0){
    float* Cb = (float*)C + zoff;
    #pragma unroll
    for (int mt = 0; mt < 4; mt++){
      long long r0 = bm + wr + mt*16 + g;
      #pragma unroll
      for (int nt = 0; nt < 4; nt++){
        long long c0 = bn + wc + nt*8 + 2*tg;
        *(float2*)(Cb + r0*ldc + c0)     = make_float2(acc[mt][nt][0]*alp, acc[mt][nt][1]*alp);
        *(float2*)(Cb + (r0+8)*ldc + c0) = make_float2(acc[mt][nt][2]*alp, acc[mt][nt][3]*alp);
      }
    }
  } else if (ep == 2){
    float* Cb = (float*)C;
    #pragma unroll
    for (int mt = 0; mt < 4; mt++){
      int r0 = (int)(bm + wr + mt*16 + g);
      #pragma unroll
      for (int half_ = 0; half_ < 2; half_++){
        int r = r0 + half_*8;
        int isT = (r < MT);
        int bb = isT ? (r/LT) : ((r-MT)/NI);
        const float* gate = (isT ? epEt : epEi) + bb*E6 + go;
        const float* R = isT ? (epRt + (long long)r*DM) : (epRi + (long long)(r-MT)*DM);
        #pragma unroll
        for (int nt = 0; nt < 4; nt++){
          int c0 = (int)(bn + wc + nt*8 + 2*tg);
          float a0 = acc[mt][nt][half_*2+0], a1 = acc[mt][nt][half_*2+1];
          float2 o = make_float2(R[c0] + gate[c0]*a0, R[c0+1] + gate[c0+1]*a1);
          *(float2*)(Cb + (long long)r*ldc + c0) = o;
        }
      }
    }
  } else if (ep == 3){
    __half* Cb = (__half*)C;
    #pragma unroll
    for (int mt = 0; mt < 4; mt++){
      int r0 = (int)(bm + wr + mt*16 + g);
      #pragma unroll
      for (int half_ = 0; half_ < 2; half_++){
        int r = r0 + half_*8;
        const float* bias = (r < MT) ? epBt : epBi;
        #pragma unroll
        for (int nt = 0; nt < 4; nt++){
          int c0 = (int)(bn + wc + nt*8 + 2*tg);
          float a0 = geluf(acc[mt][nt][half_*2+0] + bias[c0]);
          float a1 = geluf(acc[mt][nt][half_*2+1] + bias[c0+1]);
          *(__half2*)(Cb + (long long)r*ldc + c0) = __floats2half2_rn(a0, a1);
        }
      }
    }
  } else if (ep == 4){
    float* Cb = (float*)C;
    #pragma unroll
    for (int mt = 0; mt < 4; mt++){
      int r0 = (int)(bm + wr + mt*16 + g);
      #pragma unroll
      for (int half_ = 0; half_ < 2; half_++){
        int r = r0 + half_*8;
        int isT = (r < MT);
        int bb = isT ? (r/LT) : ((r-MT)/NI);
        const float* gate = (isT ? epEt : epEi) + bb*E6 + go;
        const float* bias = isT ? epBt : epBi;
        const float* Cur = epRt + (long long)r*DM;
        #pragma unroll
        for (int nt = 0; nt < 4; nt++){
          int c0 = (int)(bn + wc + nt*8 + 2*tg);
          float a0 = acc[mt][nt][half_*2+0] + bias[c0];
          float a1 = acc[mt][nt][half_*2+1] + bias[c0+1];
          float2 o = make_float2(Cur[c0] + gate[c0]*a0, Cur[c0+1] + gate[c0+1]*a1);
          *(float2*)(Cb + (long long)r*ldc + c0) = o;
        }
      }
    }
  } else {
    // ep == 5: QKV scatter: bn tile selects (q/k/v, head); rows are combined tokens.
    int typ = (int)(bn >> 9);            // 0=q, 1=k, 2=v
    int hh2 = ((int)bn >> 7) & 3;        // head
    #pragma unroll
    for (int mt = 0; mt < 4; mt++){
      #pragma unroll
      for (int half_ = 0; half_ < 2; half_++){
        int r = (int)bm + wr + mt*16 + g + half_*8;
        int isT = (r < MT);
        int bidx, kv, n = 0;
        if (isT){ bidx = r >> 9; kv = r & (LT-1); }
        else { int rr = r - MT; bidx = rr >> 11; n = rr & (NI-1); kv = LT + n; }
        long long zz = (long long)(bidx*NHD + hh2);
        if (typ == 2){
          #pragma unroll
          for (int nt = 0; nt < 4; nt++){
            int cl = wc + nt*8 + 2*tg;
            Vp[(zz*HDD + cl  )*KVL + kv] = __float2half_rn(acc[mt][nt][half_*2+0]);
            Vp[(zz*HDD + cl+1)*KVL + kv] = __float2half_rn(acc[mt][nt][half_*2+1]);
          }
        } else {
          __half* dst = (typ == 0 ? Qp : Kp) + (zz*KVL + kv)*HDD;
          if (isT){
            #pragma unroll
            for (int nt = 0; nt < 4; nt++){
              int cl = wc + nt*8 + 2*tg;
              *(__half2*)(dst + cl) = __floats2half2_rn(acc[mt][nt][half_*2+0], acc[mt][nt][half_*2+1]);
            }
          } else {
            float m = modp[zz*NI + n];
            #pragma unroll
            for (int nt = 0; nt < 4; nt++){
              int cl = wc + nt*8 + 2*tg;
              float c = ropep[n*HDD + cl];
              float s = ropep[n*HDD + cl + 1];
              float a0 = acc[mt][nt][half_*2+0];
              float a1 = acc[mt][nt][half_*2+1];
              *(__half2*)(dst + cl) = __floats2half2_rn((a0*c - a1*s)*m, (a1*c + a0*s)*m);
            }
          }
        }
      }
    }
  }
}

// ================= fused flash attention =================
#define QT 64
#define KT 64
#define NKT (KVL/KT)
#define QSTR 136
#define VSTR 72
#define FL_Q   (QT*QSTR)
#define FL_STG (KT*QSTR + HDD*VSTR)
#define FL_DSMEM ((FL_Q + 2*FL_STG)*2)

__global__ __launch_bounds__(128, 2) void k_flash(
    const __half* __restrict__ Q, const __half* __restrict__ K,
    const __half* __restrict__ V,
    __half* __restrict__ ap, const float* __restrict__ eff)
{
  extern __shared__ __half sm[];
  __half* sq  = sm;
  __half* sst = sm + FL_Q;

  const int tid = threadIdx.x;
  const int lw  = tid & 31;
  const int w   = tid >> 5;
  const int g   = lw >> 2;
  const int tg  = lw & 3;
  const int qt  = blockIdx.x;
  const int z   = blockIdx.y;
  const int b   = z >> 2;
  const int h   = z & 3;
  const float alpha = (qt < LT/QT) ? SCALE_C : eff[b];

  const __half* Qg = Q + (long long)z*KVL*HDD + (long long)qt*QT*HDD;
  const __half* Kg = K + (long long)z*KVL*HDD;
  const __half* Vg = V + (long long)z*HDD*KVL;

  {
    int row = tid >> 1;
    int co  = (tid & 1) * 64;
    uint32_t dq = sptr(sq + row*QSTR + co);
    const __half* src = Qg + (long long)row*HDD + co;
    #pragma unroll
    for (int j = 0; j < 8; j++) CPA16(dq + j*16, src + j*8);
    asm volatile("cp.async.commit_group;");
  }

  auto load_tile = [&](int t, int st){
    __half* sk = sst + st*FL_STG;
    __half* sv = sk + KT*QSTR;
    int row = tid >> 1;
    int co  = (tid & 1) * 64;
    uint32_t dk = sptr(sk + row*QSTR + co);
    const __half* ks = Kg + (long long)(t*KT + row)*HDD + co;
    #pragma unroll
    for (int j = 0; j < 8; j++) CPA16(dk + j*16, ks + j*8);
    uint32_t dv = sptr(sv + tid*VSTR);
    const __half* vs = Vg + (long long)tid*KVL + t*KT;
    #pragma unroll
    for (int j = 0; j < 8; j++) CPA16(dv + j*16, vs + j*8);
    asm volatile("cp.async.commit_group;");
  };

  load_tile(0, 0);

  const int a_row = lw & 15;
  const int a_kh  = (lw >> 4) * 8;
  const int b_row = (lw & 7) + ((lw >> 4) & 1) * 8;
  const int b_kh  = ((lw >> 3) & 1) * 8;

  uint32_t aq[8][4];
  float O[16][4];
  #pragma unroll
  for (int i=0;i<16;i++){ O[i][0]=0.f; O[i][1]=0.f; O[i][2]=0.f; O[i][3]=0.f; }
  float m0 = -1e30f, m1 = -1e30f, l0 = 0.f, l1 = 0.f;
  const uint32_t sqb = sptr(sq);

  for (int t = 0; t < NKT; t++){
    int st = t & 1;
    if (t + 1 < NKT){
      load_tile(t+1, st^1);
      asm volatile("cp.async.wait_group 1;" ::: "memory");
    } else {
      asm volatile("cp.async.wait_group 0;" ::: "memory");
    }
    __syncthreads();

    if (t == 0){
      #pragma unroll
      for (int s = 0; s < 8; s++)
        LDMX4(aq[s][0], aq[s][1], aq[s][2], aq[s][3],
              sqb + (uint32_t)(((w*16 + a_row)*QSTR + s*16 + a_kh) * 2));
    }

    uint32_t skb = sptr(sst + st*FL_STG);
    uint32_t svb = skb + KT*QSTR*2;

    float sacc[8][4];
    #pragma unroll
    for (int i=0;i<8;i++){ sacc[i][0]=0.f; sacc[i][1]=0.f; sacc[i][2]=0.f; sacc[i][3]=0.f; }
    #pragma unroll
    for (int s = 0; s < 8; s++){
      uint32_t bk[8][2];
      #pragma unroll
      for (int p = 0; p < 4; p++)
        LDMX4(bk[p*2][0], bk[p*2][1], bk[p*2+1][0], bk[p*2+1][1],
              skb + (uint32_t)(((p*16 + b_row)*QSTR + s*16 + b_kh) * 2));
      #pragma unroll
      for (int nt = 0; nt < 8; nt++)
        HMMA(sacc[nt], aq[s], bk[nt]);
    }

    float mx0 = -1e30f, mx1 = -1e30f;
    #pragma unroll
    for (int nt = 0; nt < 8; nt++){
      sacc[nt][0] *= alpha; sacc[nt][1] *= alpha;
      sacc[nt][2] *= alpha; sacc[nt][3] *= alpha;
      mx0 = fmaxf(mx0, fmaxf(sacc[nt][0], sacc[nt][1]));
      mx1 = fmaxf(mx1, fmaxf(sacc[nt][2], sacc[nt][3]));
    }
    mx0 = fmaxf(mx0, __shfl_xor_sync(0xffffffffu, mx0, 1));
    mx0 = fmaxf(mx0, __shfl_xor_sync(0xffffffffu, mx0, 2));
    mx1 = fmaxf(mx1, __shfl_xor_sync(0xffffffffu, mx1, 1));
    mx1 = fmaxf(mx1, __shfl_xor_sync(0xffffffffu, mx1, 2));
    float mn0 = fmaxf(m0, mx0), mn1 = fmaxf(m1, mx1);
    float c0 = __expf(m0 - mn0), c1 = __expf(m1 - mn1);
    float sum0 = 0.f, sum1 = 0.f;
    #pragma unroll
    for (int nt = 0; nt < 8; nt++){
      sacc[nt][0] = __expf(sacc[nt][0] - mn0);
      sacc[nt][1] = __expf(sacc[nt][1] - mn0);
      sacc[nt][2] = __expf(sacc[nt][2] - mn1);
      sacc[nt][3] = __expf(sacc[nt][3] - mn1);
      sum0 += sacc[nt][0] + sacc[nt][1];
      sum1 += sacc[nt][2] + sacc[nt][3];
    }
    sum0 += __shfl_xor_sync(0xffffffffu, sum0, 1);
    sum0 += __shfl_xor_sync(0xffffffffu, sum0, 2);
    sum1 += __shfl_xor_sync(0xffffffffu, sum1, 1);
    sum1 += __shfl_xor_sync(0xffffffffu, sum1, 2);
    l0 = l0*c0 + sum0;  l1 = l1*c1 + sum1;
    m0 = mn0;  m1 = mn1;
    #pragma unroll
    for (int nt = 0; nt < 16; nt++){
      O[nt][0] *= c0; O[nt][1] *= c0;
      O[nt][2] *= c1; O[nt][3] *= c1;
    }

    uint32_t pf[4][4];
    #pragma unroll
    for (int j = 0; j < 4; j++){
      __half2 h0 = __floats2half2_rn(sacc[2*j][0],   sacc[2*j][1]);
      __half2 h1 = __floats2half2_rn(sacc[2*j][2],   sacc[2*j][3]);
      __half2 h2 = __floats2half2_rn(sacc[2*j+1][0], sacc[2*j+1][1]);
      __half2 h3 = __floats2half2_rn(sacc[2*j+1][2], sacc[2*j+1][3]);
      pf[j][0] = *(uint32_t*)&h0;  pf[j][1] = *(uint32_t*)&h1;
      pf[j][2] = *(uint32_t*)&h2;  pf[j][3] = *(uint32_t*)&h3;
    }

    #pragma unroll
    for (int s = 0; s < 4; s++){
      uint32_t bv[16][2];
      #pragma unroll
      for (int p = 0; p < 8; p++)
        LDMX4(bv[p*2][0], bv[p*2][1], bv[p*2+1][0], bv[p*2+1][1],
              svb + (uint32_t)(((p*16 + b_row)*VSTR + s*16 + b_kh) * 2));
      #pragma unroll
      for (int nt = 0; nt < 16; nt++)
        HMMA(O[nt], pf[s], bv[nt]);
    }
    __syncthreads();
  }

  float i0 = 1.f/l0, i1 = 1.f/l1;
  int q0 = qt*QT + w*16 + g;
  int q1 = q0 + 8;
  long long tok0 = (q0 < LT) ? (long long)(b*LT + q0) : (long long)(MT + b*NI + (q0 - LT));
  long long tok1 = (q1 < LT) ? (long long)(b*LT + q1) : (long long)(MT + b*NI + (q1 - LT));
  __half* o0 = ap + tok0*DM + h*HDD + 2*tg;
  __half* o1 = ap + tok1*DM + h*HDD + 2*tg;
  #pragma unroll
  for (int nt = 0; nt < 16; nt++){
    *(__half2*)(o0 + nt*8) = __floats2half2_rn(O[nt][0]*i0, O[nt][1]*i0);
    *(__half2*)(o1 + nt*8) = __floats2half2_rn(O[nt][2]*i1, O[nt][3]*i1);
  }
}

// ---------------- convert 8 weight matrices float -> half ----------------
__global__ void k_half8(const float* __restrict__ i0, __half* __restrict__ o0,
                        const float* __restrict__ i1, __half* __restrict__ o1,
                        const float* __restrict__ i2, __half* __restrict__ o2,
                        const float* __restrict__ i3, __half* __restrict__ o3,
                        const float* __restrict__ i4, __half* __restrict__ o4,
                        const float* __restrict__ i5, __half* __restrict__ o5,
                        const float* __restrict__ i6, __half* __restrict__ o6,
                        const float* __restrict__ i7, __half* __restrict__ o7)
{
  int idx = blockIdx.x*blockDim.x + threadIdx.x;
  const float4* in; __half2* out; int off;
  if      (idx <  196608){ in=(const float4*)i0; out=(__half2*)o0; off=0; }
  else if (idx <  393216){ in=(const float4*)i1; out=(__half2*)o1; off=196608; }
  else if (idx <  458752){ in=(const float4*)i2; out=(__half2*)o2; off=393216; }
  else if (idx <  524288){ in=(const float4*)i3; out=(__half2*)o3; off=458752; }
  else if (idx <  786432){ in=(const float4*)i4; out=(__half2*)o4; off=524288; }
  else if (idx < 1048576){ in=(const float4*)i5; out=(__half2*)o5; off=786432; }
  else if (idx < 1310720){ in=(const float4*)i6; out=(__half2*)o6; off=1048576; }
  else                   { in=(const float4*)i7; out=(__half2*)o7; off=1310720; }
  int j = idx - off;
  float4 v = in[j];
  out[j*2]   = __floats2half2_rn(v.x, v.y);
  out[j*2+1] = __floats2half2_rn(v.z, v.w);
}

// ---------------- adaln embedding (both streams in one launch) ----------------
__global__ void k_emb2(const float* __restrict__ vec,
                       const float* __restrict__ Wi, const float* __restrict__ bi,
                       const float* __restrict__ Wt, const float* __restrict__ bt,
                       float* __restrict__ ei, float* __restrict__ et)
{
  int b = blockIdx.y;
  const float* W  = blockIdx.z ? Wt : Wi;
  const float* bs = blockIdx.z ? bt : bi;
  float* e        = blockIdx.z ? et : ei;
  __shared__ float s[DM];
  for (int i = threadIdx.x; i < DM; i += blockDim.x){
    float v = vec[b*DM + i];
    s[i] = v / (1.f + expf(-v));
  }
  __syncthreads();
  int n = blockIdx.x*blockDim.x + threadIdx.x;
  const float* wr = W + (long long)n*DM;
  float acc = 0.f;
  #pragma unroll 8
  for (int k = 0; k < DM; k++) acc += s[k]*wr[k];
  e[b*E6 + n] = acc + bs[n];
}

// ---------------- mod (+ eff in block 0) ----------------
__global__ void k_mod(const float* __restrict__ sp, const float* __restrict__ mw,
                      const float* __restrict__ mb, float* __restrict__ mod,
                      const float* __restrict__ temp, float* __restrict__ eff)
{
  int idx = blockIdx.x*blockDim.x + threadIdx.x;
  if (blockIdx.x == 0 && threadIdx.x < NB){
    int b = threadIdx.x;
    float m = 0.25f*(temp[b*NHD+0]+temp[b*NHD+1]+temp[b*NHD+2]+temp[b*NHD+3]);
    eff[b] = SCALE_C / fmaxf(m, 0.1f);
  }
  if (idx >= NB*NHD*NI) return;
  int n = idx & (NI-1);
  int h = (idx >> 11) & (NHD-1);
  int b = idx >> 13;
  int y = n >> 5;
  int x = n & 31;
  float fy = (y + 0.5f)*0.125f - 0.5f;
  float fx = (x + 0.5f)*0.25f  - 0.5f;
  int y0 = (int)floorf(fy); float wy = fy - (float)y0;
  int x0 = (int)floorf(fx); float wx = fx - (float)x0;
  int y0c = min(max(y0,0),7), y1c = min(max(y0+1,0),7);
  int x0c = min(max(x0,0),7), x1c = min(max(x0+1,0),7);
  const float* p = sp + b*64;
  float v = (1.f-wy)*((1.f-wx)*p[y0c*8+x0c] + wx*p[y0c*8+x1c])
          +      wy *((1.f-wx)*p[y1c*8+x0c] + wx*p[y1c*8+x1c]);
  v = v*mw[h] + mb[h];
  v = fminf(fmaxf(v, -2.f), 2.f);
  mod[idx] = expf(v);
}

// ---------------- combined rms-norm + adaln modulate -> half ----------------
__global__ __launch_bounds__(128) void k_rmsmod(
    const float* __restrict__ xt, const float* __restrict__ xi,
    const float* __restrict__ wt, const float* __restrict__ wi,
    const float* __restrict__ et, const float* __restrict__ ei,
    int shift_off, int scale_off, __half* __restrict__ out)
{
  int row = blockIdx.x;
  const float* x; const float* w; const float* eb;
  if (row < MT){
    x = xt + (long long)row*DM; w = wt; eb = et + (row/LT)*E6;
  } else {
    int rr = row - MT;
    x = xi + (long long)rr*DM; w = wi; eb = ei + (rr/NI)*E6;
  }
  float4 xv = ((const float4*)x)[threadIdx.x];
  float ss = xv.x*xv.x + xv.y*xv.y + xv.z*xv.z + xv.w*xv.w;
  ss = warpSum(ss);
  __shared__ float red[4];
  int lane = threadIdx.x & 31, wid = threadIdx.x >> 5;
  if (lane==0) red[wid]=ss;
  __syncthreads();
  float tot = red[0]+red[1]+red[2]+red[3];
  float inv = rsqrtf(tot*(1.f/DM) + 1e-6f);
  int c = threadIdx.x*4;
  float ox = xv.x*inv*w[c+0]*(1.f+eb[scale_off+c+0]) + eb[shift_off+c+0];
  float oy = xv.y*inv*w[c+1]*(1.f+eb[scale_off+c+1]) + eb[shift_off+c+1];
  float oz = xv.z*inv*w[c+2]*(1.f+eb[scale_off+c+2]) + eb[shift_off+c+2];
  float ow = xv.w*inv*w[c+3]*(1.f+eb[scale_off+c+3]) + eb[shift_off+c+3];
  __half2* op = (__half2*)(out + (long long)row*DM);
  op[threadIdx.x*2]   = __floats2half2_rn(ox, oy);
  op[threadIdx.x*2+1] = __floats2half2_rn(oz, ow);
}

// ---------------- launch ----------------
#define GETSYMF(var, sym) float* var; cudaGetSymbolAddress((void**)&var, sym)
#define GETSYMH(var, sym) __half* var; cudaGetSymbolAddress((void**)&var, sym)

extern "C" void kernel_launch(void* const* d_in, const int* in_sizes, int n_in,
                              void* d_out, int out_size)
{
  const float* txt          = (const float*)d_in[0];
  const float* img          = (const float*)d_in[1];
  const float* vec          = (const float*)d_in[2];
  const float* rope         = (const float*)d_in[3];
  const float* sol_t        = (const float*)d_in[4];
  const float* sol_s        = (const float*)d_in[5];
  const float* img_adaln_w  = (const float*)d_in[6];
  const float* img_adaln_b  = (const float*)d_in[7];
  const float* img_adaln_nw = (const float*)d_in[8];
  const float* txt_adaln_w  = (const float*)d_in[9];
  const float* txt_adaln_b  = (const float*)d_in[10];
  const float* txt_adaln_nw = (const float*)d_in[11];
  const float* txt_qkv_w    = (const float*)d_in[12];
  const float* img_qkv_w    = (const float*)d_in[13];
  const float* txt_out_w    = (const float*)d_in[14];
  const float* img_out_w    = (const float*)d_in[15];
  const float* sol_mod_w    = (const float*)d_in[16];
  const float* sol_mod_b    = (const float*)d_in[17];
  const float* img_norm2_w  = (const float*)d_in[18];
  const float* txt_norm2_w  = (const float*)d_in[19];
  const float* img_fc1_w    = (const float*)d_in[20];
  const float* img_fc1_b    = (const float*)d_in[21];
  const float* img_fc2_w    = (const float*)d_in[22];
  const float* img_fc2_b    = (const float*)d_in[23];
  const float* txt_fc1_w    = (const float*)d_in[24];
  const float* txt_fc1_b    = (const float*)d_in[25];
  const float* txt_fc2_w    = (const float*)d_in[26];
  const float* txt_fc2_b    = (const float*)d_in[27];
  float* out = (float*)d_out;

  GETSYMF(e_img, d_e_img);  GETSYMF(e_txt, d_e_txt);
  GETSYMF(eff, d_eff);      GETSYMF(mod, d_mod);
  GETSYMH(nrm, d_nrm);
  GETSYMH(Qc, d_Qc);        GETSYMH(Kc, d_Kc);
  GETSYMH(VT, d_VT);
  GETSYMH(ap, d_ap);        GETSYMH(hh, d_h);
  GETSYMF(cc, d_c);
  GETSYMH(wq_t, d_wq_t);    GETSYMH(wq_i, d_wq_i);
  GETSYMH(wo_t, d_wo_t);    GETSYMH(wo_i, d_wo_i);
  GETSYMH(w1_t, d_w1_t);    GETSYMH(w1_i, d_w1_i);
  GETSYMH(w2_t, d_w2_t);    GETSYMH(w2_i, d_w2_i);

  cudaFuncSetAttribute(tgemm,   cudaFuncAttributeMaxDynamicSharedMemorySize, TG_DSMEM);
  cudaFuncSetAttribute(k_flash, cudaFuncAttributeMaxDynamicSharedMemorySize, FL_DSMEM);

  // 0. weights -> half
  k_half8<<<1572864/256, 256>>>(txt_qkv_w, wq_t, img_qkv_w, wq_i,
                                txt_out_w, wo_t, img_out_w, wo_i,
                                txt_fc1_w, w1_t, img_fc1_w, w1_i,
                                txt_fc2_w, w2_t, img_fc2_w, w2_i);
  // 1. adaln embeddings + (eff + mod fused)
  k_emb2<<<dim3(E6/256, NB, 2), 256>>>(vec, img_adaln_w, img_adaln_b,
                                       txt_adaln_w, txt_adaln_b, e_img, e_txt);
  k_mod<<<(NB*NHD*NI)/256, 256>>>(sol_s, sol_mod_w, sol_mod_b, mod, sol_t, eff);
  // 2. norm1 combined -> half
  k_rmsmod<<<MALL, 128>>>(txt, img, txt_adaln_nw, img_adaln_nw, e_txt, e_img, 0, 512, nrm);
  // 3. QKV GEMM with fused rope/mod scatter (ep5) -> Qc, Kc, VT directly
  tgemm<<<dim3(12, MALL/128, 1), 256, TG_DSMEM>>>(nrm, wq_t, wq_i, MT,
      Qc, 1536, DM, 1536, 0, 0,
      BIGR, 1, 0, 0, 0, 0, 1.f, eff, 1, BIGR,
      5, nullptr, nullptr, nullptr, nullptr, nullptr, nullptr, 0,
      rope, mod, Qc, Kc, VT);
  // 4. fused flash attention -> packed half ap
  k_flash<<<dim3(KVL/QT, NB*NHD), 128, FL_DSMEM>>>(Qc, Kc, VT, ap, eff);
  // 5. output projection + residual gate fused (ep2) -> float cc
  tgemm<<<dim3(4, MALL/128, 1), 256, TG_DSMEM>>>(ap, wo_t, wo_i, MT,
      cc, DM, DM, DM, 0, 0,
      BIGR, 1, 0, 0, 0, 0, 1.f, eff, 1, BIGR,
      2, txt, img, e_txt, e_img, nullptr, nullptr, 1024,
      nullptr, nullptr, nullptr, nullptr, nullptr);
  // 6. norm2 combined -> half
  k_rmsmod<<<MALL, 128>>>(cc, cc + (long long)MT*DM, txt_norm2_w, img_norm2_w,
                          e_txt, e_img, 1536, 2048, nrm);
  // 7. fc1 + bias + gelu fused (ep3) -> half h
  tgemm<<<dim3(16, MALL/128, 1), 256, TG_DSMEM>>>(nrm, w1_t, w1_i, MT,
      hh, FFD, DM, FFD, 0, 0,
      BIGR, 1, 0, 0, 0, 0, 1.f, eff, 1, BIGR,
      3, nullptr, nullptr, nullptr, nullptr, txt_fc1_b, img_fc1_b, 0,
      nullptr, nullptr, nullptr, nullptr, nullptr);
  // 8. fc2 + bias + gate + residual fused (ep4) -> d_out directly
  tgemm<<<dim3(4, MALL/128, 1), 256, TG_DSMEM>>>(hh, w2_t, w2_i, MT,
      out, DM, FFD, DM, 0, 0,
      BIGR, 1, 0, 0, 0, 0, 1.f, eff, 1, BIGR,
      4, cc, nullptr, e_txt, e_img, txt_fc2_b, img_fc2_b, 2560,
      nullptr, nullptr, nullptr, nullptr, nullptr);
}